// round 5
// baseline (speedup 1.0000x reference)
#include <cuda_runtime.h>
#include <math.h>

// Problem constants
#define NB 64
#define CB 64
#define DB 64
#define TB 300
#define VB 25
#define EPSB 1e-5f
#define NTOT (NB*TB)          // 19200 rows
#define FEAT (VB*DB)          // 1600 features
#define LTOT (TB+VB)          // 325
#define Y_SIZE (NB*DB*TB*VB)  // 30720000

#define K7T 10                // t-rows per k7 block
#define K7_BLOCKS (NB*(TB/K7T))   // 1920

// ---------------- scratch (device globals; no runtime allocation) ----------------
__device__ float g_xv[NB*CB*TB];        // 4.9 MB
__device__ float g_xt[NB*CB*VB];        // 0.4 MB
__device__ float g_part1[NB*CB*4];      // per-(n,c) partials (sv,svv,st,stt)
__device__ float g_xs[NB*DB*LTOT];      // 5.3 MB
__device__ float g_part2[320*DB*2];     // per-(n,kc) per-o partials
__device__ float g_scale[VB*CB];        // tanh(sigmoid(view))+1, [w][c]
__device__ float g_y0[(size_t)NTOT*FEAT];     // 123 MB
__device__ float g_part3[K7_BLOCKS*3200];     // 24.6 MB : per-block BN partials
__device__ float g_stats3[FEAT*2];      // y0 feature mean/rstd

__device__ __forceinline__ float hswish(float x) {
    float c = fminf(fmaxf(x + 3.0f, 0.0f), 6.0f);
    return x * c * (1.0f / 6.0f);
}
__device__ __forceinline__ unsigned long long pk2(float lo, float hi) {
    unsigned long long r;
    asm("mov.b64 %0, {%1, %2};" : "=l"(r) : "f"(lo), "f"(hi));
    return r;
}
__device__ __forceinline__ void upk2(float& lo, float& hi, unsigned long long v) {
    asm("mov.b64 {%0, %1}, %2;" : "=f"(lo), "=f"(hi) : "l"(v));
}
__device__ __forceinline__ void fma2(unsigned long long& d, unsigned long long a, unsigned long long b) {
    asm("fma.rn.f32x2 %0, %1, %2, %0;" : "+l"(d) : "l"(a), "l"(b));
}

// ---------------- K1: per-(n,c) slice — xv (V-reduce) + xt (T-reduce) + partials ----
__global__ void k1(const float* __restrict__ x0, const float* __restrict__ Wv,
                   const float* __restrict__ bv, const float* __restrict__ Wt,
                   const float* __restrict__ bt)
{
    __shared__ float xs_[TB*VB];
    __shared__ float wt_[TB];
    __shared__ float wvc[VB];
    __shared__ float red[64];
    __shared__ float xta[VB];

    int nc = blockIdx.x;
    int c  = nc & 63;
    int tid = threadIdx.x;

    const float* src = x0 + (size_t)nc * (TB*VB);
    for (int i = tid; i < TB*VB; i += blockDim.x) xs_[i] = src[i];
    for (int i = tid; i < TB;    i += blockDim.x) wt_[i] = Wt[i];
    if (tid < VB) {
        int v = (tid - c) % VB; if (v < 0) v += VB;
        wvc[tid] = Wv[v];
    }
    float bvv = bv[0], btv = bt[0];
    __syncthreads();

    float s = 0.f, ss = 0.f;
    for (int t = tid; t < TB; t += blockDim.x) {
        float a = bvv;
        #pragma unroll
        for (int v = 0; v < VB; v++) a += wvc[v] * xs_[t*VB + v];
        g_xv[nc*TB + t] = a;
        s += a; ss += a*a;
    }
    #pragma unroll
    for (int o = 16; o; o >>= 1) {
        s  += __shfl_down_sync(0xffffffffu, s,  o);
        ss += __shfl_down_sync(0xffffffffu, ss, o);
    }
    if ((tid & 31) == 0) { red[tid>>5] = s; red[32 + (tid>>5)] = ss; }

    // xt: warps 0-6 fully execute shfl; lanes vp>=25 carry zeros
    if (tid < 224) {
        int vp = tid >> 3, sl = tid & 7;
        float a = 0.f;
        if (vp < VB) {
            for (int t = sl; t < TB; t += 8) a += wt_[t] * xs_[t*VB + vp];
        }
        a += __shfl_down_sync(0xffffffffu, a, 4);
        a += __shfl_down_sync(0xffffffffu, a, 2);
        a += __shfl_down_sync(0xffffffffu, a, 1);
        if (sl == 0 && vp < VB) {
            a += btv;
            int v = (vp - c) % VB; if (v < 0) v += VB;
            g_xt[nc*VB + v] = a;
            xta[vp] = a;
        }
    }
    __syncthreads();
    if (tid == 0) {
        float S = 0.f, SS = 0.f;
        for (int w = 0; w < (int)(blockDim.x >> 5); w++) { S += red[w]; SS += red[32+w]; }
        g_part1[nc*4 + 0] = S; g_part1[nc*4 + 1] = SS;
        S = 0.f; SS = 0.f;
        for (int v = 0; v < VB; v++) { S += xta[v]; SS += xta[v]*xta[v]; }
        g_part1[nc*4 + 2] = S; g_part1[nc*4 + 3] = SS;
    }
}

// ---------------- K3: inline stats1 + Ws stage (grid n x 5 chunks), 4x4 tiles ----------------
__global__ void k3(const float* __restrict__ gv, const float* __restrict__ bev,
                   const float* __restrict__ gt, const float* __restrict__ bet,
                   const float* __restrict__ Ws, const float* __restrict__ bs)
{
    extern __shared__ float sm3[];
    float* sfs    = sm3;            // [64][68]
    float* wst    = sm3 + 64*68;    // [64*64] transposed Ws
    float* red_s  = wst + 4096;     // [17][64]
    float* red_ss = red_s + 17*64;  // [17][64]
    __shared__ float rbuf[9*4];
    __shared__ float st1[4];        // mv, rv, mt, rt

    int b = blockIdx.x;
    int n = b / 5, kc = b % 5;
    int tid = threadIdx.x;

    // ---- inline k2: reduce g_part1 (redundant per block) ----
    {
        float a0=0.f, a1=0.f, a2=0.f, a3=0.f;
        for (int j = tid; j < NB*CB; j += blockDim.x) {
            a0 += g_part1[j*4+0]; a1 += g_part1[j*4+1];
            a2 += g_part1[j*4+2]; a3 += g_part1[j*4+3];
        }
        #pragma unroll
        for (int o = 16; o; o >>= 1) {
            a0 += __shfl_down_sync(0xffffffffu, a0, o);
            a1 += __shfl_down_sync(0xffffffffu, a1, o);
            a2 += __shfl_down_sync(0xffffffffu, a2, o);
            a3 += __shfl_down_sync(0xffffffffu, a3, o);
        }
        if ((tid & 31) == 0) {
            int w = tid >> 5;
            rbuf[w*4+0]=a0; rbuf[w*4+1]=a1; rbuf[w*4+2]=a2; rbuf[w*4+3]=a3;
        }
        __syncthreads();
        if (tid == 0) {
            float A0=0,A1=0,A2=0,A3=0;
            for (int w = 0; w < 9; w++) { A0+=rbuf[w*4]; A1+=rbuf[w*4+1]; A2+=rbuf[w*4+2]; A3+=rbuf[w*4+3]; }
            float cntv = (float)(NB*CB*TB), cntt = (float)(NB*CB*VB);
            float mv = A0/cntv, vv = A1/cntv - mv*mv;
            float mt = A2/cntt, vt = A3/cntt - mt*mt;
            st1[0] = mv; st1[1] = rsqrtf(vv + EPSB);
            st1[2] = mt; st1[3] = rsqrtf(vt + EPSB);
        }
        __syncthreads();
    }
    float mv = st1[0], rv = st1[1], mt = st1[2], rt = st1[3];
    float gvv = gv[0], bevv = bev[0], gtv = gt[0], betv = bet[0];

    // load/transform slice: flat p = cc*325 + k
    for (int i = tid; i < 64*68; i += blockDim.x) {
        int cc = i / 68, ll = i % 68;
        float val = 0.f;
        if (ll < 65) {
            int p = cc*LTOT + kc*65 + ll;
            if (p < 1600) {
                int cs = p / 25, v = p % 25;
                float x = g_xt[(n*64 + cs)*25 + v];
                val = hswish(gtv * (x - mt) * rt + betv);
            } else {
                int q = p - 1600;
                int cs = q / 300, t = q % 300;
                float x = g_xv[(n*64 + cs)*300 + t];
                val = hswish(gvv * (x - mv) * rv + bevv);
            }
        }
        sfs[i] = val;
    }
    for (int i = tid; i < 4096; i += blockDim.x) {
        int o = i & 63, cc = i >> 6;
        wst[i] = Ws[o*64 + cc];
    }
    __syncthreads();

    if (tid < 272) {
        int og = tid & 15, kg = tid >> 4;
        int o0 = og * 4, kl0 = kg * 4;
        float acc[4][4];
        #pragma unroll
        for (int j = 0; j < 4; j++) {
            float bb = bs[o0 + j];
            #pragma unroll
            for (int i = 0; i < 4; i++) acc[j][i] = bb;
        }
        for (int cc = 0; cc < 64; cc++) {
            float4 a = *(const float4*)&wst[cc*64 + o0];
            float4 bq = *(const float4*)&sfs[cc*68 + kl0];
            acc[0][0] += a.x*bq.x; acc[0][1] += a.x*bq.y; acc[0][2] += a.x*bq.z; acc[0][3] += a.x*bq.w;
            acc[1][0] += a.y*bq.x; acc[1][1] += a.y*bq.y; acc[1][2] += a.y*bq.z; acc[1][3] += a.y*bq.w;
            acc[2][0] += a.z*bq.x; acc[2][1] += a.z*bq.y; acc[2][2] += a.z*bq.z; acc[2][3] += a.z*bq.w;
            acc[3][0] += a.w*bq.x; acc[3][1] += a.w*bq.y; acc[3][2] += a.w*bq.z; acc[3][3] += a.w*bq.w;
        }
        #pragma unroll
        for (int j = 0; j < 4; j++) {
            float s = 0.f, ssum = 0.f;
            #pragma unroll
            for (int i = 0; i < 4; i++) {
                int kl = kl0 + i;
                if (kl < 65) {
                    float v = acc[j][i];
                    g_xs[(n*64 + o0 + j)*LTOT + kc*65 + kl] = v;
                    s += v; ssum += v*v;
                }
            }
            red_s [kg*64 + o0 + j] = s;
            red_ss[kg*64 + o0 + j] = ssum;
        }
    }
    __syncthreads();
    if (tid < 64) {
        float S = 0.f, SS = 0.f;
        for (int kg = 0; kg < 17; kg++) { S += red_s[kg*64 + tid]; SS += red_ss[kg*64 + tid]; }
        g_part2[(b*64 + tid)*2 + 0] = S;
        g_part2[(b*64 + tid)*2 + 1] = SS;
    }
}

// ---------------- K56: fused stats2 + xbar column + squeeze outputs (block per l) ----
__global__ void k56(const float* __restrict__ gs, const float* __restrict__ bes,
                    const float* __restrict__ Wt2, const float* __restrict__ bt2,
                    const float* __restrict__ Wv2, const float* __restrict__ bv2,
                    float* __restrict__ out_xtime)
{
    __shared__ float w2t[4096];      // transposed squeeze weight [d][o]
    __shared__ float red_a[256], red_b[256];
    __shared__ float stats2_s[128];  // m, rstd per o
    __shared__ float xbar_s[64];

    int l = blockIdx.x;              // 0..324
    int tid = threadIdx.x;

    // stage transposed weight for phase C (uniform branch per block)
    const float* W2 = (l < TB) ? Wt2 : Wv2;
    for (int i = tid; i < 4096; i += blockDim.x) {
        int o = i >> 6, d = i & 63;
        w2t[d*64 + o] = W2[i];
    }

    // ---- phase A: stats2 (redundant reduce of g_part2) ----
    {
        int o = tid & 63, sl = tid >> 6;     // 4 slices
        float s = 0.f, ss = 0.f;
        for (int ch = sl; ch < 320; ch += 4) {
            s  += g_part2[(ch*64 + o)*2 + 0];
            ss += g_part2[(ch*64 + o)*2 + 1];
        }
        red_a[tid] = s; red_b[tid] = ss;
        __syncthreads();
        if (tid < 64) {
            float S  = red_a[tid] + red_a[64+tid] + red_a[128+tid] + red_a[192+tid];
            float SS = red_b[tid] + red_b[64+tid] + red_b[128+tid] + red_b[192+tid];
            float cnt = 64.f * (float)LTOT;
            float m = S/cnt, v = SS/cnt - m*m;
            stats2_s[tid*2 + 0] = m;
            stats2_s[tid*2 + 1] = rsqrtf(v + EPSB);
        }
        __syncthreads();
    }

    // ---- phase B: xbar[:, l] = mean_n hardswish(bn(g_xs[:, :, l])) ----
    {
        int d = tid & 63, ns = tid >> 6;
        float m = stats2_s[d*2], r = stats2_s[d*2+1];
        float g = gs[d], bb = bes[d];
        float acc = 0.f;
        for (int n = ns; n < 64; n += 4)
            acc += hswish(g * (g_xs[(n*64 + d)*LTOT + l] - m) * r + bb);
        red_a[tid] = acc;
        __syncthreads();
        if (tid < 64)
            xbar_s[tid] = (red_a[tid] + red_a[64+tid] + red_a[128+tid] + red_a[192+tid]) * (1.0f/64.0f);
        __syncthreads();
    }

    // ---- phase C: squeeze dot + sigmoid (+tanh for view gate) ----
    if (tid < 64) {
        int o = tid;
        float acc = (l < TB) ? bt2[o] : bv2[o];
        #pragma unroll 8
        for (int d = 0; d < 64; d++) acc += w2t[d*64 + o] * xbar_s[d];
        float sg = 1.0f / (1.0f + expf(-acc));
        if (l < TB) out_xtime[o*TB + l] = sg;
        else        g_scale[(l - TB)*64 + o] = tanhf(sg) + 1.0f;
    }
}

// ---------------- K7: GEMM + inline BN partials ----------------
// block = (n, 10 t-rows), 512 threads; compute: 2 t-groups x (25 w x 8 ddg), 5t x 8dd, FFMA2.
#define XM_WP 66
#define XM_TP 1664
__global__ void k7(const float* __restrict__ x0, const float* __restrict__ Lw,
                   const float* __restrict__ Lb)
{
    extern __shared__ float sm7[];
    float* xsl = sm7;              // 64 c x 250  = 16000 (reused for BN partials)
    float* xm  = sm7 + 16000;      // 10 x 1664   = 16640
    float* lws = xm + 10*XM_TP;    // 4096
    float* ssc = lws + 4096;       // 1600
    float* lbs = ssc + 1600;       // 64
    float* bsum = xsl;             // alias after xsl dead: [2][1600]
    float* bsq  = xsl + 3200;      // [2][1600]

    int b = blockIdx.x;
    int n = b / (TB/K7T);
    int t0 = (b % (TB/K7T)) * K7T;
    int tid = threadIdx.x;

    const float* xbase = x0 + ((size_t)(n*64) * 300 + t0) * 25;
    for (int i = tid; i < 64*25*K7T; i += blockDim.x) {
        int c = i / (25*K7T), r = i % (25*K7T);
        xsl[i] = xbase[(size_t)c * 7500 + r];
    }
    for (int i = tid; i < 4096; i += blockDim.x) lws[i] = Lw[i];
    for (int i = tid; i < 1600; i += blockDim.x) ssc[i] = g_scale[i];
    if (tid < 64) lbs[tid] = Lb[tid];
    __syncthreads();

    // xm[t][w*66 + c] = x0[n,c,t0+t,(w+c)%25] * scale[w,c]
    for (int i = tid; i < K7T*1600; i += blockDim.x) {
        int t = i / 1600, rem = i % 1600;
        int w = rem >> 6, c = rem & 63;
        int v = (w + c) % 25;
        xm[t*XM_TP + w*XM_WP + c] = xsl[c*(25*K7T) + t*25 + v] * ssc[rem];
    }
    __syncthreads();

    int g = tid >> 8;            // t-group 0/1 (t = g*5 + 0..4)
    int r = tid & 255;
    bool active = (r < 200);
    float psum[8], psq[8];

    if (active) {
        int ddg = r & 7;
        int w   = r >> 3;
        int dd0 = ddg << 3;
        int w66 = w * XM_WP;
        const float* xg = xm + (g*5)*XM_TP + w66;

        unsigned long long acc[5][4];
        #pragma unroll
        for (int p = 0; p < 4; p++) {
            unsigned long long init = pk2(lbs[dd0 + 2*p], lbs[dd0 + 2*p + 1]);
            #pragma unroll
            for (int t = 0; t < 5; t++) acc[t][p] = init;
        }

        #pragma unroll 4
        for (int c = 0; c < 64; c++) {
            float a0 = xg[0*XM_TP + c];
            float a1 = xg[1*XM_TP + c];
            float a2 = xg[2*XM_TP + c];
            float a3 = xg[3*XM_TP + c];
            float a4 = xg[4*XM_TP + c];
            unsigned long long p0 = pk2(a0, a0);
            unsigned long long p1 = pk2(a1, a1);
            unsigned long long p2 = pk2(a2, a2);
            unsigned long long p3 = pk2(a3, a3);
            unsigned long long p4 = pk2(a4, a4);
            ulonglong2 b01 = *(const ulonglong2*)&lws[(c << 6) + dd0];
            ulonglong2 b23 = *(const ulonglong2*)&lws[(c << 6) + dd0 + 4];
            fma2(acc[0][0], p0, b01.x); fma2(acc[0][1], p0, b01.y);
            fma2(acc[0][2], p0, b23.x); fma2(acc[0][3], p0, b23.y);
            fma2(acc[1][0], p1, b01.x); fma2(acc[1][1], p1, b01.y);
            fma2(acc[1][2], p1, b23.x); fma2(acc[1][3], p1, b23.y);
            fma2(acc[2][0], p2, b01.x); fma2(acc[2][1], p2, b01.y);
            fma2(acc[2][2], p2, b23.x); fma2(acc[2][3], p2, b23.y);
            fma2(acc[3][0], p3, b01.x); fma2(acc[3][1], p3, b01.y);
            fma2(acc[3][2], p3, b23.x); fma2(acc[3][3], p3, b23.y);
            fma2(acc[4][0], p4, b01.x); fma2(acc[4][1], p4, b01.y);
            fma2(acc[4][2], p4, b23.x); fma2(acc[4][3], p4, b23.y);
        }

        #pragma unroll
        for (int j = 0; j < 8; j++) { psum[j] = 0.f; psq[j] = 0.f; }

        #pragma unroll
        for (int t = 0; t < 5; t++) {
            float vals[8];
            upk2(vals[0], vals[1], acc[t][0]);
            upk2(vals[2], vals[3], acc[t][1]);
            upk2(vals[4], vals[5], acc[t][2]);
            upk2(vals[6], vals[7], acc[t][3]);
            float* dst = &g_y0[(size_t)(n*300 + t0 + g*5 + t) * 1600 + (w << 6) + dd0];
            *(float4*)dst       = make_float4(vals[0], vals[1], vals[2], vals[3]);
            *(float4*)(dst + 4) = make_float4(vals[4], vals[5], vals[6], vals[7]);
            #pragma unroll
            for (int j = 0; j < 8; j++) { psum[j] += vals[j]; psq[j] += vals[j]*vals[j]; }
        }
    }
    __syncthreads();   // xsl dead; safe to alias as BN buffers
    if (active) {
        int ddg = r & 7, w = r >> 3, dd0 = ddg << 3;
        #pragma unroll
        for (int j = 0; j < 8; j++) {
            bsum[g*1600 + (w << 6) + dd0 + j] = psum[j];
            bsq [g*1600 + (w << 6) + dd0 + j] = psq[j];
        }
    }
    __syncthreads();
    for (int f = tid; f < 1600; f += blockDim.x) {
        g_part3[(size_t)b*3200 + f]        = bsum[f] + bsum[1600 + f];
        g_part3[(size_t)b*3200 + 1600 + f] = bsq[f]  + bsq[1600 + f];
    }
}

// ---------------- K8b: reduce BN partials -> per-feature stats ----------------
__global__ void k8b()
{
    __shared__ float red_s[256], red_ss[256];
    int f = blockIdx.x * 32 + (threadIdx.x & 31);
    int sl = threadIdx.x >> 5;     // 8 slices
    float s = 0.f, ss = 0.f;
    for (int b = sl; b < K7_BLOCKS; b += 8) {
        s  += g_part3[(size_t)b*3200 + f];
        ss += g_part3[(size_t)b*3200 + 1600 + f];
    }
    red_s[threadIdx.x] = s; red_ss[threadIdx.x] = ss;
    __syncthreads();
    if (threadIdx.x < 32) {
        float S = 0.f, SS = 0.f;
        #pragma unroll
        for (int k = 0; k < 8; k++) { S += red_s[k*32 + threadIdx.x]; SS += red_ss[k*32 + threadIdx.x]; }
        int ff = blockIdx.x * 32 + threadIdx.x;
        float cnt = (float)NTOT;
        float m = S/cnt, v = SS/cnt - m*m;
        g_stats3[ff*2 + 0] = m;
        g_stats3[ff*2 + 1] = rsqrtf(v + EPSB);
    }
}

// ---------------- K9: shift + BN + residual + relu ----------------
#define K9_TT 15
#define K9_PITCH 1632
__global__ void k9(const float* __restrict__ x0, const float* __restrict__ gbn,
                   const float* __restrict__ bbn, float* __restrict__ out)
{
    extern __shared__ float sm9[];
    float* ysm   = sm9;                       // 15 * 1632
    float* gbn_s = sm9 + K9_TT*K9_PITCH;
    float* bbn_s = gbn_s + 1600;

    int b = blockIdx.x;
    int n = b / 20, t0 = (b % 20) * K9_TT;
    int tid = threadIdx.x;

    for (int i = tid; i < 1600; i += blockDim.x) { gbn_s[i] = gbn[i]; bbn_s[i] = bbn[i]; }

    for (int t = 0; t < K9_TT; t++) {
        const float* row = &g_y0[(size_t)(n*300 + t0 + t) * 1600];
        for (int p = tid; p < 1600; p += blockDim.x) {
            float v = row[p];
            v = (v - g_stats3[p*2]) * g_stats3[p*2 + 1];
            int w = p >> 6, dd = p & 63;
            int i = (w + dd) % 25;
            ysm[t*K9_PITCH + i*65 + dd] = v;
        }
    }
    __syncthreads();

    for (int idx = tid; idx < 64 * K9_TT * 25; idx += blockDim.x) {
        int dd = idx / (K9_TT*25), r = idx % (K9_TT*25);
        int t = r / 25, i = r % 25;
        int f = i*64 + dd;
        float v = fmaf(gbn_s[f], ysm[t*K9_PITCH + i*65 + dd], bbn_s[f]);
        size_t go = ((size_t)(n*64 + dd) * 300 + t0) * 25 + r;
        v += x0[go];
        out[go] = fmaxf(v, 0.0f);
    }
}

// ---------------- launcher (6 launches; slot 4 = k7 for ncu capture) ----------------
extern "C" void kernel_launch(void* const* d_in, const int* in_sizes, int n_in,
                              void* d_out, int out_size)
{
    const float* x0  = (const float*)d_in[0];
    const float* Wv  = (const float*)d_in[3];
    const float* bv  = (const float*)d_in[4];
    const float* gv  = (const float*)d_in[5];
    const float* bev = (const float*)d_in[6];
    const float* Wt  = (const float*)d_in[7];
    const float* bt  = (const float*)d_in[8];
    const float* gt  = (const float*)d_in[9];
    const float* bet = (const float*)d_in[10];
    const float* Ws  = (const float*)d_in[11];
    const float* bs  = (const float*)d_in[12];
    const float* gs  = (const float*)d_in[13];
    const float* bes = (const float*)d_in[14];
    const float* Wv2 = (const float*)d_in[15];
    const float* bv2 = (const float*)d_in[16];
    const float* Wt2 = (const float*)d_in[17];
    const float* bt2 = (const float*)d_in[18];
    const float* Lw  = (const float*)d_in[19];
    const float* Lb  = (const float*)d_in[20];
    const float* gbn = (const float*)d_in[21];
    const float* bbn = (const float*)d_in[22];
    float* out = (float*)d_out;

    static_assert(K9_TT * 20 == TB, "t tiling");
    static_assert((TB % K7T) == 0, "k7 t tiling");

    const int smem3 = (64*68 + 4096 + 17*64*2) * 4;                         // 51200
    const int smem7 = (16000 + K7T*XM_TP + 4096 + 1600 + 64) * 4;           // 153600
    const int smem9 = (K9_TT*K9_PITCH + 1600 + 1600) * 4;                   // 110720
    cudaFuncSetAttribute(k3, cudaFuncAttributeMaxDynamicSharedMemorySize, smem3);
    cudaFuncSetAttribute(k7, cudaFuncAttributeMaxDynamicSharedMemorySize, smem7);
    cudaFuncSetAttribute(k9, cudaFuncAttributeMaxDynamicSharedMemorySize, smem9);

    k1 <<<NB*CB, 256>>>(x0, Wv, bv, Wt, bt);
    k3 <<<NB*5, 288, smem3>>>(gv, bev, gt, bet, Ws, bs);
    k56<<<LTOT, 256>>>(gs, bes, Wt2, bt2, Wv2, bv2, out + Y_SIZE);
    k7 <<<K7_BLOCKS, 512, smem7>>>(x0, Lw, Lb);
    k8b<<<FEAT/32, 256>>>();
    k9 <<<NB*20, 256, smem9>>>(x0, gbn, bbn, out);
}

// round 6
// speedup vs baseline: 1.0009x; 1.0009x over previous
#include <cuda_runtime.h>
#include <math.h>

// Problem constants
#define NB 64
#define CB 64
#define DB 64
#define TB 300
#define VB 25
#define EPSB 1e-5f
#define NTOT (NB*TB)          // 19200 rows
#define FEAT (VB*DB)          // 1600 features
#define LTOT (TB+VB)          // 325
#define Y_SIZE (NB*DB*TB*VB)  // 30720000

#define K7T 10                // t-rows per k7 block
#define K7_BLOCKS (NB*(TB/K7T))   // 1920

// ---------------- scratch (device globals; no runtime allocation) ----------------
__device__ float g_xv[NB*CB*TB];        // 4.9 MB
__device__ float g_xt[NB*CB*VB];        // 0.4 MB
__device__ float g_part1[NB*CB*4];      // per-(n,c) partials (sv,svv,st,stt)
__device__ float g_xs[NB*DB*LTOT];      // 5.3 MB
__device__ float g_part2[320*DB*2];     // per-(n,kc) per-o partials
__device__ float g_scale[VB*CB];        // tanh(sigmoid(view))+1, [w][c]
__device__ float g_y0[(size_t)NTOT*FEAT];     // 123 MB
__device__ float g_part3[K7_BLOCKS*3200];     // 24.6 MB : per-block BN partials
__device__ float g_stats3[FEAT*2];      // y0 feature mean/rstd

__device__ __forceinline__ float hswish(float x) {
    float c = fminf(fmaxf(x + 3.0f, 0.0f), 6.0f);
    return x * c * (1.0f / 6.0f);
}
__device__ __forceinline__ unsigned long long pk2(float lo, float hi) {
    unsigned long long r;
    asm("mov.b64 %0, {%1, %2};" : "=l"(r) : "f"(lo), "f"(hi));
    return r;
}
__device__ __forceinline__ void upk2(float& lo, float& hi, unsigned long long v) {
    asm("mov.b64 {%0, %1}, %2;" : "=f"(lo), "=f"(hi) : "l"(v));
}
__device__ __forceinline__ void fma2(unsigned long long& d, unsigned long long a, unsigned long long b) {
    asm("fma.rn.f32x2 %0, %1, %2, %0;" : "+l"(d) : "l"(a), "l"(b));
}

// ---------------- K1: per-(n,c) slice — xv (V-reduce) + xt (T-reduce) + partials ----
__global__ void k1(const float* __restrict__ x0, const float* __restrict__ Wv,
                   const float* __restrict__ bv, const float* __restrict__ Wt,
                   const float* __restrict__ bt)
{
    __shared__ float xs_[TB*VB];
    __shared__ float wt_[TB];
    __shared__ float wvc[VB];
    __shared__ float red[64];
    __shared__ float xta[VB];

    int nc = blockIdx.x;
    int c  = nc & 63;
    int tid = threadIdx.x;

    const float* src = x0 + (size_t)nc * (TB*VB);
    for (int i = tid; i < TB*VB; i += blockDim.x) xs_[i] = src[i];
    for (int i = tid; i < TB;    i += blockDim.x) wt_[i] = Wt[i];
    if (tid < VB) {
        int v = (tid - c) % VB; if (v < 0) v += VB;
        wvc[tid] = Wv[v];
    }
    float bvv = bv[0], btv = bt[0];
    __syncthreads();

    float s = 0.f, ss = 0.f;
    for (int t = tid; t < TB; t += blockDim.x) {
        float a = bvv;
        #pragma unroll
        for (int v = 0; v < VB; v++) a += wvc[v] * xs_[t*VB + v];
        g_xv[nc*TB + t] = a;
        s += a; ss += a*a;
    }
    #pragma unroll
    for (int o = 16; o; o >>= 1) {
        s  += __shfl_down_sync(0xffffffffu, s,  o);
        ss += __shfl_down_sync(0xffffffffu, ss, o);
    }
    if ((tid & 31) == 0) { red[tid>>5] = s; red[32 + (tid>>5)] = ss; }

    // xt: warps 0-6 fully execute shfl; lanes vp>=25 carry zeros
    if (tid < 224) {
        int vp = tid >> 3, sl = tid & 7;
        float a = 0.f;
        if (vp < VB) {
            for (int t = sl; t < TB; t += 8) a += wt_[t] * xs_[t*VB + vp];
        }
        a += __shfl_down_sync(0xffffffffu, a, 4);
        a += __shfl_down_sync(0xffffffffu, a, 2);
        a += __shfl_down_sync(0xffffffffu, a, 1);
        if (sl == 0 && vp < VB) {
            a += btv;
            int v = (vp - c) % VB; if (v < 0) v += VB;
            g_xt[nc*VB + v] = a;
            xta[vp] = a;
        }
    }
    __syncthreads();
    if (tid == 0) {
        float S = 0.f, SS = 0.f;
        for (int w = 0; w < (int)(blockDim.x >> 5); w++) { S += red[w]; SS += red[32+w]; }
        g_part1[nc*4 + 0] = S; g_part1[nc*4 + 1] = SS;
        S = 0.f; SS = 0.f;
        for (int v = 0; v < VB; v++) { S += xta[v]; SS += xta[v]*xta[v]; }
        g_part1[nc*4 + 2] = S; g_part1[nc*4 + 3] = SS;
    }
}

// ---------------- K3: inline stats1 + Ws stage (grid n x 5 chunks), 4x4 tiles ----------------
__global__ void k3(const float* __restrict__ gv, const float* __restrict__ bev,
                   const float* __restrict__ gt, const float* __restrict__ bet,
                   const float* __restrict__ Ws, const float* __restrict__ bs)
{
    extern __shared__ float sm3[];
    float* sfs    = sm3;            // [64][68]
    float* wst    = sm3 + 64*68;    // [64*64] transposed Ws
    float* red_s  = wst + 4096;     // [17][64]
    float* red_ss = red_s + 17*64;  // [17][64]
    __shared__ float rbuf[9*4];
    __shared__ float st1[4];        // mv, rv, mt, rt

    int b = blockIdx.x;
    int n = b / 5, kc = b % 5;
    int tid = threadIdx.x;

    // ---- inline k2: reduce g_part1 (redundant per block) ----
    {
        float a0=0.f, a1=0.f, a2=0.f, a3=0.f;
        for (int j = tid; j < NB*CB; j += blockDim.x) {
            a0 += g_part1[j*4+0]; a1 += g_part1[j*4+1];
            a2 += g_part1[j*4+2]; a3 += g_part1[j*4+3];
        }
        #pragma unroll
        for (int o = 16; o; o >>= 1) {
            a0 += __shfl_down_sync(0xffffffffu, a0, o);
            a1 += __shfl_down_sync(0xffffffffu, a1, o);
            a2 += __shfl_down_sync(0xffffffffu, a2, o);
            a3 += __shfl_down_sync(0xffffffffu, a3, o);
        }
        if ((tid & 31) == 0) {
            int w = tid >> 5;
            rbuf[w*4+0]=a0; rbuf[w*4+1]=a1; rbuf[w*4+2]=a2; rbuf[w*4+3]=a3;
        }
        __syncthreads();
        if (tid == 0) {
            float A0=0,A1=0,A2=0,A3=0;
            for (int w = 0; w < 9; w++) { A0+=rbuf[w*4]; A1+=rbuf[w*4+1]; A2+=rbuf[w*4+2]; A3+=rbuf[w*4+3]; }
            float cntv = (float)(NB*CB*TB), cntt = (float)(NB*CB*VB);
            float mv = A0/cntv, vv = A1/cntv - mv*mv;
            float mt = A2/cntt, vt = A3/cntt - mt*mt;
            st1[0] = mv; st1[1] = rsqrtf(vv + EPSB);
            st1[2] = mt; st1[3] = rsqrtf(vt + EPSB);
        }
        __syncthreads();
    }
    float mv = st1[0], rv = st1[1], mt = st1[2], rt = st1[3];
    float gvv = gv[0], bevv = bev[0], gtv = gt[0], betv = bet[0];

    // load/transform slice: flat p = cc*325 + k
    for (int i = tid; i < 64*68; i += blockDim.x) {
        int cc = i / 68, ll = i % 68;
        float val = 0.f;
        if (ll < 65) {
            int p = cc*LTOT + kc*65 + ll;
            if (p < 1600) {
                int cs = p / 25, v = p % 25;
                float x = g_xt[(n*64 + cs)*25 + v];
                val = hswish(gtv * (x - mt) * rt + betv);
            } else {
                int q = p - 1600;
                int cs = q / 300, t = q % 300;
                float x = g_xv[(n*64 + cs)*300 + t];
                val = hswish(gvv * (x - mv) * rv + bevv);
            }
        }
        sfs[i] = val;
    }
    for (int i = tid; i < 4096; i += blockDim.x) {
        int o = i & 63, cc = i >> 6;
        wst[i] = Ws[o*64 + cc];
    }
    __syncthreads();

    if (tid < 272) {
        int og = tid & 15, kg = tid >> 4;
        int o0 = og * 4, kl0 = kg * 4;
        float acc[4][4];
        #pragma unroll
        for (int j = 0; j < 4; j++) {
            float bb = bs[o0 + j];
            #pragma unroll
            for (int i = 0; i < 4; i++) acc[j][i] = bb;
        }
        for (int cc = 0; cc < 64; cc++) {
            float4 a = *(const float4*)&wst[cc*64 + o0];
            float4 bq = *(const float4*)&sfs[cc*68 + kl0];
            acc[0][0] += a.x*bq.x; acc[0][1] += a.x*bq.y; acc[0][2] += a.x*bq.z; acc[0][3] += a.x*bq.w;
            acc[1][0] += a.y*bq.x; acc[1][1] += a.y*bq.y; acc[1][2] += a.y*bq.z; acc[1][3] += a.y*bq.w;
            acc[2][0] += a.z*bq.x; acc[2][1] += a.z*bq.y; acc[2][2] += a.z*bq.z; acc[2][3] += a.z*bq.w;
            acc[3][0] += a.w*bq.x; acc[3][1] += a.w*bq.y; acc[3][2] += a.w*bq.z; acc[3][3] += a.w*bq.w;
        }
        #pragma unroll
        for (int j = 0; j < 4; j++) {
            float s = 0.f, ssum = 0.f;
            #pragma unroll
            for (int i = 0; i < 4; i++) {
                int kl = kl0 + i;
                if (kl < 65) {
                    float v = acc[j][i];
                    g_xs[(n*64 + o0 + j)*LTOT + kc*65 + kl] = v;
                    s += v; ssum += v*v;
                }
            }
            red_s [kg*64 + o0 + j] = s;
            red_ss[kg*64 + o0 + j] = ssum;
        }
    }
    __syncthreads();
    if (tid < 64) {
        float S = 0.f, SS = 0.f;
        for (int kg = 0; kg < 17; kg++) { S += red_s[kg*64 + tid]; SS += red_ss[kg*64 + tid]; }
        g_part2[(b*64 + tid)*2 + 0] = S;
        g_part2[(b*64 + tid)*2 + 1] = SS;
    }
}

// ---------------- K56: fused stats2 + xbar column + squeeze outputs (block per l) ----
__global__ void k56(const float* __restrict__ gs, const float* __restrict__ bes,
                    const float* __restrict__ Wt2, const float* __restrict__ bt2,
                    const float* __restrict__ Wv2, const float* __restrict__ bv2,
                    float* __restrict__ out_xtime)
{
    __shared__ float w2t[4096];      // transposed squeeze weight [d][o]
    __shared__ float red_a[256], red_b[256];
    __shared__ float stats2_s[128];  // m, rstd per o
    __shared__ float xbar_s[64];

    int l = blockIdx.x;              // 0..324
    int tid = threadIdx.x;

    // stage transposed weight for phase C (uniform branch per block)
    const float* W2 = (l < TB) ? Wt2 : Wv2;
    for (int i = tid; i < 4096; i += blockDim.x) {
        int o = i >> 6, d = i & 63;
        w2t[d*64 + o] = W2[i];
    }

    // ---- phase A: stats2 (redundant reduce of g_part2) ----
    {
        int o = tid & 63, sl = tid >> 6;     // 4 slices
        float s = 0.f, ss = 0.f;
        for (int ch = sl; ch < 320; ch += 4) {
            s  += g_part2[(ch*64 + o)*2 + 0];
            ss += g_part2[(ch*64 + o)*2 + 1];
        }
        red_a[tid] = s; red_b[tid] = ss;
        __syncthreads();
        if (tid < 64) {
            float S  = red_a[tid] + red_a[64+tid] + red_a[128+tid] + red_a[192+tid];
            float SS = red_b[tid] + red_b[64+tid] + red_b[128+tid] + red_b[192+tid];
            float cnt = 64.f * (float)LTOT;
            float m = S/cnt, v = SS/cnt - m*m;
            stats2_s[tid*2 + 0] = m;
            stats2_s[tid*2 + 1] = rsqrtf(v + EPSB);
        }
        __syncthreads();
    }

    // ---- phase B: xbar[:, l] = mean_n hardswish(bn(g_xs[:, :, l])) ----
    {
        int d = tid & 63, ns = tid >> 6;
        float m = stats2_s[d*2], r = stats2_s[d*2+1];
        float g = gs[d], bb = bes[d];
        float acc = 0.f;
        for (int n = ns; n < 64; n += 4)
            acc += hswish(g * (g_xs[(n*64 + d)*LTOT + l] - m) * r + bb);
        red_a[tid] = acc;
        __syncthreads();
        if (tid < 64)
            xbar_s[tid] = (red_a[tid] + red_a[64+tid] + red_a[128+tid] + red_a[192+tid]) * (1.0f/64.0f);
        __syncthreads();
    }

    // ---- phase C: squeeze dot + sigmoid (+tanh for view gate) ----
    if (tid < 64) {
        int o = tid;
        float acc = (l < TB) ? bt2[o] : bv2[o];
        #pragma unroll 8
        for (int d = 0; d < 64; d++) acc += w2t[d*64 + o] * xbar_s[d];
        float sg = 1.0f / (1.0f + expf(-acc));
        if (l < TB) out_xtime[o*TB + l] = sg;
        else        g_scale[(l - TB)*64 + o] = tanhf(sg) + 1.0f;
    }
}

// ---------------- K7: GEMM + inline BN partials ----------------
// block = (n, 10 t-rows), 512 threads; compute: 2 t-groups x (25 w x 8 ddg), 5t x 8dd, FFMA2.
#define XM_WP 66
#define XM_TP 1664
__global__ void k7(const float* __restrict__ x0, const float* __restrict__ Lw,
                   const float* __restrict__ Lb)
{
    extern __shared__ float sm7[];
    float* xsl = sm7;              // 64 c x 250  = 16000 (reused for BN partials)
    float* xm  = sm7 + 16000;      // 10 x 1664   = 16640
    float* lws = xm + 10*XM_TP;    // 4096
    float* ssc = lws + 4096;       // 1600
    float* lbs = ssc + 1600;       // 64
    float* bsum = xsl;             // alias after xsl dead: [2][1600]
    float* bsq  = xsl + 3200;      // [2][1600]

    int b = blockIdx.x;
    int n = b / (TB/K7T);
    int t0 = (b % (TB/K7T)) * K7T;
    int tid = threadIdx.x;

    const float* xbase = x0 + ((size_t)(n*64) * 300 + t0) * 25;
    for (int i = tid; i < 64*25*K7T; i += blockDim.x) {
        int c = i / (25*K7T), r = i % (25*K7T);
        xsl[i] = xbase[(size_t)c * 7500 + r];
    }
    for (int i = tid; i < 4096; i += blockDim.x) lws[i] = Lw[i];
    for (int i = tid; i < 1600; i += blockDim.x) ssc[i] = g_scale[i];
    if (tid < 64) lbs[tid] = Lb[tid];
    __syncthreads();

    // xm[t][w*66 + c] = x0[n,c,t0+t,(w+c)%25] * scale[w,c]
    for (int i = tid; i < K7T*1600; i += blockDim.x) {
        int t = i / 1600, rem = i % 1600;
        int w = rem >> 6, c = rem & 63;
        int v = (w + c) % 25;
        xm[t*XM_TP + w*XM_WP + c] = xsl[c*(25*K7T) + t*25 + v] * ssc[rem];
    }
    __syncthreads();

    int g = tid >> 8;            // t-group 0/1 (t = g*5 + 0..4)
    int r = tid & 255;
    bool active = (r < 200);
    float psum[8], psq[8];

    if (active) {
        int ddg = r & 7;
        int w   = r >> 3;
        int dd0 = ddg << 3;
        int w66 = w * XM_WP;
        const float* xg = xm + (g*5)*XM_TP + w66;

        unsigned long long acc[5][4];
        #pragma unroll
        for (int p = 0; p < 4; p++) {
            unsigned long long init = pk2(lbs[dd0 + 2*p], lbs[dd0 + 2*p + 1]);
            #pragma unroll
            for (int t = 0; t < 5; t++) acc[t][p] = init;
        }

        #pragma unroll 4
        for (int c = 0; c < 64; c++) {
            float a0 = xg[0*XM_TP + c];
            float a1 = xg[1*XM_TP + c];
            float a2 = xg[2*XM_TP + c];
            float a3 = xg[3*XM_TP + c];
            float a4 = xg[4*XM_TP + c];
            unsigned long long p0 = pk2(a0, a0);
            unsigned long long p1 = pk2(a1, a1);
            unsigned long long p2 = pk2(a2, a2);
            unsigned long long p3 = pk2(a3, a3);
            unsigned long long p4 = pk2(a4, a4);
            ulonglong2 b01 = *(const ulonglong2*)&lws[(c << 6) + dd0];
            ulonglong2 b23 = *(const ulonglong2*)&lws[(c << 6) + dd0 + 4];
            fma2(acc[0][0], p0, b01.x); fma2(acc[0][1], p0, b01.y);
            fma2(acc[0][2], p0, b23.x); fma2(acc[0][3], p0, b23.y);
            fma2(acc[1][0], p1, b01.x); fma2(acc[1][1], p1, b01.y);
            fma2(acc[1][2], p1, b23.x); fma2(acc[1][3], p1, b23.y);
            fma2(acc[2][0], p2, b01.x); fma2(acc[2][1], p2, b01.y);
            fma2(acc[2][2], p2, b23.x); fma2(acc[2][3], p2, b23.y);
            fma2(acc[3][0], p3, b01.x); fma2(acc[3][1], p3, b01.y);
            fma2(acc[3][2], p3, b23.x); fma2(acc[3][3], p3, b23.y);
            fma2(acc[4][0], p4, b01.x); fma2(acc[4][1], p4, b01.y);
            fma2(acc[4][2], p4, b23.x); fma2(acc[4][3], p4, b23.y);
        }

        #pragma unroll
        for (int j = 0; j < 8; j++) { psum[j] = 0.f; psq[j] = 0.f; }

        #pragma unroll
        for (int t = 0; t < 5; t++) {
            float vals[8];
            upk2(vals[0], vals[1], acc[t][0]);
            upk2(vals[2], vals[3], acc[t][1]);
            upk2(vals[4], vals[5], acc[t][2]);
            upk2(vals[6], vals[7], acc[t][3]);
            float* dst = &g_y0[(size_t)(n*300 + t0 + g*5 + t) * 1600 + (w << 6) + dd0];
            *(float4*)dst       = make_float4(vals[0], vals[1], vals[2], vals[3]);
            *(float4*)(dst + 4) = make_float4(vals[4], vals[5], vals[6], vals[7]);
            #pragma unroll
            for (int j = 0; j < 8; j++) { psum[j] += vals[j]; psq[j] += vals[j]*vals[j]; }
        }
    }
    __syncthreads();   // xsl dead; safe to alias as BN buffers
    if (active) {
        int ddg = r & 7, w = r >> 3, dd0 = ddg << 3;
        #pragma unroll
        for (int j = 0; j < 8; j++) {
            bsum[g*1600 + (w << 6) + dd0 + j] = psum[j];
            bsq [g*1600 + (w << 6) + dd0 + j] = psq[j];
        }
    }
    __syncthreads();
    for (int f = tid; f < 1600; f += blockDim.x) {
        g_part3[(size_t)b*3200 + f]        = bsum[f] + bsum[1600 + f];
        g_part3[(size_t)b*3200 + 1600 + f] = bsq[f]  + bsq[1600 + f];
    }
}

// ---------------- K8b: reduce BN partials -> per-feature stats ----------------
__global__ void k8b()
{
    __shared__ float red_s[256], red_ss[256];
    int f = blockIdx.x * 32 + (threadIdx.x & 31);
    int sl = threadIdx.x >> 5;     // 8 slices
    float s = 0.f, ss = 0.f;
    for (int b = sl; b < K7_BLOCKS; b += 8) {
        s  += g_part3[(size_t)b*3200 + f];
        ss += g_part3[(size_t)b*3200 + 1600 + f];
    }
    red_s[threadIdx.x] = s; red_ss[threadIdx.x] = ss;
    __syncthreads();
    if (threadIdx.x < 32) {
        float S = 0.f, SS = 0.f;
        #pragma unroll
        for (int k = 0; k < 8; k++) { S += red_s[k*32 + threadIdx.x]; SS += red_ss[k*32 + threadIdx.x]; }
        int ff = blockIdx.x * 32 + threadIdx.x;
        float cnt = (float)NTOT;
        float m = S/cnt, v = SS/cnt - m*m;
        g_stats3[ff*2 + 0] = m;
        g_stats3[ff*2 + 1] = rsqrtf(v + EPSB);
    }
}

// ---------------- K9: shift + BN + residual + relu ----------------
#define K9_TT 15
#define K9_PITCH 1632
__global__ void k9(const float* __restrict__ x0, const float* __restrict__ gbn,
                   const float* __restrict__ bbn, float* __restrict__ out)
{
    extern __shared__ float sm9[];
    float* ysm   = sm9;                       // 15 * 1632
    float* gbn_s = sm9 + K9_TT*K9_PITCH;
    float* bbn_s = gbn_s + 1600;

    int b = blockIdx.x;
    int n = b / 20, t0 = (b % 20) * K9_TT;
    int tid = threadIdx.x;

    for (int i = tid; i < 1600; i += blockDim.x) { gbn_s[i] = gbn[i]; bbn_s[i] = bbn[i]; }

    for (int t = 0; t < K9_TT; t++) {
        const float* row = &g_y0[(size_t)(n*300 + t0 + t) * 1600];
        for (int p = tid; p < 1600; p += blockDim.x) {
            float v = row[p];
            v = (v - g_stats3[p*2]) * g_stats3[p*2 + 1];
            int w = p >> 6, dd = p & 63;
            int i = (w + dd) % 25;
            ysm[t*K9_PITCH + i*65 + dd] = v;
        }
    }
    __syncthreads();

    for (int idx = tid; idx < 64 * K9_TT * 25; idx += blockDim.x) {
        int dd = idx / (K9_TT*25), r = idx % (K9_TT*25);
        int t = r / 25, i = r % 25;
        int f = i*64 + dd;
        float v = fmaf(gbn_s[f], ysm[t*K9_PITCH + i*65 + dd], bbn_s[f]);
        size_t go = ((size_t)(n*64 + dd) * 300 + t0) * 25 + r;
        v += x0[go];
        out[go] = fmaxf(v, 0.0f);
    }
}

// ---------------- launcher (6 launches; slot 4 = k7 for ncu capture) ----------------
extern "C" void kernel_launch(void* const* d_in, const int* in_sizes, int n_in,
                              void* d_out, int out_size)
{
    const float* x0  = (const float*)d_in[0];
    const float* Wv  = (const float*)d_in[3];
    const float* bv  = (const float*)d_in[4];
    const float* gv  = (const float*)d_in[5];
    const float* bev = (const float*)d_in[6];
    const float* Wt  = (const float*)d_in[7];
    const float* bt  = (const float*)d_in[8];
    const float* gt  = (const float*)d_in[9];
    const float* bet = (const float*)d_in[10];
    const float* Ws  = (const float*)d_in[11];
    const float* bs  = (const float*)d_in[12];
    const float* gs  = (const float*)d_in[13];
    const float* bes = (const float*)d_in[14];
    const float* Wv2 = (const float*)d_in[15];
    const float* bv2 = (const float*)d_in[16];
    const float* Wt2 = (const float*)d_in[17];
    const float* bt2 = (const float*)d_in[18];
    const float* Lw  = (const float*)d_in[19];
    const float* Lb  = (const float*)d_in[20];
    const float* gbn = (const float*)d_in[21];
    const float* bbn = (const float*)d_in[22];
    float* out = (float*)d_out;

    static_assert(K9_TT * 20 == TB, "t tiling");
    static_assert((TB % K7T) == 0, "k7 t tiling");

    const int smem3 = (64*68 + 4096 + 17*64*2) * 4;                         // 51200
    const int smem7 = (16000 + K7T*XM_TP + 4096 + 1600 + 64) * 4;           // 153600
    const int smem9 = (K9_TT*K9_PITCH + 1600 + 1600) * 4;                   // 110720
    cudaFuncSetAttribute(k3, cudaFuncAttributeMaxDynamicSharedMemorySize, smem3);
    cudaFuncSetAttribute(k7, cudaFuncAttributeMaxDynamicSharedMemorySize, smem7);
    cudaFuncSetAttribute(k9, cudaFuncAttributeMaxDynamicSharedMemorySize, smem9);

    k1 <<<NB*CB, 256>>>(x0, Wv, bv, Wt, bt);
    k3 <<<NB*5, 288, smem3>>>(gv, bev, gt, bet, Ws, bs);
    k56<<<LTOT, 256>>>(gs, bes, Wt2, bt2, Wv2, bv2, out + Y_SIZE);
    k7 <<<K7_BLOCKS, 512, smem7>>>(x0, Lw, Lb);
    k8b<<<FEAT/32, 256>>>();
    k9 <<<NB*20, 256, smem9>>>(x0, gbn, bbn, out);
}

// round 8
// speedup vs baseline: 1.0858x; 1.0849x over previous
#include <cuda_runtime.h>
#include <math.h>

// Problem constants
#define NB 64
#define CB 64
#define DB 64
#define TB 300
#define VB 25
#define EPSB 1e-5f
#define NTOT (NB*TB)          // 19200 rows
#define FEAT (VB*DB)          // 1600 features
#define LTOT (TB+VB)          // 325
#define Y_SIZE (NB*DB*TB*VB)  // 30720000

#define K7T 10                // t-rows per k7 block
#define K7_BLOCKS (NB*(TB/K7T))   // 1920

// ---------------- scratch (device globals; no runtime allocation) ----------------
__device__ float g_xv[NB*CB*TB];        // 4.9 MB
__device__ float g_xt[NB*CB*VB];        // 0.4 MB
__device__ float g_part1[NB*CB*4];      // per-(n,c) partials (sv,svv,st,stt)
__device__ float g_xs[NB*DB*LTOT];      // 5.3 MB
__device__ float g_part2[320*DB*2];     // per-(n,kc) per-o partials
__device__ float g_scale[VB*CB];        // tanh(sigmoid(view))+1, [w][c]
__device__ float g_y0[(size_t)NTOT*FEAT];     // 123 MB
__device__ float g_part3[K7_BLOCKS*3200];     // 24.6 MB : per-block BN partials
__device__ float g_stats3[FEAT*2];      // y0 feature mean/rstd

__device__ __forceinline__ float hswish(float x) {
    float c = fminf(fmaxf(x + 3.0f, 0.0f), 6.0f);
    return x * c * (1.0f / 6.0f);
}
__device__ __forceinline__ unsigned long long pk2(float lo, float hi) {
    unsigned long long r;
    asm("mov.b64 %0, {%1, %2};" : "=l"(r) : "f"(lo), "f"(hi));
    return r;
}
__device__ __forceinline__ void upk2(float& lo, float& hi, unsigned long long v) {
    asm("mov.b64 {%0, %1}, %2;" : "=f"(lo), "=f"(hi) : "l"(v));
}
__device__ __forceinline__ void fma2(unsigned long long& d, unsigned long long a, unsigned long long b) {
    asm("fma.rn.f32x2 %0, %1, %2, %0;" : "+l"(d) : "l"(a), "l"(b));
}

// ---------------- K1: per-(n,c) slice — xv (V-reduce) + xt (T-reduce) + partials ----
__global__ void k1(const float* __restrict__ x0, const float* __restrict__ Wv,
                   const float* __restrict__ bv, const float* __restrict__ Wt,
                   const float* __restrict__ bt)
{
    __shared__ float xs_[TB*VB];
    __shared__ float wt_[TB];
    __shared__ float wvc[VB];
    __shared__ float red[64];
    __shared__ float xta[VB];

    int nc = blockIdx.x;
    int c  = nc & 63;
    int tid = threadIdx.x;

    const float* src = x0 + (size_t)nc * (TB*VB);
    for (int i = tid; i < TB*VB; i += blockDim.x) xs_[i] = src[i];
    for (int i = tid; i < TB;    i += blockDim.x) wt_[i] = Wt[i];
    if (tid < VB) {
        int v = (tid - c) % VB; if (v < 0) v += VB;
        wvc[tid] = Wv[v];
    }
    float bvv = bv[0], btv = bt[0];
    __syncthreads();

    float s = 0.f, ss = 0.f;
    for (int t = tid; t < TB; t += blockDim.x) {
        float a = bvv;
        #pragma unroll
        for (int v = 0; v < VB; v++) a += wvc[v] * xs_[t*VB + v];
        g_xv[nc*TB + t] = a;
        s += a; ss += a*a;
    }
    #pragma unroll
    for (int o = 16; o; o >>= 1) {
        s  += __shfl_down_sync(0xffffffffu, s,  o);
        ss += __shfl_down_sync(0xffffffffu, ss, o);
    }
    if ((tid & 31) == 0) { red[tid>>5] = s; red[32 + (tid>>5)] = ss; }

    // xt: warps 0-6 fully execute shfl; lanes vp>=25 carry zeros
    if (tid < 224) {
        int vp = tid >> 3, sl = tid & 7;
        float a = 0.f;
        if (vp < VB) {
            for (int t = sl; t < TB; t += 8) a += wt_[t] * xs_[t*VB + vp];
        }
        a += __shfl_down_sync(0xffffffffu, a, 4);
        a += __shfl_down_sync(0xffffffffu, a, 2);
        a += __shfl_down_sync(0xffffffffu, a, 1);
        if (sl == 0 && vp < VB) {
            a += btv;
            int v = (vp - c) % VB; if (v < 0) v += VB;
            g_xt[nc*VB + v] = a;
            xta[vp] = a;
        }
    }
    __syncthreads();
    if (tid == 0) {
        float S = 0.f, SS = 0.f;
        for (int w = 0; w < (int)(blockDim.x >> 5); w++) { S += red[w]; SS += red[32+w]; }
        g_part1[nc*4 + 0] = S; g_part1[nc*4 + 1] = SS;
        S = 0.f; SS = 0.f;
        for (int v = 0; v < VB; v++) { S += xta[v]; SS += xta[v]*xta[v]; }
        g_part1[nc*4 + 2] = S; g_part1[nc*4 + 3] = SS;
    }
}

// ---------------- K3: inline stats1 + Ws stage (grid n x 5 chunks), 4x4 tiles ----------------
__global__ void k3(const float* __restrict__ gv, const float* __restrict__ bev,
                   const float* __restrict__ gt, const float* __restrict__ bet,
                   const float* __restrict__ Ws, const float* __restrict__ bs)
{
    extern __shared__ float sm3[];
    float* sfs    = sm3;            // [64][68]
    float* wst    = sm3 + 64*68;    // [64*64] transposed Ws
    float* red_s  = wst + 4096;     // [17][64]
    float* red_ss = red_s + 17*64;  // [17][64]
    __shared__ float rbuf[9*4];
    __shared__ float st1[4];        // mv, rv, mt, rt

    int b = blockIdx.x;
    int n = b / 5, kc = b % 5;
    int tid = threadIdx.x;

    // ---- inline k2: reduce g_part1 (redundant per block) ----
    {
        float a0=0.f, a1=0.f, a2=0.f, a3=0.f;
        for (int j = tid; j < NB*CB; j += blockDim.x) {
            a0 += g_part1[j*4+0]; a1 += g_part1[j*4+1];
            a2 += g_part1[j*4+2]; a3 += g_part1[j*4+3];
        }
        #pragma unroll
        for (int o = 16; o; o >>= 1) {
            a0 += __shfl_down_sync(0xffffffffu, a0, o);
            a1 += __shfl_down_sync(0xffffffffu, a1, o);
            a2 += __shfl_down_sync(0xffffffffu, a2, o);
            a3 += __shfl_down_sync(0xffffffffu, a3, o);
        }
        if ((tid & 31) == 0) {
            int w = tid >> 5;
            rbuf[w*4+0]=a0; rbuf[w*4+1]=a1; rbuf[w*4+2]=a2; rbuf[w*4+3]=a3;
        }
        __syncthreads();
        if (tid == 0) {
            float A0=0,A1=0,A2=0,A3=0;
            for (int w = 0; w < 9; w++) { A0+=rbuf[w*4]; A1+=rbuf[w*4+1]; A2+=rbuf[w*4+2]; A3+=rbuf[w*4+3]; }
            float cntv = (float)(NB*CB*TB), cntt = (float)(NB*CB*VB);
            float mv = A0/cntv, vv = A1/cntv - mv*mv;
            float mt = A2/cntt, vt = A3/cntt - mt*mt;
            st1[0] = mv; st1[1] = rsqrtf(vv + EPSB);
            st1[2] = mt; st1[3] = rsqrtf(vt + EPSB);
        }
        __syncthreads();
    }
    float mv = st1[0], rv = st1[1], mt = st1[2], rt = st1[3];
    float gvv = gv[0], bevv = bev[0], gtv = gt[0], betv = bet[0];

    // load/transform slice: flat p = cc*325 + k
    for (int i = tid; i < 64*68; i += blockDim.x) {
        int cc = i / 68, ll = i % 68;
        float val = 0.f;
        if (ll < 65) {
            int p = cc*LTOT + kc*65 + ll;
            if (p < 1600) {
                int cs = p / 25, v = p % 25;
                float x = g_xt[(n*64 + cs)*25 + v];
                val = hswish(gtv * (x - mt) * rt + betv);
            } else {
                int q = p - 1600;
                int cs = q / 300, t = q % 300;
                float x = g_xv[(n*64 + cs)*300 + t];
                val = hswish(gvv * (x - mv) * rv + bevv);
            }
        }
        sfs[i] = val;
    }
    for (int i = tid; i < 4096; i += blockDim.x) {
        int o = i & 63, cc = i >> 6;
        wst[i] = Ws[o*64 + cc];
    }
    __syncthreads();

    if (tid < 272) {
        int og = tid & 15, kg = tid >> 4;
        int o0 = og * 4, kl0 = kg * 4;
        float acc[4][4];
        #pragma unroll
        for (int j = 0; j < 4; j++) {
            float bb = bs[o0 + j];
            #pragma unroll
            for (int i = 0; i < 4; i++) acc[j][i] = bb;
        }
        for (int cc = 0; cc < 64; cc++) {
            float4 a = *(const float4*)&wst[cc*64 + o0];
            float4 bq = *(const float4*)&sfs[cc*68 + kl0];
            acc[0][0] += a.x*bq.x; acc[0][1] += a.x*bq.y; acc[0][2] += a.x*bq.z; acc[0][3] += a.x*bq.w;
            acc[1][0] += a.y*bq.x; acc[1][1] += a.y*bq.y; acc[1][2] += a.y*bq.z; acc[1][3] += a.y*bq.w;
            acc[2][0] += a.z*bq.x; acc[2][1] += a.z*bq.y; acc[2][2] += a.z*bq.z; acc[2][3] += a.z*bq.w;
            acc[3][0] += a.w*bq.x; acc[3][1] += a.w*bq.y; acc[3][2] += a.w*bq.z; acc[3][3] += a.w*bq.w;
        }
        #pragma unroll
        for (int j = 0; j < 4; j++) {
            float s = 0.f, ssum = 0.f;
            #pragma unroll
            for (int i = 0; i < 4; i++) {
                int kl = kl0 + i;
                if (kl < 65) {
                    float v = acc[j][i];
                    g_xs[(n*64 + o0 + j)*LTOT + kc*65 + kl] = v;
                    s += v; ssum += v*v;
                }
            }
            red_s [kg*64 + o0 + j] = s;
            red_ss[kg*64 + o0 + j] = ssum;
        }
    }
    __syncthreads();
    if (tid < 64) {
        float S = 0.f, SS = 0.f;
        for (int kg = 0; kg < 17; kg++) { S += red_s[kg*64 + tid]; SS += red_ss[kg*64 + tid]; }
        g_part2[(b*64 + tid)*2 + 0] = S;
        g_part2[(b*64 + tid)*2 + 1] = SS;
    }
}

// ---------------- K56: fused stats2 + xbar column + squeeze outputs (block per l) ----
__global__ void k56(const float* __restrict__ gs, const float* __restrict__ bes,
                    const float* __restrict__ Wt2, const float* __restrict__ bt2,
                    const float* __restrict__ Wv2, const float* __restrict__ bv2,
                    float* __restrict__ out_xtime)
{
    __shared__ float w2t[4096];      // transposed squeeze weight [d][o]
    __shared__ float red_a[256], red_b[256];
    __shared__ float stats2_s[128];  // m, rstd per o
    __shared__ float xbar_s[64];

    int l = blockIdx.x;              // 0..324
    int tid = threadIdx.x;

    const float* W2 = (l < TB) ? Wt2 : Wv2;
    for (int i = tid; i < 4096; i += blockDim.x) {
        int o = i >> 6, d = i & 63;
        w2t[d*64 + o] = W2[i];
    }

    // ---- phase A: stats2 (redundant reduce of g_part2) ----
    {
        int o = tid & 63, sl = tid >> 6;
        float s = 0.f, ss = 0.f;
        for (int ch = sl; ch < 320; ch += 4) {
            s  += g_part2[(ch*64 + o)*2 + 0];
            ss += g_part2[(ch*64 + o)*2 + 1];
        }
        red_a[tid] = s; red_b[tid] = ss;
        __syncthreads();
        if (tid < 64) {
            float S  = red_a[tid] + red_a[64+tid] + red_a[128+tid] + red_a[192+tid];
            float SS = red_b[tid] + red_b[64+tid] + red_b[128+tid] + red_b[192+tid];
            float cnt = 64.f * (float)LTOT;
            float m = S/cnt, v = SS/cnt - m*m;
            stats2_s[tid*2 + 0] = m;
            stats2_s[tid*2 + 1] = rsqrtf(v + EPSB);
        }
        __syncthreads();
    }

    // ---- phase B: xbar[:, l] = mean_n hardswish(bn(g_xs[:, :, l])) ----
    {
        int d = tid & 63, ns = tid >> 6;
        float m = stats2_s[d*2], r = stats2_s[d*2+1];
        float g = gs[d], bb = bes[d];
        float acc = 0.f;
        for (int n = ns; n < 64; n += 4)
            acc += hswish(g * (g_xs[(n*64 + d)*LTOT + l] - m) * r + bb);
        red_a[tid] = acc;
        __syncthreads();
        if (tid < 64)
            xbar_s[tid] = (red_a[tid] + red_a[64+tid] + red_a[128+tid] + red_a[192+tid]) * (1.0f/64.0f);
        __syncthreads();
    }

    // ---- phase C: squeeze dot + sigmoid (+tanh for view gate) ----
    if (tid < 64) {
        int o = tid;
        float acc = (l < TB) ? bt2[o] : bv2[o];
        #pragma unroll 8
        for (int d = 0; d < 64; d++) acc += w2t[d*64 + o] * xbar_s[d];
        float sg = 1.0f / (1.0f + expf(-acc));
        if (l < TB) out_xtime[o*TB + l] = sg;
        else        g_scale[(l - TB)*64 + o] = tanhf(sg) + 1.0f;
    }
}

// ---------------- K7: GEMM + inline BN partials (packed-pair layout) ----------------
// block = (n, 10 t-rows), 512 threads (400 compute: 25 w x 16 ddg), 10t x 4dd, FFMA2.
// xmp[w][c][t]: t contiguous -> LDS.64 yields packed (a_t, a_{t+1}) directly.
#define XMP_WS 642      // per-w stride (64*10 + 2 pad; even => LDS.64 aligned, bank-spread)
#define XMP_TOT 16064   // 25*642 = 16050, padded to multiple of 4 so lws is 16B-aligned
__global__ void k7(const float* __restrict__ x0, const float* __restrict__ Lw,
                   const float* __restrict__ Lb)
{
    extern __shared__ float sm7[];
    float* xmp = sm7;                 // 16050 used (16064 reserved)
    float* lws = sm7 + XMP_TOT;       // 4096, 16B-aligned
    float* ssc = lws + 4096;          // 25*65 = 1625 (padded stride 65)
    float* lbs = ssc + 1625;          // 64

    int b = blockIdx.x;
    int n = b / (TB/K7T);
    int t0 = (b % (TB/K7T)) * K7T;
    int tid = threadIdx.x;

    for (int i = tid; i < 4096; i += 512) lws[i] = Lw[i];
    for (int i = tid; i < VB*CB; i += 512) {
        int w = i >> 6, c = i & 63;
        ssc[w*65 + c] = g_scale[i];
    }
    if (tid < 64) lbs[tid] = Lb[tid];
    __syncthreads();

    // build xmp[w*642 + c*10 + t] = x0[n,c,t0+t,v] * scale[w,c], w = (v - c) mod 25
    const float* xbase = x0 + ((size_t)(n*64) * 300 + t0) * 25;
    for (int i = tid; i < 64*25*K7T; i += 512) {
        int c = i / (25*K7T), r = i % (25*K7T);
        int t = r / 25, v = r % 25;
        int w = v - (c % 25); if (w < 0) w += 25;
        xmp[w*XMP_WS + c*10 + t] = xbase[(size_t)c * 7500 + r] * ssc[w*65 + c];
    }
    __syncthreads();

    if (tid < 400) {
        int ddg = tid & 15, w = tid >> 4;
        int dd0 = ddg << 2;
        const float* xw = xmp + w*XMP_WS;

        unsigned long long acc[5][4];
        #pragma unroll
        for (int j = 0; j < 4; j++) {
            unsigned long long init = pk2(lbs[dd0 + j], lbs[dd0 + j]);
            #pragma unroll
            for (int tp = 0; tp < 5; tp++) acc[tp][j] = init;
        }

        #pragma unroll 4
        for (int c = 0; c < 64; c++) {
            unsigned long long a0 = *(const unsigned long long*)&xw[c*10 + 0];
            unsigned long long a1 = *(const unsigned long long*)&xw[c*10 + 2];
            unsigned long long a2 = *(const unsigned long long*)&xw[c*10 + 4];
            unsigned long long a3 = *(const unsigned long long*)&xw[c*10 + 6];
            unsigned long long a4 = *(const unsigned long long*)&xw[c*10 + 8];
            float4 bv4 = *(const float4*)&lws[(c << 6) + dd0];
            unsigned long long b0 = pk2(bv4.x, bv4.x);
            unsigned long long b1 = pk2(bv4.y, bv4.y);
            unsigned long long b2 = pk2(bv4.z, bv4.z);
            unsigned long long b3 = pk2(bv4.w, bv4.w);
            fma2(acc[0][0], a0, b0); fma2(acc[0][1], a0, b1);
            fma2(acc[0][2], a0, b2); fma2(acc[0][3], a0, b3);
            fma2(acc[1][0], a1, b0); fma2(acc[1][1], a1, b1);
            fma2(acc[1][2], a1, b2); fma2(acc[1][3], a1, b3);
            fma2(acc[2][0], a2, b0); fma2(acc[2][1], a2, b1);
            fma2(acc[2][2], a2, b2); fma2(acc[2][3], a2, b3);
            fma2(acc[3][0], a3, b0); fma2(acc[3][1], a3, b1);
            fma2(acc[3][2], a3, b2); fma2(acc[3][3], a3, b3);
            fma2(acc[4][0], a4, b0); fma2(acc[4][1], a4, b1);
            fma2(acc[4][2], a4, b2); fma2(acc[4][3], a4, b3);
        }

        float psum[4] = {0.f, 0.f, 0.f, 0.f};
        float psq [4] = {0.f, 0.f, 0.f, 0.f};
        #pragma unroll
        for (int tp = 0; tp < 5; tp++) {
            float e0, o0, e1, o1, e2, o2, e3, o3;
            upk2(e0, o0, acc[tp][0]);
            upk2(e1, o1, acc[tp][1]);
            upk2(e2, o2, acc[tp][2]);
            upk2(e3, o3, acc[tp][3]);
            size_t rowe = (size_t)(n*300 + t0 + 2*tp) * 1600 + (w << 6) + dd0;
            *(float4*)&g_y0[rowe]        = make_float4(e0, e1, e2, e3);
            *(float4*)&g_y0[rowe + 1600] = make_float4(o0, o1, o2, o3);
            psum[0] += e0 + o0; psq[0] += e0*e0 + o0*o0;
            psum[1] += e1 + o1; psq[1] += e1*e1 + o1*o1;
            psum[2] += e2 + o2; psq[2] += e2*e2 + o2*o2;
            psum[3] += e3 + o3; psq[3] += e3*e3 + o3*o3;
        }
        // per-block BN partials: each thread owns features w*64+dd0..+3 exclusively
        *(float4*)&g_part3[(size_t)b*3200 + (w << 6) + dd0]        = make_float4(psum[0], psum[1], psum[2], psum[3]);
        *(float4*)&g_part3[(size_t)b*3200 + 1600 + (w << 6) + dd0] = make_float4(psq[0],  psq[1],  psq[2],  psq[3]);
    }
}

// ---------------- K8b: reduce BN partials -> per-feature stats ----------------
__global__ void k8b()
{
    __shared__ float red_s[256], red_ss[256];
    int f = blockIdx.x * 32 + (threadIdx.x & 31);
    int sl = threadIdx.x >> 5;     // 8 slices
    float s = 0.f, ss = 0.f;
    for (int b = sl; b < K7_BLOCKS; b += 8) {
        s  += g_part3[(size_t)b*3200 + f];
        ss += g_part3[(size_t)b*3200 + 1600 + f];
    }
    red_s[threadIdx.x] = s; red_ss[threadIdx.x] = ss;
    __syncthreads();
    if (threadIdx.x < 32) {
        float S = 0.f, SS = 0.f;
        #pragma unroll
        for (int k = 0; k < 8; k++) { S += red_s[k*32 + threadIdx.x]; SS += red_ss[k*32 + threadIdx.x]; }
        int ff = blockIdx.x * 32 + threadIdx.x;
        float cnt = (float)NTOT;
        float m = S/cnt, v = SS/cnt - m*m;
        g_stats3[ff*2 + 0] = m;
        g_stats3[ff*2 + 1] = rsqrtf(v + EPSB);
    }
}

// ---------------- K9: shift + BN + residual + relu ----------------
#define K9_TT 15
#define K9_PITCH 1632
__global__ void k9(const float* __restrict__ x0, const float* __restrict__ gbn,
                   const float* __restrict__ bbn, float* __restrict__ out)
{
    extern __shared__ float sm9[];
    float* ysm   = sm9;                       // 15 * 1632
    float* gbn_s = sm9 + K9_TT*K9_PITCH;
    float* bbn_s = gbn_s + 1600;

    int b = blockIdx.x;
    int n = b / 20, t0 = (b % 20) * K9_TT;
    int tid = threadIdx.x;

    for (int i = tid; i < 1600; i += blockDim.x) { gbn_s[i] = gbn[i]; bbn_s[i] = bbn[i]; }

    for (int t = 0; t < K9_TT; t++) {
        const float* row = &g_y0[(size_t)(n*300 + t0 + t) * 1600];
        for (int p = tid; p < 1600; p += blockDim.x) {
            float v = row[p];
            v = (v - g_stats3[p*2]) * g_stats3[p*2 + 1];
            int w = p >> 6, dd = p & 63;
            int i = (w + dd) % 25;
            ysm[t*K9_PITCH + i*65 + dd] = v;
        }
    }
    __syncthreads();

    for (int idx = tid; idx < 64 * K9_TT * 25; idx += blockDim.x) {
        int dd = idx / (K9_TT*25), r = idx % (K9_TT*25);
        int t = r / 25, i = r % 25;
        int f = i*64 + dd;
        float v = fmaf(gbn_s[f], ysm[t*K9_PITCH + i*65 + dd], bbn_s[f]);
        size_t go = ((size_t)(n*64 + dd) * 300 + t0) * 25 + r;
        v += x0[go];
        out[go] = fmaxf(v, 0.0f);
    }
}

// ---------------- launcher (6 launches; slot 4 = k7 for ncu capture) ----------------
extern "C" void kernel_launch(void* const* d_in, const int* in_sizes, int n_in,
                              void* d_out, int out_size)
{
    const float* x0  = (const float*)d_in[0];
    const float* Wv  = (const float*)d_in[3];
    const float* bv  = (const float*)d_in[4];
    const float* gv  = (const float*)d_in[5];
    const float* bev = (const float*)d_in[6];
    const float* Wt  = (const float*)d_in[7];
    const float* bt  = (const float*)d_in[8];
    const float* gt  = (const float*)d_in[9];
    const float* bet = (const float*)d_in[10];
    const float* Ws  = (const float*)d_in[11];
    const float* bs  = (const float*)d_in[12];
    const float* gs  = (const float*)d_in[13];
    const float* bes = (const float*)d_in[14];
    const float* Wv2 = (const float*)d_in[15];
    const float* bv2 = (const float*)d_in[16];
    const float* Wt2 = (const float*)d_in[17];
    const float* bt2 = (const float*)d_in[18];
    const float* Lw  = (const float*)d_in[19];
    const float* Lb  = (const float*)d_in[20];
    const float* gbn = (const float*)d_in[21];
    const float* bbn = (const float*)d_in[22];
    float* out = (float*)d_out;

    static_assert(K9_TT * 20 == TB, "t tiling");
    static_assert((TB % K7T) == 0, "k7 t tiling");
    static_assert((XMP_TOT % 4) == 0 && XMP_TOT >= VB*XMP_WS, "xmp pad");

    const int smem3 = (64*68 + 4096 + 17*64*2) * 4;                 // 51200
    const int smem7 = (XMP_TOT + 4096 + 1625 + 64) * 4;             // 87396
    const int smem9 = (K9_TT*K9_PITCH + 1600 + 1600) * 4;           // 110720
    cudaFuncSetAttribute(k3, cudaFuncAttributeMaxDynamicSharedMemorySize, smem3);
    cudaFuncSetAttribute(k7, cudaFuncAttributeMaxDynamicSharedMemorySize, smem7);
    cudaFuncSetAttribute(k9, cudaFuncAttributeMaxDynamicSharedMemorySize, smem9);

    k1 <<<NB*CB, 256>>>(x0, Wv, bv, Wt, bt);
    k3 <<<NB*5, 288, smem3>>>(gv, bev, gt, bet, Ws, bs);
    k56<<<LTOT, 256>>>(gs, bes, Wt2, bt2, Wv2, bv2, out + Y_SIZE);
    k7 <<<K7_BLOCKS, 512, smem7>>>(x0, Lw, Lb);
    k8b<<<FEAT/32, 256>>>();
    k9 <<<NB*20, 256, smem9>>>(x0, gbn, bbn, out);
}

// round 10
// speedup vs baseline: 1.4132x; 1.3014x over previous
#include <cuda_runtime.h>
#include <math.h>

// Problem constants
#define NB 64
#define CB 64
#define DB 64
#define TB 300
#define VB 25
#define EPSB 1e-5f
#define NTOT (NB*TB)          // 19200 rows
#define FEAT (VB*DB)          // 1600 features
#define LTOT (TB+VB)          // 325
#define Y_SIZE (NB*DB*TB*VB)  // 30720000

#define K7T 10                // t-rows per k7 block
#define K7_BLOCKS (NB*(TB/K7T))   // 1920

// ---------------- scratch (device globals; no runtime allocation) ----------------
__device__ float g_xv[NB*CB*TB];        // 4.9 MB
__device__ float g_xt[NB*CB*VB];        // 0.4 MB
__device__ float g_part1[NB*CB*4];      // per-(n,c) partials (sv,svv,st,stt)
__device__ float g_xs[NB*DB*LTOT];      // 5.3 MB
__device__ float g_part2[320*DB*2];     // per-(n,kc) per-o partials
__device__ float g_scale[VB*CB];        // tanh(sigmoid(view))+1, [w][c]
__device__ float g_y0[(size_t)NTOT*FEAT];     // 123 MB
__device__ float g_part3[K7_BLOCKS*3200];     // 24.6 MB : per-block BN partials
__device__ float g_stats3[FEAT*2];      // y0 feature mean/rstd

__device__ __forceinline__ float hswish(float x) {
    float c = fminf(fmaxf(x + 3.0f, 0.0f), 6.0f);
    return x * c * (1.0f / 6.0f);
}
__device__ __forceinline__ unsigned long long pk2(float lo, float hi) {
    unsigned long long r;
    asm("mov.b64 %0, {%1, %2};" : "=l"(r) : "f"(lo), "f"(hi));
    return r;
}
__device__ __forceinline__ void upk2(float& lo, float& hi, unsigned long long v) {
    asm("mov.b64 {%0, %1}, %2;" : "=f"(lo), "=f"(hi) : "l"(v));
}
__device__ __forceinline__ void fma2(unsigned long long& d, unsigned long long a, unsigned long long b) {
    asm("fma.rn.f32x2 %0, %1, %2, %0;" : "+l"(d) : "l"(a), "l"(b));
}

// ---------------- K1: per-(n,c) slice — xv (V-reduce) + xt (T-reduce) + partials ----
__global__ void k1(const float* __restrict__ x0, const float* __restrict__ Wv,
                   const float* __restrict__ bv, const float* __restrict__ Wt,
                   const float* __restrict__ bt)
{
    __shared__ float xs_[TB*VB];
    __shared__ float wt_[TB];
    __shared__ float wvc[VB];
    __shared__ float red[64];
    __shared__ float xta[VB];

    int nc = blockIdx.x;
    int c  = nc & 63;
    int tid = threadIdx.x;

    // x0 row is 7500 floats = 1875 float4, 16B-aligned (nc*30000 % 16 == 0)
    const float4* src4 = (const float4*)(x0 + (size_t)nc * (TB*VB));
    for (int i = tid; i < 1875; i += blockDim.x) ((float4*)xs_)[i] = src4[i];
    for (int i = tid; i < TB;   i += blockDim.x) wt_[i] = Wt[i];
    if (tid < VB) {
        int v = (tid - c) % VB; if (v < 0) v += VB;
        wvc[tid] = Wv[v];
    }
    float bvv = bv[0], btv = bt[0];
    __syncthreads();

    float s = 0.f, ss = 0.f;
    for (int t = tid; t < TB; t += blockDim.x) {
        float a = bvv;
        #pragma unroll
        for (int v = 0; v < VB; v++) a += wvc[v] * xs_[t*VB + v];
        g_xv[nc*TB + t] = a;
        s += a; ss += a*a;
    }
    #pragma unroll
    for (int o = 16; o; o >>= 1) {
        s  += __shfl_down_sync(0xffffffffu, s,  o);
        ss += __shfl_down_sync(0xffffffffu, ss, o);
    }
    if ((tid & 31) == 0) { red[tid>>5] = s; red[32 + (tid>>5)] = ss; }

    // xt: warps 0-6 fully execute shfl; lanes vp>=25 carry zeros
    if (tid < 224) {
        int vp = tid >> 3, sl = tid & 7;
        float a = 0.f;
        if (vp < VB) {
            for (int t = sl; t < TB; t += 8) a += wt_[t] * xs_[t*VB + vp];
        }
        a += __shfl_down_sync(0xffffffffu, a, 4);
        a += __shfl_down_sync(0xffffffffu, a, 2);
        a += __shfl_down_sync(0xffffffffu, a, 1);
        if (sl == 0 && vp < VB) {
            a += btv;
            int v = (vp - c) % VB; if (v < 0) v += VB;
            g_xt[nc*VB + v] = a;
            xta[vp] = a;
        }
    }
    __syncthreads();
    if (tid == 0) {
        float S = 0.f, SS = 0.f;
        for (int w = 0; w < (int)(blockDim.x >> 5); w++) { S += red[w]; SS += red[32+w]; }
        g_part1[nc*4 + 0] = S; g_part1[nc*4 + 1] = SS;
        S = 0.f; SS = 0.f;
        for (int v = 0; v < VB; v++) { S += xta[v]; SS += xta[v]*xta[v]; }
        g_part1[nc*4 + 2] = S; g_part1[nc*4 + 3] = SS;
    }
}

// ---------------- K3: inline stats1 + Ws stage (grid n x 5 chunks), 4x4 tiles ----------------
__global__ void k3(const float* __restrict__ gv, const float* __restrict__ bev,
                   const float* __restrict__ gt, const float* __restrict__ bet,
                   const float* __restrict__ Ws, const float* __restrict__ bs)
{
    extern __shared__ float sm3[];
    float* sfs    = sm3;            // [64][68]
    float* wst    = sm3 + 64*68;    // [64*64] transposed Ws
    float* red_s  = wst + 4096;     // [17][64]
    float* red_ss = red_s + 17*64;  // [17][64]
    __shared__ float rbuf[9*4];
    __shared__ float st1[4];        // mv, rv, mt, rt

    int b = blockIdx.x;
    int n = b / 5, kc = b % 5;
    int tid = threadIdx.x;

    // ---- inline k2: reduce g_part1 (redundant per block) ----
    {
        float a0=0.f, a1=0.f, a2=0.f, a3=0.f;
        for (int j = tid; j < NB*CB; j += blockDim.x) {
            a0 += g_part1[j*4+0]; a1 += g_part1[j*4+1];
            a2 += g_part1[j*4+2]; a3 += g_part1[j*4+3];
        }
        #pragma unroll
        for (int o = 16; o; o >>= 1) {
            a0 += __shfl_down_sync(0xffffffffu, a0, o);
            a1 += __shfl_down_sync(0xffffffffu, a1, o);
            a2 += __shfl_down_sync(0xffffffffu, a2, o);
            a3 += __shfl_down_sync(0xffffffffu, a3, o);
        }
        if ((tid & 31) == 0) {
            int w = tid >> 5;
            rbuf[w*4+0]=a0; rbuf[w*4+1]=a1; rbuf[w*4+2]=a2; rbuf[w*4+3]=a3;
        }
        __syncthreads();
        if (tid == 0) {
            float A0=0,A1=0,A2=0,A3=0;
            for (int w = 0; w < 9; w++) { A0+=rbuf[w*4]; A1+=rbuf[w*4+1]; A2+=rbuf[w*4+2]; A3+=rbuf[w*4+3]; }
            float cntv = (float)(NB*CB*TB), cntt = (float)(NB*CB*VB);
            float mv = A0/cntv, vv = A1/cntv - mv*mv;
            float mt = A2/cntt, vt = A3/cntt - mt*mt;
            st1[0] = mv; st1[1] = rsqrtf(vv + EPSB);
            st1[2] = mt; st1[3] = rsqrtf(vt + EPSB);
        }
        __syncthreads();
    }
    float mv = st1[0], rv = st1[1], mt = st1[2], rt = st1[3];
    float gvv = gv[0], bevv = bev[0], gtv = gt[0], betv = bet[0];

    // load/transform slice: flat p = cc*325 + k
    for (int i = tid; i < 64*68; i += blockDim.x) {
        int cc = i / 68, ll = i % 68;
        float val = 0.f;
        if (ll < 65) {
            int p = cc*LTOT + kc*65 + ll;
            if (p < 1600) {
                int cs = p / 25, v = p % 25;
                float x = g_xt[(n*64 + cs)*25 + v];
                val = hswish(gtv * (x - mt) * rt + betv);
            } else {
                int q = p - 1600;
                int cs = q / 300, t = q % 300;
                float x = g_xv[(n*64 + cs)*300 + t];
                val = hswish(gvv * (x - mv) * rv + bevv);
            }
        }
        sfs[i] = val;
    }
    for (int i = tid; i < 4096; i += blockDim.x) {
        int o = i & 63, cc = i >> 6;
        wst[i] = Ws[o*64 + cc];
    }
    __syncthreads();

    if (tid < 272) {
        int og = tid & 15, kg = tid >> 4;
        int o0 = og * 4, kl0 = kg * 4;
        float acc[4][4];
        #pragma unroll
        for (int j = 0; j < 4; j++) {
            float bb = bs[o0 + j];
            #pragma unroll
            for (int i = 0; i < 4; i++) acc[j][i] = bb;
        }
        for (int cc = 0; cc < 64; cc++) {
            float4 a = *(const float4*)&wst[cc*64 + o0];
            float4 bq = *(const float4*)&sfs[cc*68 + kl0];
            acc[0][0] += a.x*bq.x; acc[0][1] += a.x*bq.y; acc[0][2] += a.x*bq.z; acc[0][3] += a.x*bq.w;
            acc[1][0] += a.y*bq.x; acc[1][1] += a.y*bq.y; acc[1][2] += a.y*bq.z; acc[1][3] += a.y*bq.w;
            acc[2][0] += a.z*bq.x; acc[2][1] += a.z*bq.y; acc[2][2] += a.z*bq.z; acc[2][3] += a.z*bq.w;
            acc[3][0] += a.w*bq.x; acc[3][1] += a.w*bq.y; acc[3][2] += a.w*bq.z; acc[3][3] += a.w*bq.w;
        }
        #pragma unroll
        for (int j = 0; j < 4; j++) {
            float s = 0.f, ssum = 0.f;
            #pragma unroll
            for (int i = 0; i < 4; i++) {
                int kl = kl0 + i;
                if (kl < 65) {
                    float v = acc[j][i];
                    g_xs[(n*64 + o0 + j)*LTOT + kc*65 + kl] = v;
                    s += v; ssum += v*v;
                }
            }
            red_s [kg*64 + o0 + j] = s;
            red_ss[kg*64 + o0 + j] = ssum;
        }
    }
    __syncthreads();
    if (tid < 64) {
        float S = 0.f, SS = 0.f;
        for (int kg = 0; kg < 17; kg++) { S += red_s[kg*64 + tid]; SS += red_ss[kg*64 + tid]; }
        g_part2[(b*64 + tid)*2 + 0] = S;
        g_part2[(b*64 + tid)*2 + 1] = SS;
    }
}

// ---------------- K56: fused stats2 + xbar column + squeeze outputs (block per l) ----
__global__ void k56(const float* __restrict__ gs, const float* __restrict__ bes,
                    const float* __restrict__ Wt2, const float* __restrict__ bt2,
                    const float* __restrict__ Wv2, const float* __restrict__ bv2,
                    float* __restrict__ out_xtime)
{
    __shared__ float w2t[4096];      // transposed squeeze weight [d][o]
    __shared__ float red_a[256], red_b[256];
    __shared__ float stats2_s[128];  // m, rstd per o
    __shared__ float xbar_s[64];

    int l = blockIdx.x;              // 0..324
    int tid = threadIdx.x;

    const float* W2 = (l < TB) ? Wt2 : Wv2;
    for (int i = tid; i < 4096; i += blockDim.x) {
        int o = i >> 6, d = i & 63;
        w2t[d*64 + o] = W2[i];
    }

    // ---- phase A: stats2 (redundant reduce of g_part2) ----
    {
        int o = tid & 63, sl = tid >> 6;
        float s = 0.f, ss = 0.f;
        for (int ch = sl; ch < 320; ch += 4) {
            s  += g_part2[(ch*64 + o)*2 + 0];
            ss += g_part2[(ch*64 + o)*2 + 1];
        }
        red_a[tid] = s; red_b[tid] = ss;
        __syncthreads();
        if (tid < 64) {
            float S  = red_a[tid] + red_a[64+tid] + red_a[128+tid] + red_a[192+tid];
            float SS = red_b[tid] + red_b[64+tid] + red_b[128+tid] + red_b[192+tid];
            float cnt = 64.f * (float)LTOT;
            float m = S/cnt, v = SS/cnt - m*m;
            stats2_s[tid*2 + 0] = m;
            stats2_s[tid*2 + 1] = rsqrtf(v + EPSB);
        }
        __syncthreads();
    }

    // ---- phase B: xbar[:, l] = mean_n hardswish(bn(g_xs[:, :, l])) ----
    {
        int d = tid & 63, ns = tid >> 6;
        float m = stats2_s[d*2], r = stats2_s[d*2+1];
        float g = gs[d], bb = bes[d];
        float acc = 0.f;
        for (int n = ns; n < 64; n += 4)
            acc += hswish(g * (g_xs[(n*64 + d)*LTOT + l] - m) * r + bb);
        red_a[tid] = acc;
        __syncthreads();
        if (tid < 64)
            xbar_s[tid] = (red_a[tid] + red_a[64+tid] + red_a[128+tid] + red_a[192+tid]) * (1.0f/64.0f);
        __syncthreads();
    }

    // ---- phase C: squeeze dot + sigmoid (+tanh for view gate) ----
    if (tid < 64) {
        int o = tid;
        float acc = (l < TB) ? bt2[o] : bv2[o];
        #pragma unroll 8
        for (int d = 0; d < 64; d++) acc += w2t[d*64 + o] * xbar_s[d];
        float sg = 1.0f / (1.0f + expf(-acc));
        if (l < TB) out_xtime[o*TB + l] = sg;
        else        g_scale[(l - TB)*64 + o] = tanhf(sg) + 1.0f;
    }
}

// ---------------- K7: GEMM + inline BN partials (packed-pair layout, 1024 thr) ----------------
// block = (n, 10 t-rows), 1024 threads (800 compute: warp w 0..24, lane = ddg 0..31),
// 10t x 2dd per thread, FFMA2. xmp[w][c][t]: t contiguous -> LDS.64 = packed (a_t, a_{t+1}).
#define XMP_WS 642      // per-w stride (64*10 + 2 pad)
#define XMP_TOT 16064   // 25*642 padded so lws is 16B-aligned
__global__ void __launch_bounds__(1024, 1)
k7(const float* __restrict__ x0, const float* __restrict__ Lw,
   const float* __restrict__ Lb)
{
    extern __shared__ float sm7[];
    float* xmp = sm7;                 // 16050 used (16064 reserved)
    float* lws = sm7 + XMP_TOT;       // 4096, 16B-aligned
    float* ssc = lws + 4096;          // 25*65
    float* lbs = ssc + 1625;          // 64

    int b = blockIdx.x;
    int n = b / (TB/K7T);
    int t0 = (b % (TB/K7T)) * K7T;
    int tid = threadIdx.x;

    for (int i = tid; i < 4096; i += 1024) lws[i] = Lw[i];
    for (int i = tid; i < VB*CB; i += 1024) {      // FIX: was if(tid<1600) with 1024 threads
        int w = i >> 6, c = i & 63;
        ssc[w*65 + c] = g_scale[i];
    }
    if (tid < 64) lbs[tid] = Lb[tid];
    __syncthreads();

    // build xmp[w*642 + c*10 + t] = x0[n,c,t0+t,v] * scale[w,c], w = (v - c) mod 25
    const float* xbase = x0 + ((size_t)(n*64) * 300 + t0) * 25;
    for (int i = tid; i < 64*25*K7T; i += 1024) {
        int c = i / (25*K7T), r = i % (25*K7T);
        int t = r / 25, v = r % 25;
        int w = v - (c % 25); if (w < 0) w += 25;
        xmp[w*XMP_WS + c*10 + t] = xbase[(size_t)c * 7500 + r] * ssc[w*65 + c];
    }
    __syncthreads();

    int w   = tid >> 5;     // warp index == w
    int ddg = tid & 31;
    if (w < 25) {
        int dd0 = ddg << 1;
        const float* xw = xmp + w*XMP_WS;

        unsigned long long acc[5][2];
        {
            unsigned long long i0 = pk2(lbs[dd0],     lbs[dd0]);
            unsigned long long i1 = pk2(lbs[dd0 + 1], lbs[dd0 + 1]);
            #pragma unroll
            for (int tp = 0; tp < 5; tp++) { acc[tp][0] = i0; acc[tp][1] = i1; }
        }

        #pragma unroll 4
        for (int c = 0; c < 64; c++) {
            unsigned long long a0 = *(const unsigned long long*)&xw[c*10 + 0];
            unsigned long long a1 = *(const unsigned long long*)&xw[c*10 + 2];
            unsigned long long a2 = *(const unsigned long long*)&xw[c*10 + 4];
            unsigned long long a3 = *(const unsigned long long*)&xw[c*10 + 6];
            unsigned long long a4 = *(const unsigned long long*)&xw[c*10 + 8];
            float2 bf = *(const float2*)&lws[(c << 6) + dd0];
            unsigned long long b0 = pk2(bf.x, bf.x);
            unsigned long long b1 = pk2(bf.y, bf.y);
            fma2(acc[0][0], a0, b0); fma2(acc[0][1], a0, b1);
            fma2(acc[1][0], a1, b0); fma2(acc[1][1], a1, b1);
            fma2(acc[2][0], a2, b0); fma2(acc[2][1], a2, b1);
            fma2(acc[3][0], a3, b0); fma2(acc[3][1], a3, b1);
            fma2(acc[4][0], a4, b0); fma2(acc[4][1], a4, b1);
        }

        float psum0 = 0.f, psum1 = 0.f, psq0 = 0.f, psq1 = 0.f;
        #pragma unroll
        for (int tp = 0; tp < 5; tp++) {
            float e0, o0, e1, o1;
            upk2(e0, o0, acc[tp][0]);
            upk2(e1, o1, acc[tp][1]);
            size_t rowe = (size_t)(n*300 + t0 + 2*tp) * 1600 + (w << 6) + dd0;
            *(float2*)&g_y0[rowe]        = make_float2(e0, e1);
            *(float2*)&g_y0[rowe + 1600] = make_float2(o0, o1);
            psum0 += e0 + o0; psq0 += e0*e0 + o0*o0;
            psum1 += e1 + o1; psq1 += e1*e1 + o1*o1;
        }
        // per-block BN partials: each thread owns features w*64+dd0, +1 exclusively
        *(float2*)&g_part3[(size_t)b*3200 + (w << 6) + dd0]        = make_float2(psum0, psum1);
        *(float2*)&g_part3[(size_t)b*3200 + 1600 + (w << 6) + dd0] = make_float2(psq0,  psq1);
    }
}

// ---------------- K8b: reduce BN partials -> per-feature stats ----------------
__global__ void k8b()
{
    __shared__ float red_s[256], red_ss[256];
    int f = blockIdx.x * 32 + (threadIdx.x & 31);
    int sl = threadIdx.x >> 5;     // 8 slices
    float s = 0.f, ss = 0.f;
    for (int b = sl; b < K7_BLOCKS; b += 8) {
        s  += g_part3[(size_t)b*3200 + f];
        ss += g_part3[(size_t)b*3200 + 1600 + f];
    }
    red_s[threadIdx.x] = s; red_ss[threadIdx.x] = ss;
    __syncthreads();
    if (threadIdx.x < 32) {
        float S = 0.f, SS = 0.f;
        #pragma unroll
        for (int k = 0; k < 8; k++) { S += red_s[k*32 + threadIdx.x]; SS += red_ss[k*32 + threadIdx.x]; }
        int ff = blockIdx.x * 32 + threadIdx.x;
        float cnt = (float)NTOT;
        float m = S/cnt, v = SS/cnt - m*m;
        g_stats3[ff*2 + 0] = m;
        g_stats3[ff*2 + 1] = rsqrtf(v + EPSB);
    }
}

// ---------------- K9: shift + BN + residual + relu (small tiles, float4 loads) ----------------
#define K9_TT 5
#define K9_PITCH 1632
__global__ void k9(const float* __restrict__ x0, const float* __restrict__ gbn,
                   const float* __restrict__ bbn, float* __restrict__ out)
{
    extern __shared__ float sm9[];
    float* ysm   = sm9;                       // 5 * 1632 = 8160
    float* gbn_s = sm9 + K9_TT*K9_PITCH;      // 1600
    float* bbn_s = gbn_s + 1600;              // 1600

    int b = blockIdx.x;
    int n = b / (TB/K9_TT), t0 = (b % (TB/K9_TT)) * K9_TT;
    int tid = threadIdx.x;

    for (int i = tid; i < 400; i += blockDim.x) {
        ((float4*)gbn_s)[i] = ((const float4*)gbn)[i];
        ((float4*)bbn_s)[i] = ((const float4*)bbn)[i];
    }

    // phase 1: float4 y0 row reads, normalize with src stats, scatter by inverse shift
    #pragma unroll
    for (int t = 0; t < K9_TT; t++) {
        const float4* row4 = (const float4*)&g_y0[(size_t)(n*300 + t0 + t) * 1600];
        for (int p4 = tid; p4 < 400; p4 += blockDim.x) {
            float4 v4 = row4[p4];
            int p = p4 << 2;
            float vv[4] = {v4.x, v4.y, v4.z, v4.w};
            #pragma unroll
            for (int e = 0; e < 4; e++) {
                float2 st = *(const float2*)&g_stats3[(p + e)*2];
                float v = (vv[e] - st.x) * st.y;
                int w = (p + e) >> 6, dd = (p + e) & 63;
                int i = (w + dd) % 25;
                ysm[t*K9_PITCH + i*65 + dd] = v;
            }
        }
    }
    __syncthreads();

    // phase 2: fully coalesced output in (n, dd, t, i) layout + residual relu
    for (int idx = tid; idx < 64 * K9_TT * 25; idx += blockDim.x) {
        int dd = idx / (K9_TT*25), r = idx % (K9_TT*25);
        int t = r / 25, i = r % 25;
        int f = i*64 + dd;
        float v = fmaf(gbn_s[f], ysm[t*K9_PITCH + i*65 + dd], bbn_s[f]);
        size_t go = ((size_t)(n*64 + dd) * 300 + t0) * 25 + r;
        v += x0[go];
        out[go] = fmaxf(v, 0.0f);
    }
}

// ---------------- launcher (6 launches; slot 4 = k7 for ncu capture) ----------------
extern "C" void kernel_launch(void* const* d_in, const int* in_sizes, int n_in,
                              void* d_out, int out_size)
{
    const float* x0  = (const float*)d_in[0];
    const float* Wv  = (const float*)d_in[3];
    const float* bv  = (const float*)d_in[4];
    const float* gv  = (const float*)d_in[5];
    const float* bev = (const float*)d_in[6];
    const float* Wt  = (const float*)d_in[7];
    const float* bt  = (const float*)d_in[8];
    const float* gt  = (const float*)d_in[9];
    const float* bet = (const float*)d_in[10];
    const float* Ws  = (const float*)d_in[11];
    const float* bs  = (const float*)d_in[12];
    const float* gs  = (const float*)d_in[13];
    const float* bes = (const float*)d_in[14];
    const float* Wv2 = (const float*)d_in[15];
    const float* bv2 = (const float*)d_in[16];
    const float* Wt2 = (const float*)d_in[17];
    const float* bt2 = (const float*)d_in[18];
    const float* Lw  = (const float*)d_in[19];
    const float* Lb  = (const float*)d_in[20];
    const float* gbn = (const float*)d_in[21];
    const float* bbn = (const float*)d_in[22];
    float* out = (float*)d_out;

    static_assert((TB % K9_TT) == 0, "k9 t tiling");
    static_assert((TB % K7T) == 0, "k7 t tiling");
    static_assert((XMP_TOT % 4) == 0 && XMP_TOT >= VB*XMP_WS, "xmp pad");

    const int smem3 = (64*68 + 4096 + 17*64*2) * 4;                 // 51200
    const int smem7 = (XMP_TOT + 4096 + 1625 + 64) * 4;             // 87396
    const int smem9 = (K9_TT*K9_PITCH + 1600 + 1600) * 4;           // 45440
    cudaFuncSetAttribute(k3, cudaFuncAttributeMaxDynamicSharedMemorySize, smem3);
    cudaFuncSetAttribute(k7, cudaFuncAttributeMaxDynamicSharedMemorySize, smem7);
    cudaFuncSetAttribute(k9, cudaFuncAttributeMaxDynamicSharedMemorySize, smem9);

    k1 <<<NB*CB, 256>>>(x0, Wv, bv, Wt, bt);
    k3 <<<NB*5, 288, smem3>>>(gv, bev, gt, bet, Ws, bs);
    k56<<<LTOT, 256>>>(gs, bes, Wt2, bt2, Wv2, bv2, out + Y_SIZE);
    k7 <<<K7_BLOCKS, 1024, smem7>>>(x0, Lw, Lb);
    k8b<<<FEAT/32, 256>>>();
    k9 <<<NB*(TB/K9_TT), 256, smem9>>>(x0, gbn, bbn, out);
}

// round 11
// speedup vs baseline: 1.6132x; 1.1416x over previous
#include <cuda_runtime.h>
#include <math.h>

// Problem constants
#define NB 64
#define CB 64
#define DB 64
#define TB 300
#define VB 25
#define EPSB 1e-5f
#define NTOT (NB*TB)          // 19200 rows
#define FEAT (VB*DB)          // 1600 features
#define LTOT (TB+VB)          // 325
#define Y_SIZE (NB*DB*TB*VB)  // 30720000

#define K7T 10                // t-rows per k7 block
#define K7_BLOCKS (NB*(TB/K7T))   // 1920

// ---------------- scratch (device globals; no runtime allocation) ----------------
__device__ float g_xv[NB*CB*TB];        // 4.9 MB
__device__ float g_xt[NB*CB*VB];        // 0.4 MB
__device__ float g_part1[NB*CB*4];      // per-(n,c) partials (sv,svv,st,stt)
__device__ float g_xs[NB*DB*LTOT];      // 5.3 MB
__device__ float g_part2[320*DB*2];     // per-(n,kc) per-o partials
__device__ float g_scale[VB*CB];        // tanh(sigmoid(view))+1, [w][c]
__device__ float g_y0[(size_t)NTOT*FEAT];     // 123 MB
__device__ float g_part3[K7_BLOCKS*3200];     // 24.6 MB : per-block BN partials
__device__ float g_stats3[FEAT*2];      // y0 feature mean/rstd

__device__ __forceinline__ float hswish(float x) {
    float c = fminf(fmaxf(x + 3.0f, 0.0f), 6.0f);
    return x * c * (1.0f / 6.0f);
}
__device__ __forceinline__ unsigned long long pk2(float lo, float hi) {
    unsigned long long r;
    asm("mov.b64 %0, {%1, %2};" : "=l"(r) : "f"(lo), "f"(hi));
    return r;
}
__device__ __forceinline__ void upk2(float& lo, float& hi, unsigned long long v) {
    asm("mov.b64 {%0, %1}, %2;" : "=f"(lo), "=f"(hi) : "l"(v));
}
__device__ __forceinline__ void fma2(unsigned long long& d, unsigned long long a, unsigned long long b) {
    asm("fma.rn.f32x2 %0, %1, %2, %0;" : "+l"(d) : "l"(a), "l"(b));
}

// ---------------- K1: per-(n,c) slice — xv (V-reduce) + xt (T-reduce) + partials ----
__global__ void k1(const float* __restrict__ x0, const float* __restrict__ Wv,
                   const float* __restrict__ bv, const float* __restrict__ Wt,
                   const float* __restrict__ bt)
{
    __shared__ float xs_[TB*VB];
    __shared__ float wt_[TB];
    __shared__ float wvc[VB];
    __shared__ float red[64];
    __shared__ float xta[VB];

    int nc = blockIdx.x;
    int c  = nc & 63;
    int tid = threadIdx.x;

    const float4* src4 = (const float4*)(x0 + (size_t)nc * (TB*VB));
    for (int i = tid; i < 1875; i += blockDim.x) ((float4*)xs_)[i] = src4[i];
    for (int i = tid; i < TB;   i += blockDim.x) wt_[i] = Wt[i];
    if (tid < VB) {
        int v = (tid - c) % VB; if (v < 0) v += VB;
        wvc[tid] = Wv[v];
    }
    float bvv = bv[0], btv = bt[0];
    __syncthreads();

    float s = 0.f, ss = 0.f;
    for (int t = tid; t < TB; t += blockDim.x) {
        float a = bvv;
        #pragma unroll
        for (int v = 0; v < VB; v++) a += wvc[v] * xs_[t*VB + v];
        g_xv[nc*TB + t] = a;
        s += a; ss += a*a;
    }
    #pragma unroll
    for (int o = 16; o; o >>= 1) {
        s  += __shfl_down_sync(0xffffffffu, s,  o);
        ss += __shfl_down_sync(0xffffffffu, ss, o);
    }
    if ((tid & 31) == 0) { red[tid>>5] = s; red[32 + (tid>>5)] = ss; }

    if (tid < 224) {
        int vp = tid >> 3, sl = tid & 7;
        float a = 0.f;
        if (vp < VB) {
            for (int t = sl; t < TB; t += 8) a += wt_[t] * xs_[t*VB + vp];
        }
        a += __shfl_down_sync(0xffffffffu, a, 4);
        a += __shfl_down_sync(0xffffffffu, a, 2);
        a += __shfl_down_sync(0xffffffffu, a, 1);
        if (sl == 0 && vp < VB) {
            a += btv;
            int v = (vp - c) % VB; if (v < 0) v += VB;
            g_xt[nc*VB + v] = a;
            xta[vp] = a;
        }
    }
    __syncthreads();
    if (tid == 0) {
        float S = 0.f, SS = 0.f;
        for (int w = 0; w < (int)(blockDim.x >> 5); w++) { S += red[w]; SS += red[32+w]; }
        g_part1[nc*4 + 0] = S; g_part1[nc*4 + 1] = SS;
        S = 0.f; SS = 0.f;
        for (int v = 0; v < VB; v++) { S += xta[v]; SS += xta[v]*xta[v]; }
        g_part1[nc*4 + 2] = S; g_part1[nc*4 + 3] = SS;
    }
}

// ---------------- K3: inline stats1 + Ws stage (grid n x 5 chunks), 4x4 tiles ----------------
__global__ void k3(const float* __restrict__ gv, const float* __restrict__ bev,
                   const float* __restrict__ gt, const float* __restrict__ bet,
                   const float* __restrict__ Ws, const float* __restrict__ bs)
{
    extern __shared__ float sm3[];
    float* sfs    = sm3;            // [64][68]
    float* wst    = sm3 + 64*68;    // [64*64] transposed Ws
    float* red_s  = wst + 4096;     // [17][64]
    float* red_ss = red_s + 17*64;  // [17][64]
    __shared__ float rbuf[9*4];
    __shared__ float st1[4];

    int b = blockIdx.x;
    int n = b / 5, kc = b % 5;
    int tid = threadIdx.x;

    {
        float a0=0.f, a1=0.f, a2=0.f, a3=0.f;
        for (int j = tid; j < NB*CB; j += blockDim.x) {
            a0 += g_part1[j*4+0]; a1 += g_part1[j*4+1];
            a2 += g_part1[j*4+2]; a3 += g_part1[j*4+3];
        }
        #pragma unroll
        for (int o = 16; o; o >>= 1) {
            a0 += __shfl_down_sync(0xffffffffu, a0, o);
            a1 += __shfl_down_sync(0xffffffffu, a1, o);
            a2 += __shfl_down_sync(0xffffffffu, a2, o);
            a3 += __shfl_down_sync(0xffffffffu, a3, o);
        }
        if ((tid & 31) == 0) {
            int w = tid >> 5;
            rbuf[w*4+0]=a0; rbuf[w*4+1]=a1; rbuf[w*4+2]=a2; rbuf[w*4+3]=a3;
        }
        __syncthreads();
        if (tid == 0) {
            float A0=0,A1=0,A2=0,A3=0;
            for (int w = 0; w < 9; w++) { A0+=rbuf[w*4]; A1+=rbuf[w*4+1]; A2+=rbuf[w*4+2]; A3+=rbuf[w*4+3]; }
            float cntv = (float)(NB*CB*TB), cntt = (float)(NB*CB*VB);
            float mv = A0/cntv, vv = A1/cntv - mv*mv;
            float mt = A2/cntt, vt = A3/cntt - mt*mt;
            st1[0] = mv; st1[1] = rsqrtf(vv + EPSB);
            st1[2] = mt; st1[3] = rsqrtf(vt + EPSB);
        }
        __syncthreads();
    }
    float mv = st1[0], rv = st1[1], mt = st1[2], rt = st1[3];
    float gvv = gv[0], bevv = bev[0], gtv = gt[0], betv = bet[0];

    for (int i = tid; i < 64*68; i += blockDim.x) {
        int cc = i / 68, ll = i % 68;
        float val = 0.f;
        if (ll < 65) {
            int p = cc*LTOT + kc*65 + ll;
            if (p < 1600) {
                int cs = p / 25, v = p % 25;
                float x = g_xt[(n*64 + cs)*25 + v];
                val = hswish(gtv * (x - mt) * rt + betv);
            } else {
                int q = p - 1600;
                int cs = q / 300, t = q % 300;
                float x = g_xv[(n*64 + cs)*300 + t];
                val = hswish(gvv * (x - mv) * rv + bevv);
            }
        }
        sfs[i] = val;
    }
    for (int i = tid; i < 4096; i += blockDim.x) {
        int o = i & 63, cc = i >> 6;
        wst[i] = Ws[o*64 + cc];
    }
    __syncthreads();

    if (tid < 272) {
        int og = tid & 15, kg = tid >> 4;
        int o0 = og * 4, kl0 = kg * 4;
        float acc[4][4];
        #pragma unroll
        for (int j = 0; j < 4; j++) {
            float bb = bs[o0 + j];
            #pragma unroll
            for (int i = 0; i < 4; i++) acc[j][i] = bb;
        }
        for (int cc = 0; cc < 64; cc++) {
            float4 a = *(const float4*)&wst[cc*64 + o0];
            float4 bq = *(const float4*)&sfs[cc*68 + kl0];
            acc[0][0] += a.x*bq.x; acc[0][1] += a.x*bq.y; acc[0][2] += a.x*bq.z; acc[0][3] += a.x*bq.w;
            acc[1][0] += a.y*bq.x; acc[1][1] += a.y*bq.y; acc[1][2] += a.y*bq.z; acc[1][3] += a.y*bq.w;
            acc[2][0] += a.z*bq.x; acc[2][1] += a.z*bq.y; acc[2][2] += a.z*bq.z; acc[2][3] += a.z*bq.w;
            acc[3][0] += a.w*bq.x; acc[3][1] += a.w*bq.y; acc[3][2] += a.w*bq.z; acc[3][3] += a.w*bq.w;
        }
        #pragma unroll
        for (int j = 0; j < 4; j++) {
            float s = 0.f, ssum = 0.f;
            #pragma unroll
            for (int i = 0; i < 4; i++) {
                int kl = kl0 + i;
                if (kl < 65) {
                    float v = acc[j][i];
                    g_xs[(n*64 + o0 + j)*LTOT + kc*65 + kl] = v;
                    s += v; ssum += v*v;
                }
            }
            red_s [kg*64 + o0 + j] = s;
            red_ss[kg*64 + o0 + j] = ssum;
        }
    }
    __syncthreads();
    if (tid < 64) {
        float S = 0.f, SS = 0.f;
        for (int kg = 0; kg < 17; kg++) { S += red_s[kg*64 + tid]; SS += red_ss[kg*64 + tid]; }
        g_part2[(b*64 + tid)*2 + 0] = S;
        g_part2[(b*64 + tid)*2 + 1] = SS;
    }
}

// ---------------- K56: fused stats2 + xbar column + squeeze outputs (block per l) ----
__global__ void k56(const float* __restrict__ gs, const float* __restrict__ bes,
                    const float* __restrict__ Wt2, const float* __restrict__ bt2,
                    const float* __restrict__ Wv2, const float* __restrict__ bv2,
                    float* __restrict__ out_xtime)
{
    __shared__ float w2t[4096];
    __shared__ float red_a[256], red_b[256];
    __shared__ float stats2_s[128];
    __shared__ float xbar_s[64];

    int l = blockIdx.x;
    int tid = threadIdx.x;

    const float* W2 = (l < TB) ? Wt2 : Wv2;
    for (int i = tid; i < 4096; i += blockDim.x) {
        int o = i >> 6, d = i & 63;
        w2t[d*64 + o] = W2[i];
    }

    {
        int o = tid & 63, sl = tid >> 6;
        float s = 0.f, ss = 0.f;
        for (int ch = sl; ch < 320; ch += 4) {
            s  += g_part2[(ch*64 + o)*2 + 0];
            ss += g_part2[(ch*64 + o)*2 + 1];
        }
        red_a[tid] = s; red_b[tid] = ss;
        __syncthreads();
        if (tid < 64) {
            float S  = red_a[tid] + red_a[64+tid] + red_a[128+tid] + red_a[192+tid];
            float SS = red_b[tid] + red_b[64+tid] + red_b[128+tid] + red_b[192+tid];
            float cnt = 64.f * (float)LTOT;
            float m = S/cnt, v = SS/cnt - m*m;
            stats2_s[tid*2 + 0] = m;
            stats2_s[tid*2 + 1] = rsqrtf(v + EPSB);
        }
        __syncthreads();
    }

    {
        int d = tid & 63, ns = tid >> 6;
        float m = stats2_s[d*2], r = stats2_s[d*2+1];
        float g = gs[d], bb = bes[d];
        float acc = 0.f;
        for (int n = ns; n < 64; n += 4)
            acc += hswish(g * (g_xs[(n*64 + d)*LTOT + l] - m) * r + bb);
        red_a[tid] = acc;
        __syncthreads();
        if (tid < 64)
            xbar_s[tid] = (red_a[tid] + red_a[64+tid] + red_a[128+tid] + red_a[192+tid]) * (1.0f/64.0f);
        __syncthreads();
    }

    if (tid < 64) {
        int o = tid;
        float acc = (l < TB) ? bt2[o] : bv2[o];
        #pragma unroll 8
        for (int d = 0; d < 64; d++) acc += w2t[d*64 + o] * xbar_s[d];
        float sg = 1.0f / (1.0f + expf(-acc));
        if (l < TB) out_xtime[o*TB + l] = sg;
        else        g_scale[(l - TB)*64 + o] = tanhf(sg) + 1.0f;
    }
}

// ---------------- K7: GEMM + inline BN partials ----------------
// 1024 threads; warp w (0..24), lane = ddg; 10t x 2dd per thread via FFMA2.
// xmp[w][c][t]: per-c stride 12 floats (16B-aligned) -> a-loads are 2x LDS.128 + 1x LDS.64
// that land directly in packed (t,t+1) register pairs — no packing MOVs.
#define XMP_CS 12
#define XMP_WS 772      // 64*12 + 4 pad; 772%32=4 spreads build-phase STS banks; *4B %16 == 0
#define XMP_TOT (VB*XMP_WS)   // 19300 floats; *4B = 77200, %16 == 0 -> lws aligned
__global__ void __launch_bounds__(1024, 1)
k7(const float* __restrict__ x0, const float* __restrict__ Lw,
   const float* __restrict__ Lb)
{
    extern __shared__ float sm7[];
    float* xmp = sm7;                 // 19300
    float* lws = sm7 + XMP_TOT;       // 4096, 16B-aligned
    float* ssc = lws + 4096;          // 25*65
    float* lbs = ssc + 1625;          // 64

    int b = blockIdx.x;
    int n = b / (TB/K7T);
    int t0 = (b % (TB/K7T)) * K7T;
    int tid = threadIdx.x;

    for (int i = tid; i < 4096; i += 1024) lws[i] = Lw[i];
    for (int i = tid; i < VB*CB; i += 1024) {
        int w = i >> 6, c = i & 63;
        ssc[w*65 + c] = g_scale[i];
    }
    if (tid < 64) lbs[tid] = Lb[tid];
    __syncthreads();

    // build: loop (c,v) pairs; one div by 25 per pair; strength-reduced t-loop (MLP 10)
    const float* xbase = x0 + ((size_t)(n*64) * 300 + t0) * 25;
    for (int pr = tid; pr < CB*VB; pr += 1024) {
        int c = pr / 25;
        int v = pr - c*25;
        int w = v - (c % 25); if (w < 0) w += 25;
        float sc = ssc[w*65 + c];
        const float* src = xbase + (size_t)c * 7500 + v;
        float* dst = xmp + w*XMP_WS + c*XMP_CS;
        #pragma unroll
        for (int t = 0; t < K7T; t++)
            dst[t] = src[t*25] * sc;
    }
    __syncthreads();

    int w   = tid >> 5;     // warp index == w
    int ddg = tid & 31;
    if (w < 25) {
        int dd0 = ddg << 1;
        const unsigned long long* xq = (const unsigned long long*)(xmp + w*XMP_WS);

        unsigned long long acc[5][2];
        {
            unsigned long long i0 = pk2(lbs[dd0],     lbs[dd0]);
            unsigned long long i1 = pk2(lbs[dd0 + 1], lbs[dd0 + 1]);
            #pragma unroll
            for (int tp = 0; tp < 5; tp++) { acc[tp][0] = i0; acc[tp][1] = i1; }
        }

        #pragma unroll 4
        for (int c = 0; c < 64; c++) {
            // a: 10 floats as packed (t,t+1) pairs straight from shared
            ulonglong2 A01 = *(const ulonglong2*)(xq + c*6);      // (t0,t1),(t2,t3)
            ulonglong2 A23 = *(const ulonglong2*)(xq + c*6 + 2);  // (t4,t5),(t6,t7)
            unsigned long long A4 = xq[c*6 + 4];                  // (t8,t9)
            float2 bf = *(const float2*)&lws[(c << 6) + dd0];
            unsigned long long b0 = pk2(bf.x, bf.x);
            unsigned long long b1 = pk2(bf.y, bf.y);
            fma2(acc[0][0], A01.x, b0); fma2(acc[0][1], A01.x, b1);
            fma2(acc[1][0], A01.y, b0); fma2(acc[1][1], A01.y, b1);
            fma2(acc[2][0], A23.x, b0); fma2(acc[2][1], A23.x, b1);
            fma2(acc[3][0], A23.y, b0); fma2(acc[3][1], A23.y, b1);
            fma2(acc[4][0], A4,    b0); fma2(acc[4][1], A4,    b1);
        }

        float psum0 = 0.f, psum1 = 0.f, psq0 = 0.f, psq1 = 0.f;
        #pragma unroll
        for (int tp = 0; tp < 5; tp++) {
            float e0, o0, e1, o1;
            upk2(e0, o0, acc[tp][0]);
            upk2(e1, o1, acc[tp][1]);
            size_t rowe = (size_t)(n*300 + t0 + 2*tp) * 1600 + (w << 6) + dd0;
            *(float2*)&g_y0[rowe]        = make_float2(e0, e1);
            *(float2*)&g_y0[rowe + 1600] = make_float2(o0, o1);
            psum0 += e0 + o0; psq0 += e0*e0 + o0*o0;
            psum1 += e1 + o1; psq1 += e1*e1 + o1*o1;
        }
        *(float2*)&g_part3[(size_t)b*3200 + (w << 6) + dd0]        = make_float2(psum0, psum1);
        *(float2*)&g_part3[(size_t)b*3200 + 1600 + (w << 6) + dd0] = make_float2(psq0,  psq1);
    }
}

// ---------------- K8b: reduce BN partials -> per-feature stats ----------------
__global__ void k8b()
{
    __shared__ float red_s[256], red_ss[256];
    int f = blockIdx.x * 32 + (threadIdx.x & 31);
    int sl = threadIdx.x >> 5;
    float s = 0.f, ss = 0.f;
    for (int b = sl; b < K7_BLOCKS; b += 8) {
        s  += g_part3[(size_t)b*3200 + f];
        ss += g_part3[(size_t)b*3200 + 1600 + f];
    }
    red_s[threadIdx.x] = s; red_ss[threadIdx.x] = ss;
    __syncthreads();
    if (threadIdx.x < 32) {
        float S = 0.f, SS = 0.f;
        #pragma unroll
        for (int k = 0; k < 8; k++) { S += red_s[k*32 + threadIdx.x]; SS += red_ss[k*32 + threadIdx.x]; }
        int ff = blockIdx.x * 32 + threadIdx.x;
        float cnt = (float)NTOT;
        float m = S/cnt, v = SS/cnt - m*m;
        g_stats3[ff*2 + 0] = m;
        g_stats3[ff*2 + 1] = rsqrtf(v + EPSB);
    }
}

// ---------------- K9: shift + BN + residual + relu (small tiles, float4 loads) ----------------
#define K9_TT 5
#define K9_PITCH 1632
__global__ void k9(const float* __restrict__ x0, const float* __restrict__ gbn,
                   const float* __restrict__ bbn, float* __restrict__ out)
{
    extern __shared__ float sm9[];
    float* ysm   = sm9;                       // 5 * 1632
    float* gbn_s = sm9 + K9_TT*K9_PITCH;
    float* bbn_s = gbn_s + 1600;

    int b = blockIdx.x;
    int n = b / (TB/K9_TT), t0 = (b % (TB/K9_TT)) * K9_TT;
    int tid = threadIdx.x;

    for (int i = tid; i < 400; i += blockDim.x) {
        ((float4*)gbn_s)[i] = ((const float4*)gbn)[i];
        ((float4*)bbn_s)[i] = ((const float4*)bbn)[i];
    }

    #pragma unroll
    for (int t = 0; t < K9_TT; t++) {
        const float4* row4 = (const float4*)&g_y0[(size_t)(n*300 + t0 + t) * 1600];
        for (int p4 = tid; p4 < 400; p4 += blockDim.x) {
            float4 v4 = row4[p4];
            int p = p4 << 2;
            float vv[4] = {v4.x, v4.y, v4.z, v4.w};
            #pragma unroll
            for (int e = 0; e < 4; e++) {
                float2 st = *(const float2*)&g_stats3[(p + e)*2];
                float v = (vv[e] - st.x) * st.y;
                int w = (p + e) >> 6, dd = (p + e) & 63;
                int i = (w + dd) % 25;
                ysm[t*K9_PITCH + i*65 + dd] = v;
            }
        }
    }
    __syncthreads();

    for (int idx = tid; idx < 64 * K9_TT * 25; idx += blockDim.x) {
        int dd = idx / (K9_TT*25), r = idx % (K9_TT*25);
        int t = r / 25, i = r % 25;
        int f = i*64 + dd;
        float v = fmaf(gbn_s[f], ysm[t*K9_PITCH + i*65 + dd], bbn_s[f]);
        size_t go = ((size_t)(n*64 + dd) * 300 + t0) * 25 + r;
        v += x0[go];
        out[go] = fmaxf(v, 0.0f);
    }
}

// ---------------- launcher (6 launches; slot 4 = k7 for ncu capture) ----------------
extern "C" void kernel_launch(void* const* d_in, const int* in_sizes, int n_in,
                              void* d_out, int out_size)
{
    const float* x0  = (const float*)d_in[0];
    const float* Wv  = (const float*)d_in[3];
    const float* bv  = (const float*)d_in[4];
    const float* gv  = (const float*)d_in[5];
    const float* bev = (const float*)d_in[6];
    const float* Wt  = (const float*)d_in[7];
    const float* bt  = (const float*)d_in[8];
    const float* gt  = (const float*)d_in[9];
    const float* bet = (const float*)d_in[10];
    const float* Ws  = (const float*)d_in[11];
    const float* bs  = (const float*)d_in[12];
    const float* gs  = (const float*)d_in[13];
    const float* bes = (const float*)d_in[14];
    const float* Wv2 = (const float*)d_in[15];
    const float* bv2 = (const float*)d_in[16];
    const float* Wt2 = (const float*)d_in[17];
    const float* bt2 = (const float*)d_in[18];
    const float* Lw  = (const float*)d_in[19];
    const float* Lb  = (const float*)d_in[20];
    const float* gbn = (const float*)d_in[21];
    const float* bbn = (const float*)d_in[22];
    float* out = (float*)d_out;

    static_assert((TB % K9_TT) == 0, "k9 t tiling");
    static_assert((TB % K7T) == 0, "k7 t tiling");
    static_assert((XMP_TOT % 4) == 0, "xmp align");
    static_assert(XMP_CS * CB < XMP_WS, "xmp pad");

    const int smem3 = (64*68 + 4096 + 17*64*2) * 4;                 // 51200
    const int smem7 = (XMP_TOT + 4096 + 1625 + 64) * 4;             // 100340
    const int smem9 = (K9_TT*K9_PITCH + 1600 + 1600) * 4;           // 45440
    cudaFuncSetAttribute(k3, cudaFuncAttributeMaxDynamicSharedMemorySize, smem3);
    cudaFuncSetAttribute(k7, cudaFuncAttributeMaxDynamicSharedMemorySize, smem7);
    cudaFuncSetAttribute(k9, cudaFuncAttributeMaxDynamicSharedMemorySize, smem9);

    k1 <<<NB*CB, 256>>>(x0, Wv, bv, Wt, bt);
    k3 <<<NB*5, 288, smem3>>>(gv, bev, gt, bet, Ws, bs);
    k56<<<LTOT, 256>>>(gs, bes, Wt2, bt2, Wv2, bv2, out + Y_SIZE);
    k7 <<<K7_BLOCKS, 1024, smem7>>>(x0, Lw, Lb);
    k8b<<<FEAT/32, 256>>>();
    k9 <<<NB*(TB/K9_TT), 256, smem9>>>(x0, gbn, bbn, out);
}

// round 12
// speedup vs baseline: 1.6291x; 1.0099x over previous
#include <cuda_runtime.h>
#include <math.h>

// Problem constants
#define NB 64
#define CB 64
#define DB 64
#define TB 300
#define VB 25
#define EPSB 1e-5f
#define NTOT (NB*TB)          // 19200 rows
#define FEAT (VB*DB)          // 1600 features
#define LTOT (TB+VB)          // 325
#define Y_SIZE (NB*DB*TB*VB)  // 30720000

#define K7T 10                // t-rows per k7 block
#define K7_BLOCKS (NB*(TB/K7T))   // 1920

// ---------------- scratch (device globals; no runtime allocation) ----------------
__device__ float g_xv[NB*CB*TB];        // 4.9 MB
__device__ float g_xt[NB*CB*VB];        // 0.4 MB
__device__ float g_part1[NB*CB*4];      // per-(n,c) partials (sv,svv,st,stt)
__device__ float g_xs[NB*DB*LTOT];      // 5.3 MB
__device__ float g_part2[320*DB*2];     // per-(n,kc) per-o partials
__device__ float g_scale[VB*CB];        // tanh(sigmoid(view))+1, [w][c]
__device__ float g_y0[(size_t)NTOT*FEAT];     // 123 MB
__device__ float g_part3[K7_BLOCKS*3200];     // 24.6 MB : per-block BN partials
__device__ float g_stats3[FEAT*2];      // y0 feature mean/rstd

__device__ __forceinline__ float hswish(float x) {
    float c = fminf(fmaxf(x + 3.0f, 0.0f), 6.0f);
    return x * c * (1.0f / 6.0f);
}
__device__ __forceinline__ unsigned long long pk2(float lo, float hi) {
    unsigned long long r;
    asm("mov.b64 %0, {%1, %2};" : "=l"(r) : "f"(lo), "f"(hi));
    return r;
}
__device__ __forceinline__ void upk2(float& lo, float& hi, unsigned long long v) {
    asm("mov.b64 {%0, %1}, %2;" : "=f"(lo), "=f"(hi) : "l"(v));
}
__device__ __forceinline__ void fma2(unsigned long long& d, unsigned long long a, unsigned long long b) {
    asm("fma.rn.f32x2 %0, %1, %2, %0;" : "+l"(d) : "l"(a), "l"(b));
}

// ---------------- K1: per-(n,c) slice — xv (V-reduce) + xt (T-reduce) + partials ----
__global__ void k1(const float* __restrict__ x0, const float* __restrict__ Wv,
                   const float* __restrict__ bv, const float* __restrict__ Wt,
                   const float* __restrict__ bt)
{
    __shared__ float xs_[TB*VB];
    __shared__ float wt_[TB];
    __shared__ float wvc[VB];
    __shared__ float red[64];
    __shared__ float xta[VB];

    int nc = blockIdx.x;
    int c  = nc & 63;
    int tid = threadIdx.x;

    const float4* src4 = (const float4*)(x0 + (size_t)nc * (TB*VB));
    for (int i = tid; i < 1875; i += blockDim.x) ((float4*)xs_)[i] = src4[i];
    for (int i = tid; i < TB;   i += blockDim.x) wt_[i] = Wt[i];
    if (tid < VB) {
        int v = (tid - c) % VB; if (v < 0) v += VB;
        wvc[tid] = Wv[v];
    }
    float bvv = bv[0], btv = bt[0];
    __syncthreads();

    float s = 0.f, ss = 0.f;
    for (int t = tid; t < TB; t += blockDim.x) {
        float a = bvv;
        #pragma unroll
        for (int v = 0; v < VB; v++) a += wvc[v] * xs_[t*VB + v];
        g_xv[nc*TB + t] = a;
        s += a; ss += a*a;
    }
    #pragma unroll
    for (int o = 16; o; o >>= 1) {
        s  += __shfl_down_sync(0xffffffffu, s,  o);
        ss += __shfl_down_sync(0xffffffffu, ss, o);
    }
    if ((tid & 31) == 0) { red[tid>>5] = s; red[32 + (tid>>5)] = ss; }

    if (tid < 224) {
        int vp = tid >> 3, sl = tid & 7;
        float a = 0.f;
        if (vp < VB) {
            for (int t = sl; t < TB; t += 8) a += wt_[t] * xs_[t*VB + vp];
        }
        a += __shfl_down_sync(0xffffffffu, a, 4);
        a += __shfl_down_sync(0xffffffffu, a, 2);
        a += __shfl_down_sync(0xffffffffu, a, 1);
        if (sl == 0 && vp < VB) {
            a += btv;
            int v = (vp - c) % VB; if (v < 0) v += VB;
            g_xt[nc*VB + v] = a;
            xta[vp] = a;
        }
    }
    __syncthreads();
    if (tid == 0) {
        float S = 0.f, SS = 0.f;
        for (int w = 0; w < (int)(blockDim.x >> 5); w++) { S += red[w]; SS += red[32+w]; }
        g_part1[nc*4 + 0] = S; g_part1[nc*4 + 1] = SS;
        S = 0.f; SS = 0.f;
        for (int v = 0; v < VB; v++) { S += xta[v]; SS += xta[v]*xta[v]; }
        g_part1[nc*4 + 2] = S; g_part1[nc*4 + 3] = SS;
    }
}

// ---------------- K3: inline stats1 + Ws stage (grid n x 5 chunks), 4x4 tiles ----------------
__global__ void k3(const float* __restrict__ gv, const float* __restrict__ bev,
                   const float* __restrict__ gt, const float* __restrict__ bet,
                   const float* __restrict__ Ws, const float* __restrict__ bs)
{
    extern __shared__ float sm3[];
    float* sfs    = sm3;            // [64][68]
    float* wst    = sm3 + 64*68;    // [64*64] transposed Ws
    float* red_s  = wst + 4096;     // [17][64]
    float* red_ss = red_s + 17*64;  // [17][64]
    __shared__ float rbuf[9*4];
    __shared__ float st1[4];

    int b = blockIdx.x;
    int n = b / 5, kc = b % 5;
    int tid = threadIdx.x;

    {
        float a0=0.f, a1=0.f, a2=0.f, a3=0.f;
        for (int j = tid; j < NB*CB; j += blockDim.x) {
            a0 += g_part1[j*4+0]; a1 += g_part1[j*4+1];
            a2 += g_part1[j*4+2]; a3 += g_part1[j*4+3];
        }
        #pragma unroll
        for (int o = 16; o; o >>= 1) {
            a0 += __shfl_down_sync(0xffffffffu, a0, o);
            a1 += __shfl_down_sync(0xffffffffu, a1, o);
            a2 += __shfl_down_sync(0xffffffffu, a2, o);
            a3 += __shfl_down_sync(0xffffffffu, a3, o);
        }
        if ((tid & 31) == 0) {
            int w = tid >> 5;
            rbuf[w*4+0]=a0; rbuf[w*4+1]=a1; rbuf[w*4+2]=a2; rbuf[w*4+3]=a3;
        }
        __syncthreads();
        if (tid == 0) {
            float A0=0,A1=0,A2=0,A3=0;
            for (int w = 0; w < 9; w++) { A0+=rbuf[w*4]; A1+=rbuf[w*4+1]; A2+=rbuf[w*4+2]; A3+=rbuf[w*4+3]; }
            float cntv = (float)(NB*CB*TB), cntt = (float)(NB*CB*VB);
            float mv = A0/cntv, vv = A1/cntv - mv*mv;
            float mt = A2/cntt, vt = A3/cntt - mt*mt;
            st1[0] = mv; st1[1] = rsqrtf(vv + EPSB);
            st1[2] = mt; st1[3] = rsqrtf(vt + EPSB);
        }
        __syncthreads();
    }
    float mv = st1[0], rv = st1[1], mt = st1[2], rt = st1[3];
    float gvv = gv[0], bevv = bev[0], gtv = gt[0], betv = bet[0];

    for (int i = tid; i < 64*68; i += blockDim.x) {
        int cc = i / 68, ll = i % 68;
        float val = 0.f;
        if (ll < 65) {
            int p = cc*LTOT + kc*65 + ll;
            if (p < 1600) {
                int cs = p / 25, v = p % 25;
                float x = g_xt[(n*64 + cs)*25 + v];
                val = hswish(gtv * (x - mt) * rt + betv);
            } else {
                int q = p - 1600;
                int cs = q / 300, t = q % 300;
                float x = g_xv[(n*64 + cs)*300 + t];
                val = hswish(gvv * (x - mv) * rv + bevv);
            }
        }
        sfs[i] = val;
    }
    for (int i = tid; i < 4096; i += blockDim.x) {
        int o = i & 63, cc = i >> 6;
        wst[i] = Ws[o*64 + cc];
    }
    __syncthreads();

    if (tid < 272) {
        int og = tid & 15, kg = tid >> 4;
        int o0 = og * 4, kl0 = kg * 4;
        float acc[4][4];
        #pragma unroll
        for (int j = 0; j < 4; j++) {
            float bb = bs[o0 + j];
            #pragma unroll
            for (int i = 0; i < 4; i++) acc[j][i] = bb;
        }
        for (int cc = 0; cc < 64; cc++) {
            float4 a = *(const float4*)&wst[cc*64 + o0];
            float4 bq = *(const float4*)&sfs[cc*68 + kl0];
            acc[0][0] += a.x*bq.x; acc[0][1] += a.x*bq.y; acc[0][2] += a.x*bq.z; acc[0][3] += a.x*bq.w;
            acc[1][0] += a.y*bq.x; acc[1][1] += a.y*bq.y; acc[1][2] += a.y*bq.z; acc[1][3] += a.y*bq.w;
            acc[2][0] += a.z*bq.x; acc[2][1] += a.z*bq.y; acc[2][2] += a.z*bq.z; acc[2][3] += a.z*bq.w;
            acc[3][0] += a.w*bq.x; acc[3][1] += a.w*bq.y; acc[3][2] += a.w*bq.z; acc[3][3] += a.w*bq.w;
        }
        #pragma unroll
        for (int j = 0; j < 4; j++) {
            float s = 0.f, ssum = 0.f;
            #pragma unroll
            for (int i = 0; i < 4; i++) {
                int kl = kl0 + i;
                if (kl < 65) {
                    float v = acc[j][i];
                    g_xs[(n*64 + o0 + j)*LTOT + kc*65 + kl] = v;
                    s += v; ssum += v*v;
                }
            }
            red_s [kg*64 + o0 + j] = s;
            red_ss[kg*64 + o0 + j] = ssum;
        }
    }
    __syncthreads();
    if (tid < 64) {
        float S = 0.f, SS = 0.f;
        for (int kg = 0; kg < 17; kg++) { S += red_s[kg*64 + tid]; SS += red_ss[kg*64 + tid]; }
        g_part2[(b*64 + tid)*2 + 0] = S;
        g_part2[(b*64 + tid)*2 + 1] = SS;
    }
}

// ---------------- K56: fused stats2 + xbar column + squeeze outputs (block per l) ----
__global__ void k56(const float* __restrict__ gs, const float* __restrict__ bes,
                    const float* __restrict__ Wt2, const float* __restrict__ bt2,
                    const float* __restrict__ Wv2, const float* __restrict__ bv2,
                    float* __restrict__ out_xtime)
{
    __shared__ float w2t[4096];
    __shared__ float red_a[256], red_b[256];
    __shared__ float stats2_s[128];
    __shared__ float xbar_s[64];

    int l = blockIdx.x;
    int tid = threadIdx.x;

    const float* W2 = (l < TB) ? Wt2 : Wv2;
    for (int i = tid; i < 4096; i += blockDim.x) {
        int o = i >> 6, d = i & 63;
        w2t[d*64 + o] = W2[i];
    }

    {
        int o = tid & 63, sl = tid >> 6;
        float s = 0.f, ss = 0.f;
        for (int ch = sl; ch < 320; ch += 4) {
            s  += g_part2[(ch*64 + o)*2 + 0];
            ss += g_part2[(ch*64 + o)*2 + 1];
        }
        red_a[tid] = s; red_b[tid] = ss;
        __syncthreads();
        if (tid < 64) {
            float S  = red_a[tid] + red_a[64+tid] + red_a[128+tid] + red_a[192+tid];
            float SS = red_b[tid] + red_b[64+tid] + red_b[128+tid] + red_b[192+tid];
            float cnt = 64.f * (float)LTOT;
            float m = S/cnt, v = SS/cnt - m*m;
            stats2_s[tid*2 + 0] = m;
            stats2_s[tid*2 + 1] = rsqrtf(v + EPSB);
        }
        __syncthreads();
    }

    {
        int d = tid & 63, ns = tid >> 6;
        float m = stats2_s[d*2], r = stats2_s[d*2+1];
        float g = gs[d], bb = bes[d];
        float acc = 0.f;
        for (int n = ns; n < 64; n += 4)
            acc += hswish(g * (g_xs[(n*64 + d)*LTOT + l] - m) * r + bb);
        red_a[tid] = acc;
        __syncthreads();
        if (tid < 64)
            xbar_s[tid] = (red_a[tid] + red_a[64+tid] + red_a[128+tid] + red_a[192+tid]) * (1.0f/64.0f);
        __syncthreads();
    }

    if (tid < 64) {
        int o = tid;
        float acc = (l < TB) ? bt2[o] : bv2[o];
        #pragma unroll 8
        for (int d = 0; d < 64; d++) acc += w2t[d*64 + o] * xbar_s[d];
        float sg = 1.0f / (1.0f + expf(-acc));
        if (l < TB) out_xtime[o*TB + l] = sg;
        else        g_scale[(l - TB)*64 + o] = tanhf(sg) + 1.0f;
    }
}

// ---------------- K7: GEMM + inline BN partials ----------------
// 1024 threads; warp w (0..24), lane = ddg; 10t x 2dd per thread via FFMA2.
// xmp[w][c][t]: per-c stride 12 floats (16B-aligned) -> a-loads are 2x LDS.128 + 1x LDS.64
// that land directly in packed (t,t+1) register pairs — no packing MOVs.
#define XMP_CS 12
#define XMP_WS 772      // 64*12 + 4 pad; 772%32=4 spreads build-phase STS banks; *4B %16 == 0
#define XMP_TOT (VB*XMP_WS)   // 19300 floats; *4B = 77200, %16 == 0 -> lws aligned
__global__ void __launch_bounds__(1024, 1)
k7(const float* __restrict__ x0, const float* __restrict__ Lw,
   const float* __restrict__ Lb)
{
    extern __shared__ float sm7[];
    float* xmp = sm7;                 // 19300
    float* lws = sm7 + XMP_TOT;       // 4096, 16B-aligned
    float* ssc = lws + 4096;          // 25*65
    float* lbs = ssc + 1625;          // 64

    int b = blockIdx.x;
    int n = b / (TB/K7T);
    int t0 = (b % (TB/K7T)) * K7T;
    int tid = threadIdx.x;

    for (int i = tid; i < 4096; i += 1024) lws[i] = Lw[i];
    for (int i = tid; i < VB*CB; i += 1024) {
        int w = i >> 6, c = i & 63;
        ssc[w*65 + c] = g_scale[i];
    }
    if (tid < 64) lbs[tid] = Lb[tid];
    __syncthreads();

    // build: loop (c,v) pairs; one div by 25 per pair; strength-reduced t-loop (MLP 10)
    const float* xbase = x0 + ((size_t)(n*64) * 300 + t0) * 25;
    for (int pr = tid; pr < CB*VB; pr += 1024) {
        int c = pr / 25;
        int v = pr - c*25;
        int w = v - (c % 25); if (w < 0) w += 25;
        float sc = ssc[w*65 + c];
        const float* src = xbase + (size_t)c * 7500 + v;
        float* dst = xmp + w*XMP_WS + c*XMP_CS;
        #pragma unroll
        for (int t = 0; t < K7T; t++)
            dst[t] = src[t*25] * sc;
    }
    __syncthreads();

    int w   = tid >> 5;     // warp index == w
    int ddg = tid & 31;
    if (w < 25) {
        int dd0 = ddg << 1;
        const unsigned long long* xq = (const unsigned long long*)(xmp + w*XMP_WS);

        unsigned long long acc[5][2];
        {
            unsigned long long i0 = pk2(lbs[dd0],     lbs[dd0]);
            unsigned long long i1 = pk2(lbs[dd0 + 1], lbs[dd0 + 1]);
            #pragma unroll
            for (int tp = 0; tp < 5; tp++) { acc[tp][0] = i0; acc[tp][1] = i1; }
        }

        #pragma unroll 4
        for (int c = 0; c < 64; c++) {
            // a: 10 floats as packed (t,t+1) pairs straight from shared
            ulonglong2 A01 = *(const ulonglong2*)(xq + c*6);      // (t0,t1),(t2,t3)
            ulonglong2 A23 = *(const ulonglong2*)(xq + c*6 + 2);  // (t4,t5),(t6,t7)
            unsigned long long A4 = xq[c*6 + 4];                  // (t8,t9)
            float2 bf = *(const float2*)&lws[(c << 6) + dd0];
            unsigned long long b0 = pk2(bf.x, bf.x);
            unsigned long long b1 = pk2(bf.y, bf.y);
            fma2(acc[0][0], A01.x, b0); fma2(acc[0][1], A01.x, b1);
            fma2(acc[1][0], A01.y, b0); fma2(acc[1][1], A01.y, b1);
            fma2(acc[2][0], A23.x, b0); fma2(acc[2][1], A23.x, b1);
            fma2(acc[3][0], A23.y, b0); fma2(acc[3][1], A23.y, b1);
            fma2(acc[4][0], A4,    b0); fma2(acc[4][1], A4,    b1);
        }

        float psum0 = 0.f, psum1 = 0.f, psq0 = 0.f, psq1 = 0.f;
        #pragma unroll
        for (int tp = 0; tp < 5; tp++) {
            float e0, o0, e1, o1;
            upk2(e0, o0, acc[tp][0]);
            upk2(e1, o1, acc[tp][1]);
            size_t rowe = (size_t)(n*300 + t0 + 2*tp) * 1600 + (w << 6) + dd0;
            *(float2*)&g_y0[rowe]        = make_float2(e0, e1);
            *(float2*)&g_y0[rowe + 1600] = make_float2(o0, o1);
            psum0 += e0 + o0; psq0 += e0*e0 + o0*o0;
            psum1 += e1 + o1; psq1 += e1*e1 + o1*o1;
        }
        *(float2*)&g_part3[(size_t)b*3200 + (w << 6) + dd0]        = make_float2(psum0, psum1);
        *(float2*)&g_part3[(size_t)b*3200 + 1600 + (w << 6) + dd0] = make_float2(psq0,  psq1);
    }
}

// ---------------- K8b: reduce BN partials -> per-feature stats ----------------
__global__ void k8b()
{
    __shared__ float red_s[256], red_ss[256];
    int f = blockIdx.x * 32 + (threadIdx.x & 31);
    int sl = threadIdx.x >> 5;
    float s = 0.f, ss = 0.f;
    for (int b = sl; b < K7_BLOCKS; b += 8) {
        s  += g_part3[(size_t)b*3200 + f];
        ss += g_part3[(size_t)b*3200 + 1600 + f];
    }
    red_s[threadIdx.x] = s; red_ss[threadIdx.x] = ss;
    __syncthreads();
    if (threadIdx.x < 32) {
        float S = 0.f, SS = 0.f;
        #pragma unroll
        for (int k = 0; k < 8; k++) { S += red_s[k*32 + threadIdx.x]; SS += red_ss[k*32 + threadIdx.x]; }
        int ff = blockIdx.x * 32 + threadIdx.x;
        float cnt = (float)NTOT;
        float m = S/cnt, v = SS/cnt - m*m;
        g_stats3[ff*2 + 0] = m;
        g_stats3[ff*2 + 1] = rsqrtf(v + EPSB);
    }
}

// ---------------- K9: shift + BN + residual + relu (small tiles, float4 loads) ----------------
#define K9_TT 5
#define K9_PITCH 1632
__global__ void k9(const float* __restrict__ x0, const float* __restrict__ gbn,
                   const float* __restrict__ bbn, float* __restrict__ out)
{
    extern __shared__ float sm9[];
    float* ysm   = sm9;                       // 5 * 1632
    float* gbn_s = sm9 + K9_TT*K9_PITCH;
    float* bbn_s = gbn_s + 1600;

    int b = blockIdx.x;
    int n = b / (TB/K9_TT), t0 = (b % (TB/K9_TT)) * K9_TT;
    int tid = threadIdx.x;

    for (int i = tid; i < 400; i += blockDim.x) {
        ((float4*)gbn_s)[i] = ((const float4*)gbn)[i];
        ((float4*)bbn_s)[i] = ((const float4*)bbn)[i];
    }

    #pragma unroll
    for (int t = 0; t < K9_TT; t++) {
        const float4* row4 = (const float4*)&g_y0[(size_t)(n*300 + t0 + t) * 1600];
        for (int p4 = tid; p4 < 400; p4 += blockDim.x) {
            float4 v4 = row4[p4];
            int p = p4 << 2;
            float vv[4] = {v4.x, v4.y, v4.z, v4.w};
            #pragma unroll
            for (int e = 0; e < 4; e++) {
                float2 st = *(const float2*)&g_stats3[(p + e)*2];
                float v = (vv[e] - st.x) * st.y;
                int w = (p + e) >> 6, dd = (p + e) & 63;
                int i = (w + dd) % 25;
                ysm[t*K9_PITCH + i*65 + dd] = v;
            }
        }
    }
    __syncthreads();

    for (int idx = tid; idx < 64 * K9_TT * 25; idx += blockDim.x) {
        int dd = idx / (K9_TT*25), r = idx % (K9_TT*25);
        int t = r / 25, i = r % 25;
        int f = i*64 + dd;
        float v = fmaf(gbn_s[f], ysm[t*K9_PITCH + i*65 + dd], bbn_s[f]);
        size_t go = ((size_t)(n*64 + dd) * 300 + t0) * 25 + r;
        v += x0[go];
        out[go] = fmaxf(v, 0.0f);
    }
}

// ---------------- launcher (6 launches; slot 4 = k7 for ncu capture) ----------------
extern "C" void kernel_launch(void* const* d_in, const int* in_sizes, int n_in,
                              void* d_out, int out_size)
{
    const float* x0  = (const float*)d_in[0];
    const float* Wv  = (const float*)d_in[3];
    const float* bv  = (const float*)d_in[4];
    const float* gv  = (const float*)d_in[5];
    const float* bev = (const float*)d_in[6];
    const float* Wt  = (const float*)d_in[7];
    const float* bt  = (const float*)d_in[8];
    const float* gt  = (const float*)d_in[9];
    const float* bet = (const float*)d_in[10];
    const float* Ws  = (const float*)d_in[11];
    const float* bs  = (const float*)d_in[12];
    const float* gs  = (const float*)d_in[13];
    const float* bes = (const float*)d_in[14];
    const float* Wv2 = (const float*)d_in[15];
    const float* bv2 = (const float*)d_in[16];
    const float* Wt2 = (const float*)d_in[17];
    const float* bt2 = (const float*)d_in[18];
    const float* Lw  = (const float*)d_in[19];
    const float* Lb  = (const float*)d_in[20];
    const float* gbn = (const float*)d_in[21];
    const float* bbn = (const float*)d_in[22];
    float* out = (float*)d_out;

    static_assert((TB % K9_TT) == 0, "k9 t tiling");
    static_assert((TB % K7T) == 0, "k7 t tiling");
    static_assert((XMP_TOT % 4) == 0, "xmp align");
    static_assert(XMP_CS * CB < XMP_WS, "xmp pad");

    const int smem3 = (64*68 + 4096 + 17*64*2) * 4;                 // 51200
    const int smem7 = (XMP_TOT + 4096 + 1625 + 64) * 4;             // 100340
    const int smem9 = (K9_TT*K9_PITCH + 1600 + 1600) * 4;           // 45440
    cudaFuncSetAttribute(k3, cudaFuncAttributeMaxDynamicSharedMemorySize, smem3);
    cudaFuncSetAttribute(k7, cudaFuncAttributeMaxDynamicSharedMemorySize, smem7);
    cudaFuncSetAttribute(k9, cudaFuncAttributeMaxDynamicSharedMemorySize, smem9);

    k1 <<<NB*CB, 256>>>(x0, Wv, bv, Wt, bt);
    k3 <<<NB*5, 288, smem3>>>(gv, bev, gt, bet, Ws, bs);
    k56<<<LTOT, 256>>>(gs, bes, Wt2, bt2, Wv2, bv2, out + Y_SIZE);
    k7 <<<K7_BLOCKS, 1024, smem7>>>(x0, Lw, Lb);
    k8b<<<FEAT/32, 256>>>();
    k9 <<<NB*(TB/K9_TT), 256, smem9>>>(x0, gbn, bbn, out);
}

// round 13
// speedup vs baseline: 2.1500x; 1.3198x over previous
#include <cuda_runtime.h>
#include <math.h>

// Problem constants
#define NB 64
#define CB 64
#define DB 64
#define TB 300
#define VB 25
#define EPSB 1e-5f
#define NTOT (NB*TB)          // 19200 rows
#define FEAT (VB*DB)          // 1600 features
#define LTOT (TB+VB)          // 325
#define Y_SIZE (NB*DB*TB*VB)  // 30720000

#define K7T 10                // t-rows per k7 block
#define K7_BLOCKS (NB*(TB/K7T))   // 1920

// ---------------- scratch (device globals; no runtime allocation) ----------------
__device__ float g_xv[NB*CB*TB];        // 4.9 MB
__device__ float g_xt[NB*CB*VB];        // 0.4 MB
__device__ float g_part1[NB*CB*4];      // per-(n,c) partials (sv,svv,st,stt)
__device__ float g_xs[NB*DB*LTOT];      // 5.3 MB
__device__ float g_part2[320*DB*2];     // per-(n,kc) per-o partials
__device__ float g_scale[VB*CB];        // tanh(sigmoid(view))+1, [w][c]
__device__ float g_y0[(size_t)NTOT*FEAT];     // 123 MB : SHIFTED layout [n][dd][t][i]
__device__ float g_part3[K7_BLOCKS*3200];     // 24.6 MB : per-block BN partials
__device__ float g_stats3[FEAT*2];      // y0 feature mean/rstd (pre-shift feature w*64+dd)

__device__ __forceinline__ float hswish(float x) {
    float c = fminf(fmaxf(x + 3.0f, 0.0f), 6.0f);
    return x * c * (1.0f / 6.0f);
}
__device__ __forceinline__ unsigned long long pk2(float lo, float hi) {
    unsigned long long r;
    asm("mov.b64 %0, {%1, %2};" : "=l"(r) : "f"(lo), "f"(hi));
    return r;
}
__device__ __forceinline__ void upk2(float& lo, float& hi, unsigned long long v) {
    asm("mov.b64 {%0, %1}, %2;" : "=f"(lo), "=f"(hi) : "l"(v));
}
__device__ __forceinline__ void fma2(unsigned long long& d, unsigned long long a, unsigned long long b) {
    asm("fma.rn.f32x2 %0, %1, %2, %0;" : "+l"(d) : "l"(a), "l"(b));
}

// ---------------- K1: per-(n,c) slice — xv (V-reduce) + xt (T-reduce) + partials ----
__global__ void k1(const float* __restrict__ x0, const float* __restrict__ Wv,
                   const float* __restrict__ bv, const float* __restrict__ Wt,
                   const float* __restrict__ bt)
{
    __shared__ float xs_[TB*VB];
    __shared__ float wt_[TB];
    __shared__ float wvc[VB];
    __shared__ float red[64];
    __shared__ float xta[VB];

    int nc = blockIdx.x;
    int c  = nc & 63;
    int tid = threadIdx.x;

    const float4* src4 = (const float4*)(x0 + (size_t)nc * (TB*VB));
    for (int i = tid; i < 1875; i += blockDim.x) ((float4*)xs_)[i] = src4[i];
    for (int i = tid; i < TB;   i += blockDim.x) wt_[i] = Wt[i];
    if (tid < VB) {
        int v = (tid - c) % VB; if (v < 0) v += VB;
        wvc[tid] = Wv[v];
    }
    float bvv = bv[0], btv = bt[0];
    __syncthreads();

    float s = 0.f, ss = 0.f;
    for (int t = tid; t < TB; t += blockDim.x) {
        float a = bvv;
        #pragma unroll
        for (int v = 0; v < VB; v++) a += wvc[v] * xs_[t*VB + v];
        g_xv[nc*TB + t] = a;
        s += a; ss += a*a;
    }
    #pragma unroll
    for (int o = 16; o; o >>= 1) {
        s  += __shfl_down_sync(0xffffffffu, s,  o);
        ss += __shfl_down_sync(0xffffffffu, ss, o);
    }
    if ((tid & 31) == 0) { red[tid>>5] = s; red[32 + (tid>>5)] = ss; }

    if (tid < 224) {
        int vp = tid >> 3, sl = tid & 7;
        float a = 0.f;
        if (vp < VB) {
            for (int t = sl; t < TB; t += 8) a += wt_[t] * xs_[t*VB + vp];
        }
        a += __shfl_down_sync(0xffffffffu, a, 4);
        a += __shfl_down_sync(0xffffffffu, a, 2);
        a += __shfl_down_sync(0xffffffffu, a, 1);
        if (sl == 0 && vp < VB) {
            a += btv;
            int v = (vp - c) % VB; if (v < 0) v += VB;
            g_xt[nc*VB + v] = a;
            xta[vp] = a;
        }
    }
    __syncthreads();
    if (tid == 0) {
        float S = 0.f, SS = 0.f;
        for (int w = 0; w < (int)(blockDim.x >> 5); w++) { S += red[w]; SS += red[32+w]; }
        g_part1[nc*4 + 0] = S; g_part1[nc*4 + 1] = SS;
        S = 0.f; SS = 0.f;
        for (int v = 0; v < VB; v++) { S += xta[v]; SS += xta[v]*xta[v]; }
        g_part1[nc*4 + 2] = S; g_part1[nc*4 + 3] = SS;
    }
}

// ---------------- K3: inline stats1 + Ws stage (grid n x 5 chunks), 4x4 tiles ----------------
__global__ void k3(const float* __restrict__ gv, const float* __restrict__ bev,
                   const float* __restrict__ gt, const float* __restrict__ bet,
                   const float* __restrict__ Ws, const float* __restrict__ bs)
{
    extern __shared__ float sm3[];
    float* sfs    = sm3;            // [64][68]
    float* wst    = sm3 + 64*68;    // [64*64] transposed Ws
    float* red_s  = wst + 4096;     // [17][64]
    float* red_ss = red_s + 17*64;  // [17][64]
    __shared__ float rbuf[9*4];
    __shared__ float st1[4];

    int b = blockIdx.x;
    int n = b / 5, kc = b % 5;
    int tid = threadIdx.x;

    {
        float a0=0.f, a1=0.f, a2=0.f, a3=0.f;
        for (int j = tid; j < NB*CB; j += blockDim.x) {
            a0 += g_part1[j*4+0]; a1 += g_part1[j*4+1];
            a2 += g_part1[j*4+2]; a3 += g_part1[j*4+3];
        }
        #pragma unroll
        for (int o = 16; o; o >>= 1) {
            a0 += __shfl_down_sync(0xffffffffu, a0, o);
            a1 += __shfl_down_sync(0xffffffffu, a1, o);
            a2 += __shfl_down_sync(0xffffffffu, a2, o);
            a3 += __shfl_down_sync(0xffffffffu, a3, o);
        }
        if ((tid & 31) == 0) {
            int w = tid >> 5;
            rbuf[w*4+0]=a0; rbuf[w*4+1]=a1; rbuf[w*4+2]=a2; rbuf[w*4+3]=a3;
        }
        __syncthreads();
        if (tid == 0) {
            float A0=0,A1=0,A2=0,A3=0;
            for (int w = 0; w < 9; w++) { A0+=rbuf[w*4]; A1+=rbuf[w*4+1]; A2+=rbuf[w*4+2]; A3+=rbuf[w*4+3]; }
            float cntv = (float)(NB*CB*TB), cntt = (float)(NB*CB*VB);
            float mv = A0/cntv, vv = A1/cntv - mv*mv;
            float mt = A2/cntt, vt = A3/cntt - mt*mt;
            st1[0] = mv; st1[1] = rsqrtf(vv + EPSB);
            st1[2] = mt; st1[3] = rsqrtf(vt + EPSB);
        }
        __syncthreads();
    }
    float mv = st1[0], rv = st1[1], mt = st1[2], rt = st1[3];
    float gvv = gv[0], bevv = bev[0], gtv = gt[0], betv = bet[0];

    for (int i = tid; i < 64*68; i += blockDim.x) {
        int cc = i / 68, ll = i % 68;
        float val = 0.f;
        if (ll < 65) {
            int p = cc*LTOT + kc*65 + ll;
            if (p < 1600) {
                int cs = p / 25, v = p % 25;
                float x = g_xt[(n*64 + cs)*25 + v];
                val = hswish(gtv * (x - mt) * rt + betv);
            } else {
                int q = p - 1600;
                int cs = q / 300, t = q % 300;
                float x = g_xv[(n*64 + cs)*300 + t];
                val = hswish(gvv * (x - mv) * rv + bevv);
            }
        }
        sfs[i] = val;
    }
    for (int i = tid; i < 4096; i += blockDim.x) {
        int o = i & 63, cc = i >> 6;
        wst[i] = Ws[o*64 + cc];
    }
    __syncthreads();

    if (tid < 272) {
        int og = tid & 15, kg = tid >> 4;
        int o0 = og * 4, kl0 = kg * 4;
        float acc[4][4];
        #pragma unroll
        for (int j = 0; j < 4; j++) {
            float bb = bs[o0 + j];
            #pragma unroll
            for (int i = 0; i < 4; i++) acc[j][i] = bb;
        }
        for (int cc = 0; cc < 64; cc++) {
            float4 a = *(const float4*)&wst[cc*64 + o0];
            float4 bq = *(const float4*)&sfs[cc*68 + kl0];
            acc[0][0] += a.x*bq.x; acc[0][1] += a.x*bq.y; acc[0][2] += a.x*bq.z; acc[0][3] += a.x*bq.w;
            acc[1][0] += a.y*bq.x; acc[1][1] += a.y*bq.y; acc[1][2] += a.y*bq.z; acc[1][3] += a.y*bq.w;
            acc[2][0] += a.z*bq.x; acc[2][1] += a.z*bq.y; acc[2][2] += a.z*bq.z; acc[2][3] += a.z*bq.w;
            acc[3][0] += a.w*bq.x; acc[3][1] += a.w*bq.y; acc[3][2] += a.w*bq.z; acc[3][3] += a.w*bq.w;
        }
        #pragma unroll
        for (int j = 0; j < 4; j++) {
            float s = 0.f, ssum = 0.f;
            #pragma unroll
            for (int i = 0; i < 4; i++) {
                int kl = kl0 + i;
                if (kl < 65) {
                    float v = acc[j][i];
                    g_xs[(n*64 + o0 + j)*LTOT + kc*65 + kl] = v;
                    s += v; ssum += v*v;
                }
            }
            red_s [kg*64 + o0 + j] = s;
            red_ss[kg*64 + o0 + j] = ssum;
        }
    }
    __syncthreads();
    if (tid < 64) {
        float S = 0.f, SS = 0.f;
        for (int kg = 0; kg < 17; kg++) { S += red_s[kg*64 + tid]; SS += red_ss[kg*64 + tid]; }
        g_part2[(b*64 + tid)*2 + 0] = S;
        g_part2[(b*64 + tid)*2 + 1] = SS;
    }
}

// ---------------- K56: fused stats2 + xbar column + squeeze outputs (block per l) ----
__global__ void k56(const float* __restrict__ gs, const float* __restrict__ bes,
                    const float* __restrict__ Wt2, const float* __restrict__ bt2,
                    const float* __restrict__ Wv2, const float* __restrict__ bv2,
                    float* __restrict__ out_xtime)
{
    __shared__ float w2t[4096];
    __shared__ float red_a[256], red_b[256];
    __shared__ float stats2_s[128];
    __shared__ float xbar_s[64];

    int l = blockIdx.x;
    int tid = threadIdx.x;

    const float* W2 = (l < TB) ? Wt2 : Wv2;
    for (int i = tid; i < 4096; i += blockDim.x) {
        int o = i >> 6, d = i & 63;
        w2t[d*64 + o] = W2[i];
    }

    {
        int o = tid & 63, sl = tid >> 6;
        float s = 0.f, ss = 0.f;
        for (int ch = sl; ch < 320; ch += 4) {
            s  += g_part2[(ch*64 + o)*2 + 0];
            ss += g_part2[(ch*64 + o)*2 + 1];
        }
        red_a[tid] = s; red_b[tid] = ss;
        __syncthreads();
        if (tid < 64) {
            float S  = red_a[tid] + red_a[64+tid] + red_a[128+tid] + red_a[192+tid];
            float SS = red_b[tid] + red_b[64+tid] + red_b[128+tid] + red_b[192+tid];
            float cnt = 64.f * (float)LTOT;
            float m = S/cnt, v = SS/cnt - m*m;
            stats2_s[tid*2 + 0] = m;
            stats2_s[tid*2 + 1] = rsqrtf(v + EPSB);
        }
        __syncthreads();
    }

    {
        int d = tid & 63, ns = tid >> 6;
        float m = stats2_s[d*2], r = stats2_s[d*2+1];
        float g = gs[d], bb = bes[d];
        float acc = 0.f;
        for (int n = ns; n < 64; n += 4)
            acc += hswish(g * (g_xs[(n*64 + d)*LTOT + l] - m) * r + bb);
        red_a[tid] = acc;
        __syncthreads();
        if (tid < 64)
            xbar_s[tid] = (red_a[tid] + red_a[64+tid] + red_a[128+tid] + red_a[192+tid]) * (1.0f/64.0f);
        __syncthreads();
    }

    if (tid < 64) {
        int o = tid;
        float acc = (l < TB) ? bt2[o] : bv2[o];
        #pragma unroll 8
        for (int d = 0; d < 64; d++) acc += w2t[d*64 + o] * xbar_s[d];
        float sg = 1.0f / (1.0f + expf(-acc));
        if (l < TB) out_xtime[o*TB + l] = sg;
        else        g_scale[(l - TB)*64 + o] = tanhf(sg) + 1.0f;
    }
}

// ---------------- K7: GEMM + inline BN partials + shifted-layout store ----------------
// 1024 threads; warp w (0..24), lane = ddg; 10t x 2dd per thread via FFMA2.
// Epilogue permutes through smem and writes g_y0 in FINAL output layout [n][dd][t][i].
#define XMP_CS 12
#define XMP_WS 772      // 64*12 + 4 pad
#define XMP_TOT (VB*XMP_WS)   // 19300 floats; also reused as 10x1632 perm buffer (16320)
#define YSM_PITCH 1632
__global__ void __launch_bounds__(1024, 1)
k7(const float* __restrict__ x0, const float* __restrict__ Lw,
   const float* __restrict__ Lb)
{
    extern __shared__ float sm7[];
    float* xmp = sm7;                 // 19300
    float* lws = sm7 + XMP_TOT;       // 4096, 16B-aligned
    float* ssc = lws + 4096;          // 25*65
    float* lbs = ssc + 1625;          // 64

    int b = blockIdx.x;
    int n = b / (TB/K7T);
    int t0 = (b % (TB/K7T)) * K7T;
    int tid = threadIdx.x;

    for (int i = tid; i < 4096; i += 1024) lws[i] = Lw[i];
    for (int i = tid; i < VB*CB; i += 1024) {
        int w = i >> 6, c = i & 63;
        ssc[w*65 + c] = g_scale[i];
    }
    if (tid < 64) lbs[tid] = Lb[tid];
    __syncthreads();

    // build: loop (c,v) pairs; strength-reduced t-loop (MLP 10)
    const float* xbase = x0 + ((size_t)(n*64) * 300 + t0) * 25;
    for (int pr = tid; pr < CB*VB; pr += 1024) {
        int c = pr / 25;
        int v = pr - c*25;
        int w = v - (c % 25); if (w < 0) w += 25;
        float sc = ssc[w*65 + c];
        const float* src = xbase + (size_t)c * 7500 + v;
        float* dst = xmp + w*XMP_WS + c*XMP_CS;
        #pragma unroll
        for (int t = 0; t < K7T; t++)
            dst[t] = src[t*25] * sc;
    }
    __syncthreads();

    int w   = tid >> 5;     // warp index == w
    int ddg = tid & 31;
    int dd0 = ddg << 1;
    unsigned long long acc[5][2];

    if (w < 25) {
        const unsigned long long* xq = (const unsigned long long*)(xmp + w*XMP_WS);
        {
            unsigned long long i0 = pk2(lbs[dd0],     lbs[dd0]);
            unsigned long long i1 = pk2(lbs[dd0 + 1], lbs[dd0 + 1]);
            #pragma unroll
            for (int tp = 0; tp < 5; tp++) { acc[tp][0] = i0; acc[tp][1] = i1; }
        }
        #pragma unroll 4
        for (int c = 0; c < 64; c++) {
            ulonglong2 A01 = *(const ulonglong2*)(xq + c*6);
            ulonglong2 A23 = *(const ulonglong2*)(xq + c*6 + 2);
            unsigned long long A4 = xq[c*6 + 4];
            float2 bf = *(const float2*)&lws[(c << 6) + dd0];
            unsigned long long b0 = pk2(bf.x, bf.x);
            unsigned long long b1 = pk2(bf.y, bf.y);
            fma2(acc[0][0], A01.x, b0); fma2(acc[0][1], A01.x, b1);
            fma2(acc[1][0], A01.y, b0); fma2(acc[1][1], A01.y, b1);
            fma2(acc[2][0], A23.x, b0); fma2(acc[2][1], A23.x, b1);
            fma2(acc[3][0], A23.y, b0); fma2(acc[3][1], A23.y, b1);
            fma2(acc[4][0], A4,    b0); fma2(acc[4][1], A4,    b1);
        }
    }
    __syncthreads();   // all xmp reads done; reuse as permute buffer

    float* ysm = sm7;  // [10][1632]: t*1632 + i*65 + dd
    if (w < 25) {
        int i_e = (w + dd0) % 25;          // dest i for feature dd0
        int i_o = (w + dd0 + 1) % 25;      // dest i for feature dd0+1
        float psum0 = 0.f, psum1 = 0.f, psq0 = 0.f, psq1 = 0.f;
        #pragma unroll
        for (int tp = 0; tp < 5; tp++) {
            float e0, o0, e1, o1;
            upk2(e0, o0, acc[tp][0]);      // (t=2tp, dd0), (t=2tp+1, dd0)
            upk2(e1, o1, acc[tp][1]);      // (t=2tp, dd0+1), (t=2tp+1, dd0+1)
            int te = 2*tp, to = 2*tp + 1;
            ysm[te*YSM_PITCH + i_e*65 + dd0]     = e0;
            ysm[te*YSM_PITCH + i_o*65 + dd0 + 1] = e1;
            ysm[to*YSM_PITCH + i_e*65 + dd0]     = o0;
            ysm[to*YSM_PITCH + i_o*65 + dd0 + 1] = o1;
            psum0 += e0 + o0; psq0 += e0*e0 + o0*o0;
            psum1 += e1 + o1; psq1 += e1*e1 + o1*o1;
        }
        *(float2*)&g_part3[(size_t)b*3200 + (w << 6) + dd0]        = make_float2(psum0, psum1);
        *(float2*)&g_part3[(size_t)b*3200 + 1600 + (w << 6) + dd0] = make_float2(psq0,  psq1);
    }
    __syncthreads();

    // coalesced store: g_y0 layout [n][dd][t][i]; consecutive idx = consecutive global
    size_t base = (size_t)n * 480000 + (size_t)t0 * 25;
    #pragma unroll
    for (int k = 0; k < 16; k++) {
        int idx = (k << 10) + tid;          // 0..16383
        if (idx < 16000) {
            int dd = idx / 250;
            int r  = idx - dd*250;          // t_local*25 + i
            int t  = r / 25;
            int i  = r - t*25;
            g_y0[base + (size_t)dd*7500 + r] = ysm[t*YSM_PITCH + i*65 + dd];
        }
    }
}

// ---------------- K8b: reduce BN partials -> per-feature stats ----------------
__global__ void k8b()
{
    __shared__ float red_s[256], red_ss[256];
    int f = blockIdx.x * 32 + (threadIdx.x & 31);
    int sl = threadIdx.x >> 5;
    float s = 0.f, ss = 0.f;
    for (int b = sl; b < K7_BLOCKS; b += 8) {
        s  += g_part3[(size_t)b*3200 + f];
        ss += g_part3[(size_t)b*3200 + 1600 + f];
    }
    red_s[threadIdx.x] = s; red_ss[threadIdx.x] = ss;
    __syncthreads();
    if (threadIdx.x < 32) {
        float S = 0.f, SS = 0.f;
        #pragma unroll
        for (int k = 0; k < 8; k++) { S += red_s[k*32 + threadIdx.x]; SS += red_ss[k*32 + threadIdx.x]; }
        int ff = blockIdx.x * 32 + threadIdx.x;
        float cnt = (float)NTOT;
        float m = S/cnt, v = SS/cnt - m*m;
        g_stats3[ff*2 + 0] = m;
        g_stats3[ff*2 + 1] = rsqrtf(v + EPSB);
    }
}

// ---------------- K9: pure streaming BN + residual + relu ----------------
// g_y0 is already in output layout [n][dd][t][i]; block = one (n,dd) row (7500 floats).
__global__ void k9(const float* __restrict__ x0, const float* __restrict__ gbn,
                   const float* __restrict__ bbn, float* __restrict__ out)
{
    __shared__ float A[25], Bc[25];
    int b = blockIdx.x;            // n*64 + dd
    int dd = b & 63;
    int tid = threadIdx.x;

    if (tid < 25) {
        int i = tid;
        int wsrc = i - (dd % 25); if (wsrc < 0) wsrc += 25;   // pre-shift w for (i,dd)
        int p = wsrc*64 + dd;      // stats feature (pre-shift)
        int q = i*64 + dd;         // gbn/bbn feature (post-shift)
        float m = g_stats3[p*2], r = g_stats3[p*2 + 1];
        float g = gbn[q];
        A[i]  = g * r;
        Bc[i] = bbn[q] - g * r * m;
    }
    __syncthreads();

    const float4* y4 = (const float4*)(g_y0 + (size_t)b * 7500);
    const float4* x4 = (const float4*)(x0   + (size_t)b * 7500);
    float4*       o4 = (float4*)(out        + (size_t)b * 7500);
    for (int p4 = tid; p4 < 1875; p4 += blockDim.x) {
        float4 y = y4[p4];
        float4 x = x4[p4];
        int i = (p4 << 2) % 25;
        float4 o;
        o.x = fmaxf(fmaf(A[i], y.x, Bc[i]) + x.x, 0.f); if (++i == 25) i = 0;
        o.y = fmaxf(fmaf(A[i], y.y, Bc[i]) + x.y, 0.f); if (++i == 25) i = 0;
        o.z = fmaxf(fmaf(A[i], y.z, Bc[i]) + x.z, 0.f); if (++i == 25) i = 0;
        o.w = fmaxf(fmaf(A[i], y.w, Bc[i]) + x.w, 0.f);
        o4[p4] = o;
    }
}

// ---------------- launcher (6 launches; slot 4 = k7 for ncu capture) ----------------
extern "C" void kernel_launch(void* const* d_in, const int* in_sizes, int n_in,
                              void* d_out, int out_size)
{
    const float* x0  = (const float*)d_in[0];
    const float* Wv  = (const float*)d_in[3];
    const float* bv  = (const float*)d_in[4];
    const float* gv  = (const float*)d_in[5];
    const float* bev = (const float*)d_in[6];
    const float* Wt  = (const float*)d_in[7];
    const float* bt  = (const float*)d_in[8];
    const float* gt  = (const float*)d_in[9];
    const float* bet = (const float*)d_in[10];
    const float* Ws  = (const float*)d_in[11];
    const float* bs  = (const float*)d_in[12];
    const float* gs  = (const float*)d_in[13];
    const float* bes = (const float*)d_in[14];
    const float* Wv2 = (const float*)d_in[15];
    const float* bv2 = (const float*)d_in[16];
    const float* Wt2 = (const float*)d_in[17];
    const float* bt2 = (const float*)d_in[18];
    const float* Lw  = (const float*)d_in[19];
    const float* Lb  = (const float*)d_in[20];
    const float* gbn = (const float*)d_in[21];
    const float* bbn = (const float*)d_in[22];
    float* out = (float*)d_out;

    static_assert((TB % K7T) == 0, "k7 t tiling");
    static_assert((XMP_TOT % 4) == 0, "xmp align");
    static_assert(XMP_CS * CB < XMP_WS, "xmp pad");
    static_assert(K7T * YSM_PITCH <= XMP_TOT, "perm buffer fits");

    const int smem3 = (64*68 + 4096 + 17*64*2) * 4;                 // 51200
    const int smem7 = (XMP_TOT + 4096 + 1625 + 64) * 4;             // 100340
    cudaFuncSetAttribute(k3, cudaFuncAttributeMaxDynamicSharedMemorySize, smem3);
    cudaFuncSetAttribute(k7, cudaFuncAttributeMaxDynamicSharedMemorySize, smem7);

    k1 <<<NB*CB, 256>>>(x0, Wv, bv, Wt, bt);
    k3 <<<NB*5, 288, smem3>>>(gv, bev, gt, bet, Ws, bs);
    k56<<<LTOT, 256>>>(gs, bes, Wt2, bt2, Wv2, bv2, out + Y_SIZE);
    k7 <<<K7_BLOCKS, 1024, smem7>>>(x0, Lw, Lb);
    k8b<<<FEAT/32, 256>>>();
    k9 <<<NB*DB, 256>>>(x0, gbn, bbn, out);
}

// round 14
// speedup vs baseline: 2.2449x; 1.0441x over previous
#include <cuda_runtime.h>
#include <math.h>

// Problem constants
#define NB 64
#define CB 64
#define DB 64
#define TB 300
#define VB 25
#define EPSB 1e-5f
#define NTOT (NB*TB)          // 19200 rows
#define FEAT (VB*DB)          // 1600 features
#define LTOT (TB+VB)          // 325
#define Y_SIZE (NB*DB*TB*VB)  // 30720000

#define K7T 10                // t-rows per k7 block
#define K7_BLOCKS (NB*(TB/K7T))   // 1920

// ---------------- scratch (device globals; no runtime allocation) ----------------
__device__ float g_xv[NB*CB*TB];        // 4.9 MB
__device__ float g_xt[NB*CB*VB];        // 0.4 MB
__device__ float g_part1[NB*CB*4];      // per-(n,c) partials (sv,svv,st,stt)
__device__ float g_xs[NB*DB*LTOT];      // 5.3 MB
__device__ float g_part2[320*DB*2];     // per-(n,kc) per-o partials
__device__ float g_scale[VB*CB];        // tanh(sigmoid(view))+1, [w][c]
__device__ float g_y0[(size_t)NTOT*FEAT];     // 123 MB : SHIFTED layout [n][dd][t][i]
__device__ float g_part3[K7_BLOCKS*3200];     // 24.6 MB : per-block BN partials
__device__ float g_stats3[FEAT*2];      // y0 feature mean/rstd (pre-shift feature w*64+dd)

__device__ __forceinline__ float hswish(float x) {
    float c = fminf(fmaxf(x + 3.0f, 0.0f), 6.0f);
    return x * c * (1.0f / 6.0f);
}
__device__ __forceinline__ unsigned long long pk2(float lo, float hi) {
    unsigned long long r;
    asm("mov.b64 %0, {%1, %2};" : "=l"(r) : "f"(lo), "f"(hi));
    return r;
}
__device__ __forceinline__ void upk2(float& lo, float& hi, unsigned long long v) {
    asm("mov.b64 {%0, %1}, %2;" : "=f"(lo), "=f"(hi) : "l"(v));
}
__device__ __forceinline__ void fma2(unsigned long long& d, unsigned long long a, unsigned long long b) {
    asm("fma.rn.f32x2 %0, %1, %2, %0;" : "+l"(d) : "l"(a), "l"(b));
}

// ---------------- K1: per-(n,c) slice — xv (V-reduce) + xt (T-reduce) + partials ----
__global__ void k1(const float* __restrict__ x0, const float* __restrict__ Wv,
                   const float* __restrict__ bv, const float* __restrict__ Wt,
                   const float* __restrict__ bt)
{
    __shared__ float xs_[TB*VB];
    __shared__ float wt_[TB];
    __shared__ float wvc[VB];
    __shared__ float red[64];
    __shared__ float xta[VB];

    int nc = blockIdx.x;
    int c  = nc & 63;
    int tid = threadIdx.x;

    const float4* src4 = (const float4*)(x0 + (size_t)nc * (TB*VB));
    for (int i = tid; i < 1875; i += blockDim.x) ((float4*)xs_)[i] = src4[i];
    for (int i = tid; i < TB;   i += blockDim.x) wt_[i] = Wt[i];
    if (tid < VB) {
        int v = (tid - c) % VB; if (v < 0) v += VB;
        wvc[tid] = Wv[v];
    }
    float bvv = bv[0], btv = bt[0];
    __syncthreads();

    float s = 0.f, ss = 0.f;
    for (int t = tid; t < TB; t += blockDim.x) {
        float a = bvv;
        #pragma unroll
        for (int v = 0; v < VB; v++) a += wvc[v] * xs_[t*VB + v];
        g_xv[nc*TB + t] = a;
        s += a; ss += a*a;
    }
    #pragma unroll
    for (int o = 16; o; o >>= 1) {
        s  += __shfl_down_sync(0xffffffffu, s,  o);
        ss += __shfl_down_sync(0xffffffffu, ss, o);
    }
    if ((tid & 31) == 0) { red[tid>>5] = s; red[32 + (tid>>5)] = ss; }

    if (tid < 224) {
        int vp = tid >> 3, sl = tid & 7;
        float a = 0.f;
        if (vp < VB) {
            for (int t = sl; t < TB; t += 8) a += wt_[t] * xs_[t*VB + vp];
        }
        a += __shfl_down_sync(0xffffffffu, a, 4);
        a += __shfl_down_sync(0xffffffffu, a, 2);
        a += __shfl_down_sync(0xffffffffu, a, 1);
        if (sl == 0 && vp < VB) {
            a += btv;
            int v = (vp - c) % VB; if (v < 0) v += VB;
            g_xt[nc*VB + v] = a;
            xta[vp] = a;
        }
    }
    __syncthreads();
    if (tid == 0) {
        float S = 0.f, SS = 0.f;
        for (int w = 0; w < (int)(blockDim.x >> 5); w++) { S += red[w]; SS += red[32+w]; }
        g_part1[nc*4 + 0] = S; g_part1[nc*4 + 1] = SS;
        S = 0.f; SS = 0.f;
        for (int v = 0; v < VB; v++) { S += xta[v]; SS += xta[v]*xta[v]; }
        g_part1[nc*4 + 2] = S; g_part1[nc*4 + 3] = SS;
    }
}

// ---------------- K3: inline stats1 + Ws stage (grid n x 5 chunks), 4x4 tiles ----------------
__global__ void k3(const float* __restrict__ gv, const float* __restrict__ bev,
                   const float* __restrict__ gt, const float* __restrict__ bet,
                   const float* __restrict__ Ws, const float* __restrict__ bs)
{
    extern __shared__ float sm3[];
    float* sfs    = sm3;            // [64][68]
    float* wst    = sm3 + 64*68;    // [64*64] transposed Ws
    float* red_s  = wst + 4096;     // [17][64]
    float* red_ss = red_s + 17*64;  // [17][64]
    __shared__ float rbuf[9*4];
    __shared__ float st1[4];

    int b = blockIdx.x;
    int n = b / 5, kc = b % 5;
    int tid = threadIdx.x;

    {
        float a0=0.f, a1=0.f, a2=0.f, a3=0.f;
        for (int j = tid; j < NB*CB; j += blockDim.x) {
            a0 += g_part1[j*4+0]; a1 += g_part1[j*4+1];
            a2 += g_part1[j*4+2]; a3 += g_part1[j*4+3];
        }
        #pragma unroll
        for (int o = 16; o; o >>= 1) {
            a0 += __shfl_down_sync(0xffffffffu, a0, o);
            a1 += __shfl_down_sync(0xffffffffu, a1, o);
            a2 += __shfl_down_sync(0xffffffffu, a2, o);
            a3 += __shfl_down_sync(0xffffffffu, a3, o);
        }
        if ((tid & 31) == 0) {
            int w = tid >> 5;
            rbuf[w*4+0]=a0; rbuf[w*4+1]=a1; rbuf[w*4+2]=a2; rbuf[w*4+3]=a3;
        }
        __syncthreads();
        if (tid == 0) {
            float A0=0,A1=0,A2=0,A3=0;
            for (int w = 0; w < 9; w++) { A0+=rbuf[w*4]; A1+=rbuf[w*4+1]; A2+=rbuf[w*4+2]; A3+=rbuf[w*4+3]; }
            float cntv = (float)(NB*CB*TB), cntt = (float)(NB*CB*VB);
            float mv = A0/cntv, vv = A1/cntv - mv*mv;
            float mt = A2/cntt, vt = A3/cntt - mt*mt;
            st1[0] = mv; st1[1] = rsqrtf(vv + EPSB);
            st1[2] = mt; st1[3] = rsqrtf(vt + EPSB);
        }
        __syncthreads();
    }
    float mv = st1[0], rv = st1[1], mt = st1[2], rt = st1[3];
    float gvv = gv[0], bevv = bev[0], gtv = gt[0], betv = bet[0];

    for (int i = tid; i < 64*68; i += blockDim.x) {
        int cc = i / 68, ll = i % 68;
        float val = 0.f;
        if (ll < 65) {
            int p = cc*LTOT + kc*65 + ll;
            if (p < 1600) {
                int cs = p / 25, v = p % 25;
                float x = g_xt[(n*64 + cs)*25 + v];
                val = hswish(gtv * (x - mt) * rt + betv);
            } else {
                int q = p - 1600;
                int cs = q / 300, t = q % 300;
                float x = g_xv[(n*64 + cs)*300 + t];
                val = hswish(gvv * (x - mv) * rv + bevv);
            }
        }
        sfs[i] = val;
    }
    for (int i = tid; i < 4096; i += blockDim.x) {
        int o = i & 63, cc = i >> 6;
        wst[i] = Ws[o*64 + cc];
    }
    __syncthreads();

    if (tid < 272) {
        int og = tid & 15, kg = tid >> 4;
        int o0 = og * 4, kl0 = kg * 4;
        float acc[4][4];
        #pragma unroll
        for (int j = 0; j < 4; j++) {
            float bb = bs[o0 + j];
            #pragma unroll
            for (int i = 0; i < 4; i++) acc[j][i] = bb;
        }
        for (int cc = 0; cc < 64; cc++) {
            float4 a = *(const float4*)&wst[cc*64 + o0];
            float4 bq = *(const float4*)&sfs[cc*68 + kl0];
            acc[0][0] += a.x*bq.x; acc[0][1] += a.x*bq.y; acc[0][2] += a.x*bq.z; acc[0][3] += a.x*bq.w;
            acc[1][0] += a.y*bq.x; acc[1][1] += a.y*bq.y; acc[1][2] += a.y*bq.z; acc[1][3] += a.y*bq.w;
            acc[2][0] += a.z*bq.x; acc[2][1] += a.z*bq.y; acc[2][2] += a.z*bq.z; acc[2][3] += a.z*bq.w;
            acc[3][0] += a.w*bq.x; acc[3][1] += a.w*bq.y; acc[3][2] += a.w*bq.z; acc[3][3] += a.w*bq.w;
        }
        #pragma unroll
        for (int j = 0; j < 4; j++) {
            float s = 0.f, ssum = 0.f;
            #pragma unroll
            for (int i = 0; i < 4; i++) {
                int kl = kl0 + i;
                if (kl < 65) {
                    float v = acc[j][i];
                    g_xs[(n*64 + o0 + j)*LTOT + kc*65 + kl] = v;
                    s += v; ssum += v*v;
                }
            }
            red_s [kg*64 + o0 + j] = s;
            red_ss[kg*64 + o0 + j] = ssum;
        }
    }
    __syncthreads();
    if (tid < 64) {
        float S = 0.f, SS = 0.f;
        for (int kg = 0; kg < 17; kg++) { S += red_s[kg*64 + tid]; SS += red_ss[kg*64 + tid]; }
        g_part2[(b*64 + tid)*2 + 0] = S;
        g_part2[(b*64 + tid)*2 + 1] = SS;
    }
}

// ---------------- K56: fused stats2 + xbar column + squeeze outputs (block per l) ----
__global__ void k56(const float* __restrict__ gs, const float* __restrict__ bes,
                    const float* __restrict__ Wt2, const float* __restrict__ bt2,
                    const float* __restrict__ Wv2, const float* __restrict__ bv2,
                    float* __restrict__ out_xtime)
{
    __shared__ float w2t[4096];
    __shared__ float red_a[256], red_b[256];
    __shared__ float stats2_s[128];
    __shared__ float xbar_s[64];

    int l = blockIdx.x;
    int tid = threadIdx.x;

    const float* W2 = (l < TB) ? Wt2 : Wv2;
    for (int i = tid; i < 4096; i += blockDim.x) {
        int o = i >> 6, d = i & 63;
        w2t[d*64 + o] = W2[i];
    }

    {
        int o = tid & 63, sl = tid >> 6;
        float s = 0.f, ss = 0.f;
        for (int ch = sl; ch < 320; ch += 4) {
            s  += g_part2[(ch*64 + o)*2 + 0];
            ss += g_part2[(ch*64 + o)*2 + 1];
        }
        red_a[tid] = s; red_b[tid] = ss;
        __syncthreads();
        if (tid < 64) {
            float S  = red_a[tid] + red_a[64+tid] + red_a[128+tid] + red_a[192+tid];
            float SS = red_b[tid] + red_b[64+tid] + red_b[128+tid] + red_b[192+tid];
            float cnt = 64.f * (float)LTOT;
            float m = S/cnt, v = SS/cnt - m*m;
            stats2_s[tid*2 + 0] = m;
            stats2_s[tid*2 + 1] = rsqrtf(v + EPSB);
        }
        __syncthreads();
    }

    {
        int d = tid & 63, ns = tid >> 6;
        float m = stats2_s[d*2], r = stats2_s[d*2+1];
        float g = gs[d], bb = bes[d];
        float acc = 0.f;
        for (int n = ns; n < 64; n += 4)
            acc += hswish(g * (g_xs[(n*64 + d)*LTOT + l] - m) * r + bb);
        red_a[tid] = acc;
        __syncthreads();
        if (tid < 64)
            xbar_s[tid] = (red_a[tid] + red_a[64+tid] + red_a[128+tid] + red_a[192+tid]) * (1.0f/64.0f);
        __syncthreads();
    }

    if (tid < 64) {
        int o = tid;
        float acc = (l < TB) ? bt2[o] : bv2[o];
        #pragma unroll 8
        for (int d = 0; d < 64; d++) acc += w2t[d*64 + o] * xbar_s[d];
        float sg = 1.0f / (1.0f + expf(-acc));
        if (l < TB) out_xtime[o*TB + l] = sg;
        else        g_scale[(l - TB)*64 + o] = tanhf(sg) + 1.0f;
    }
}

// ---------------- K7: GEMM + inline BN partials + shifted-layout store ----------------
// 1024 threads; warp w (0..24), lane = ddg; 10t x 2dd per thread via FFMA2.
// Epilogue permutes through smem ([dd][250] layout) and writes g_y0 in FINAL
// output layout [n][dd][t][i] with float2 coalesced stores.
#define XMP_CS 12
#define XMP_WS 772      // 64*12 + 4 pad
#define XMP_TOT (VB*XMP_WS)   // 19300 floats; also reused as 64x250 perm buffer (16000)
__global__ void __launch_bounds__(1024, 1)
k7(const float* __restrict__ x0, const float* __restrict__ Lw,
   const float* __restrict__ Lb)
{
    extern __shared__ float sm7[];
    float* xmp = sm7;                 // 19300
    float* lws = sm7 + XMP_TOT;       // 4096, 16B-aligned
    float* ssc = lws + 4096;          // 25*65
    float* lbs = ssc + 1625;          // 64

    int b = blockIdx.x;
    int n = b / (TB/K7T);
    int t0 = (b % (TB/K7T)) * K7T;
    int tid = threadIdx.x;

    for (int i = tid; i < 4096; i += 1024) lws[i] = Lw[i];
    for (int i = tid; i < VB*CB; i += 1024) {
        int w = i >> 6, c = i & 63;
        ssc[w*65 + c] = g_scale[i];
    }
    if (tid < 64) lbs[tid] = Lb[tid];
    __syncthreads();

    // build: loop (c,v) pairs; strength-reduced t-loop (MLP 10)
    const float* xbase = x0 + ((size_t)(n*64) * 300 + t0) * 25;
    for (int pr = tid; pr < CB*VB; pr += 1024) {
        int c = pr / 25;
        int v = pr - c*25;
        int w = v - (c % 25); if (w < 0) w += 25;
        float sc = ssc[w*65 + c];
        const float* src = xbase + (size_t)c * 7500 + v;
        float* dst = xmp + w*XMP_WS + c*XMP_CS;
        #pragma unroll
        for (int t = 0; t < K7T; t++)
            dst[t] = src[t*25] * sc;
    }
    __syncthreads();

    int w   = tid >> 5;     // warp index == w
    int ddg = tid & 31;
    int dd0 = ddg << 1;
    unsigned long long acc[5][2];

    if (w < 25) {
        const unsigned long long* xq = (const unsigned long long*)(xmp + w*XMP_WS);
        {
            unsigned long long i0 = pk2(lbs[dd0],     lbs[dd0]);
            unsigned long long i1 = pk2(lbs[dd0 + 1], lbs[dd0 + 1]);
            #pragma unroll
            for (int tp = 0; tp < 5; tp++) { acc[tp][0] = i0; acc[tp][1] = i1; }
        }
        #pragma unroll 4
        for (int c = 0; c < 64; c++) {
            ulonglong2 A01 = *(const ulonglong2*)(xq + c*6);
            ulonglong2 A23 = *(const ulonglong2*)(xq + c*6 + 2);
            unsigned long long A4 = xq[c*6 + 4];
            float2 bf = *(const float2*)&lws[(c << 6) + dd0];
            unsigned long long b0 = pk2(bf.x, bf.x);
            unsigned long long b1 = pk2(bf.y, bf.y);
            fma2(acc[0][0], A01.x, b0); fma2(acc[0][1], A01.x, b1);
            fma2(acc[1][0], A01.y, b0); fma2(acc[1][1], A01.y, b1);
            fma2(acc[2][0], A23.x, b0); fma2(acc[2][1], A23.x, b1);
            fma2(acc[3][0], A23.y, b0); fma2(acc[3][1], A23.y, b1);
            fma2(acc[4][0], A4,    b0); fma2(acc[4][1], A4,    b1);
        }
    }
    __syncthreads();   // all xmp reads done; reuse as permute buffer

    float* ysm = sm7;  // [64][250]: dd*250 + t*25 + i
    if (w < 25) {
        int i_e = (w + dd0) % 25;          // dest i for feature dd0
        int i_o = (w + dd0 + 1) % 25;      // dest i for feature dd0+1
        float* ysm_e = ysm + dd0*250 + i_e;
        float* ysm_o = ysm + (dd0 + 1)*250 + i_o;
        float psum0 = 0.f, psum1 = 0.f, psq0 = 0.f, psq1 = 0.f;
        #pragma unroll
        for (int tp = 0; tp < 5; tp++) {
            float e0, o0, e1, o1;
            upk2(e0, o0, acc[tp][0]);      // (t=2tp, dd0), (t=2tp+1, dd0)
            upk2(e1, o1, acc[tp][1]);      // (t=2tp, dd0+1), (t=2tp+1, dd0+1)
            ysm_e[(2*tp)*25]     = e0;
            ysm_o[(2*tp)*25]     = e1;
            ysm_e[(2*tp + 1)*25] = o0;
            ysm_o[(2*tp + 1)*25] = o1;
            psum0 += e0 + o0; psq0 += e0*e0 + o0*o0;
            psum1 += e1 + o1; psq1 += e1*e1 + o1*o1;
        }
        *(float2*)&g_part3[(size_t)b*3200 + (w << 6) + dd0]        = make_float2(psum0, psum1);
        *(float2*)&g_part3[(size_t)b*3200 + 1600 + (w << 6) + dd0] = make_float2(psq0,  psq1);
    }
    __syncthreads();

    // coalesced float2 store: g_y0 layout [n][dd][t][i]; per dd the 250 floats
    // are contiguous in both ysm and g_y0 (base and dd*7500 are even).
    size_t base = (size_t)n * 480000 + (size_t)t0 * 25;
    #pragma unroll
    for (int k = 0; k < 8; k++) {
        int idx2 = (k << 10) + tid;         // float2 index, 0..8191
        if (idx2 < 8000) {
            int dd = idx2 / 125;
            int r2 = idx2 - dd*125;
            *(float2*)&g_y0[base + (size_t)dd*7500 + 2*r2] =
                *(const float2*)&ysm[dd*250 + 2*r2];
        }
    }
}

// ---------------- K8b: reduce BN partials -> per-feature stats ----------------
__global__ void k8b()
{
    __shared__ float red_s[256], red_ss[256];
    int f = blockIdx.x * 32 + (threadIdx.x & 31);
    int sl = threadIdx.x >> 5;
    float s = 0.f, ss = 0.f;
    for (int b = sl; b < K7_BLOCKS; b += 8) {
        s  += g_part3[(size_t)b*3200 + f];
        ss += g_part3[(size_t)b*3200 + 1600 + f];
    }
    red_s[threadIdx.x] = s; red_ss[threadIdx.x] = ss;
    __syncthreads();
    if (threadIdx.x < 32) {
        float S = 0.f, SS = 0.f;
        #pragma unroll
        for (int k = 0; k < 8; k++) { S += red_s[k*32 + threadIdx.x]; SS += red_ss[k*32 + threadIdx.x]; }
        int ff = blockIdx.x * 32 + threadIdx.x;
        float cnt = (float)NTOT;
        float m = S/cnt, v = SS/cnt - m*m;
        g_stats3[ff*2 + 0] = m;
        g_stats3[ff*2 + 1] = rsqrtf(v + EPSB);
    }
}

// ---------------- K9: pure streaming BN + residual + relu ----------------
// g_y0 is already in output layout [n][dd][t][i]; block = one (n,dd) row (7500 floats).
__global__ void k9(const float* __restrict__ x0, const float* __restrict__ gbn,
                   const float* __restrict__ bbn, float* __restrict__ out)
{
    __shared__ float A[25], Bc[25];
    int b = blockIdx.x;            // n*64 + dd
    int dd = b & 63;
    int tid = threadIdx.x;

    if (tid < 25) {
        int i = tid;
        int wsrc = i - (dd % 25); if (wsrc < 0) wsrc += 25;   // pre-shift w for (i,dd)
        int p = wsrc*64 + dd;      // stats feature (pre-shift)
        int q = i*64 + dd;         // gbn/bbn feature (post-shift)
        float m = g_stats3[p*2], r = g_stats3[p*2 + 1];
        float g = gbn[q];
        A[i]  = g * r;
        Bc[i] = bbn[q] - g * r * m;
    }
    __syncthreads();

    const float4* y4 = (const float4*)(g_y0 + (size_t)b * 7500);
    const float4* x4 = (const float4*)(x0   + (size_t)b * 7500);
    float4*       o4 = (float4*)(out        + (size_t)b * 7500);
    for (int p4 = tid; p4 < 1875; p4 += blockDim.x) {
        float4 y = y4[p4];
        float4 x = x4[p4];
        int i = (p4 << 2) % 25;
        float4 o;
        o.x = fmaxf(fmaf(A[i], y.x, Bc[i]) + x.x, 0.f); if (++i == 25) i = 0;
        o.y = fmaxf(fmaf(A[i], y.y, Bc[i]) + x.y, 0.f); if (++i == 25) i = 0;
        o.z = fmaxf(fmaf(A[i], y.z, Bc[i]) + x.z, 0.f); if (++i == 25) i = 0;
        o.w = fmaxf(fmaf(A[i], y.w, Bc[i]) + x.w, 0.f);
        o4[p4] = o;
    }
}

// ---------------- launcher (6 launches; slot 4 = k7 for ncu capture) ----------------
extern "C" void kernel_launch(void* const* d_in, const int* in_sizes, int n_in,
                              void* d_out, int out_size)
{
    const float* x0  = (const float*)d_in[0];
    const float* Wv  = (const float*)d_in[3];
    const float* bv  = (const float*)d_in[4];
    const float* gv  = (const float*)d_in[5];
    const float* bev = (const float*)d_in[6];
    const float* Wt  = (const float*)d_in[7];
    const float* bt  = (const float*)d_in[8];
    const float* gt  = (const float*)d_in[9];
    const float* bet = (const float*)d_in[10];
    const float* Ws  = (const float*)d_in[11];
    const float* bs  = (const float*)d_in[12];
    const float* gs  = (const float*)d_in[13];
    const float* bes = (const float*)d_in[14];
    const float* Wv2 = (const float*)d_in[15];
    const float* bv2 = (const float*)d_in[16];
    const float* Wt2 = (const float*)d_in[17];
    const float* bt2 = (const float*)d_in[18];
    const float* Lw  = (const float*)d_in[19];
    const float* Lb  = (const float*)d_in[20];
    const float* gbn = (const float*)d_in[21];
    const float* bbn = (const float*)d_in[22];
    float* out = (float*)d_out;

    static_assert((TB % K7T) == 0, "k7 t tiling");
    static_assert((XMP_TOT % 4) == 0, "xmp align");
    static_assert(XMP_CS * CB < XMP_WS, "xmp pad");
    static_assert(DB * 250 <= XMP_TOT, "perm buffer fits");

    const int smem3 = (64*68 + 4096 + 17*64*2) * 4;                 // 51200
    const int smem7 = (XMP_TOT + 4096 + 1625 + 64) * 4;             // 100340
    cudaFuncSetAttribute(k3, cudaFuncAttributeMaxDynamicSharedMemorySize, smem3);
    cudaFuncSetAttribute(k7, cudaFuncAttributeMaxDynamicSharedMemorySize, smem7);

    k1 <<<NB*CB, 256>>>(x0, Wv, bv, Wt, bt);
    k3 <<<NB*5, 288, smem3>>>(gv, bev, gt, bet, Ws, bs);
    k56<<<LTOT, 256>>>(gs, bes, Wt2, bt2, Wv2, bv2, out + Y_SIZE);
    k7 <<<K7_BLOCKS, 1024, smem7>>>(x0, Lw, Lb);
    k8b<<<FEAT/32, 256>>>();
    k9 <<<NB*DB, 256>>>(x0, gbn, bbn, out);
}

// round 15
// speedup vs baseline: 2.3258x; 1.0360x over previous
#include <cuda_runtime.h>
#include <math.h>

// Problem constants
#define NB 64
#define CB 64
#define DB 64
#define TB 300
#define VB 25
#define EPSB 1e-5f
#define NTOT (NB*TB)          // 19200 rows
#define FEAT (VB*DB)          // 1600 features
#define LTOT (TB+VB)          // 325
#define Y_SIZE (NB*DB*TB*VB)  // 30720000

#define K7T 12                // t-rows per k7 block
#define K7_BLOCKS (NB*(TB/K7T))   // 1600

// ---------------- scratch (device globals; no runtime allocation) ----------------
__device__ float g_xv[NB*CB*TB];        // 4.9 MB
__device__ float g_xt[NB*CB*VB];        // 0.4 MB
__device__ float g_part1[NB*CB*4];      // per-(n,c) partials (sv,svv,st,stt)
__device__ float g_xs[NB*DB*LTOT];      // 5.3 MB
__device__ float g_part2[320*DB*2];     // per-(n,kc) per-o partials
__device__ float g_scale[VB*CB];        // tanh(sigmoid(view))+1, [w][c]
__device__ float g_y0[(size_t)NTOT*FEAT];     // 123 MB : SHIFTED layout [n][dd][t][i]
__device__ float g_part3[K7_BLOCKS*3200];     // 20.5 MB : per-block BN partials
__device__ float g_stats3[FEAT*2];      // y0 feature mean/rstd (pre-shift feature w*64+dd)

__device__ __forceinline__ float hswish(float x) {
    float c = fminf(fmaxf(x + 3.0f, 0.0f), 6.0f);
    return x * c * (1.0f / 6.0f);
}
__device__ __forceinline__ unsigned long long pk2(float lo, float hi) {
    unsigned long long r;
    asm("mov.b64 %0, {%1, %2};" : "=l"(r) : "f"(lo), "f"(hi));
    return r;
}
__device__ __forceinline__ void upk2(float& lo, float& hi, unsigned long long v) {
    asm("mov.b64 {%0, %1}, %2;" : "=f"(lo), "=f"(hi) : "l"(v));
}
__device__ __forceinline__ void fma2(unsigned long long& d, unsigned long long a, unsigned long long b) {
    asm("fma.rn.f32x2 %0, %1, %2, %0;" : "+l"(d) : "l"(a), "l"(b));
}

// ---------------- K1: per-(n,c) slice — xv (V-reduce) + xt (T-reduce) + partials ----
__global__ void k1(const float* __restrict__ x0, const float* __restrict__ Wv,
                   const float* __restrict__ bv, const float* __restrict__ Wt,
                   const float* __restrict__ bt)
{
    __shared__ float xs_[TB*VB];
    __shared__ float wt_[TB];
    __shared__ float wvc[VB];
    __shared__ float red[64];
    __shared__ float xta[VB];

    int nc = blockIdx.x;
    int c  = nc & 63;
    int tid = threadIdx.x;

    const float4* src4 = (const float4*)(x0 + (size_t)nc * (TB*VB));
    for (int i = tid; i < 1875; i += blockDim.x) ((float4*)xs_)[i] = src4[i];
    for (int i = tid; i < TB;   i += blockDim.x) wt_[i] = Wt[i];
    if (tid < VB) {
        int v = (tid - c) % VB; if (v < 0) v += VB;
        wvc[tid] = Wv[v];
    }
    float bvv = bv[0], btv = bt[0];
    __syncthreads();

    float s = 0.f, ss = 0.f;
    for (int t = tid; t < TB; t += blockDim.x) {
        float a = bvv;
        #pragma unroll
        for (int v = 0; v < VB; v++) a += wvc[v] * xs_[t*VB + v];
        g_xv[nc*TB + t] = a;
        s += a; ss += a*a;
    }
    #pragma unroll
    for (int o = 16; o; o >>= 1) {
        s  += __shfl_down_sync(0xffffffffu, s,  o);
        ss += __shfl_down_sync(0xffffffffu, ss, o);
    }
    if ((tid & 31) == 0) { red[tid>>5] = s; red[32 + (tid>>5)] = ss; }

    if (tid < 224) {
        int vp = tid >> 3, sl = tid & 7;
        float a = 0.f;
        if (vp < VB) {
            for (int t = sl; t < TB; t += 8) a += wt_[t] * xs_[t*VB + vp];
        }
        a += __shfl_down_sync(0xffffffffu, a, 4);
        a += __shfl_down_sync(0xffffffffu, a, 2);
        a += __shfl_down_sync(0xffffffffu, a, 1);
        if (sl == 0 && vp < VB) {
            a += btv;
            int v = (vp - c) % VB; if (v < 0) v += VB;
            g_xt[nc*VB + v] = a;
            xta[vp] = a;
        }
    }
    __syncthreads();
    if (tid == 0) {
        float S = 0.f, SS = 0.f;
        for (int w = 0; w < (int)(blockDim.x >> 5); w++) { S += red[w]; SS += red[32+w]; }
        g_part1[nc*4 + 0] = S; g_part1[nc*4 + 1] = SS;
        S = 0.f; SS = 0.f;
        for (int v = 0; v < VB; v++) { S += xta[v]; SS += xta[v]*xta[v]; }
        g_part1[nc*4 + 2] = S; g_part1[nc*4 + 3] = SS;
    }
}

// ---------------- K3: inline stats1 + Ws stage (grid n x 5 chunks), 4x4 tiles ----------------
__global__ void k3(const float* __restrict__ gv, const float* __restrict__ bev,
                   const float* __restrict__ gt, const float* __restrict__ bet,
                   const float* __restrict__ Ws, const float* __restrict__ bs)
{
    extern __shared__ float sm3[];
    float* sfs    = sm3;            // [64][68]
    float* wst    = sm3 + 64*68;    // [64*64] transposed Ws
    float* red_s  = wst + 4096;     // [17][64]
    float* red_ss = red_s + 17*64;  // [17][64]
    __shared__ float rbuf[9*4];
    __shared__ float st1[4];

    int b = blockIdx.x;
    int n = b / 5, kc = b % 5;
    int tid = threadIdx.x;

    {
        float a0=0.f, a1=0.f, a2=0.f, a3=0.f;
        for (int j = tid; j < NB*CB; j += blockDim.x) {
            a0 += g_part1[j*4+0]; a1 += g_part1[j*4+1];
            a2 += g_part1[j*4+2]; a3 += g_part1[j*4+3];
        }
        #pragma unroll
        for (int o = 16; o; o >>= 1) {
            a0 += __shfl_down_sync(0xffffffffu, a0, o);
            a1 += __shfl_down_sync(0xffffffffu, a1, o);
            a2 += __shfl_down_sync(0xffffffffu, a2, o);
            a3 += __shfl_down_sync(0xffffffffu, a3, o);
        }
        if ((tid & 31) == 0) {
            int w = tid >> 5;
            rbuf[w*4+0]=a0; rbuf[w*4+1]=a1; rbuf[w*4+2]=a2; rbuf[w*4+3]=a3;
        }
        __syncthreads();
        if (tid == 0) {
            float A0=0,A1=0,A2=0,A3=0;
            for (int w = 0; w < 9; w++) { A0+=rbuf[w*4]; A1+=rbuf[w*4+1]; A2+=rbuf[w*4+2]; A3+=rbuf[w*4+3]; }
            float cntv = (float)(NB*CB*TB), cntt = (float)(NB*CB*VB);
            float mv = A0/cntv, vv = A1/cntv - mv*mv;
            float mt = A2/cntt, vt = A3/cntt - mt*mt;
            st1[0] = mv; st1[1] = rsqrtf(vv + EPSB);
            st1[2] = mt; st1[3] = rsqrtf(vt + EPSB);
        }
        __syncthreads();
    }
    float mv = st1[0], rv = st1[1], mt = st1[2], rt = st1[3];
    float gvv = gv[0], bevv = bev[0], gtv = gt[0], betv = bet[0];

    for (int i = tid; i < 64*68; i += blockDim.x) {
        int cc = i / 68, ll = i % 68;
        float val = 0.f;
        if (ll < 65) {
            int p = cc*LTOT + kc*65 + ll;
            if (p < 1600) {
                int cs = p / 25, v = p % 25;
                float x = g_xt[(n*64 + cs)*25 + v];
                val = hswish(gtv * (x - mt) * rt + betv);
            } else {
                int q = p - 1600;
                int cs = q / 300, t = q % 300;
                float x = g_xv[(n*64 + cs)*300 + t];
                val = hswish(gvv * (x - mv) * rv + bevv);
            }
        }
        sfs[i] = val;
    }
    for (int i = tid; i < 4096; i += blockDim.x) {
        int o = i & 63, cc = i >> 6;
        wst[i] = Ws[o*64 + cc];
    }
    __syncthreads();

    if (tid < 272) {
        int og = tid & 15, kg = tid >> 4;
        int o0 = og * 4, kl0 = kg * 4;
        float acc[4][4];
        #pragma unroll
        for (int j = 0; j < 4; j++) {
            float bb = bs[o0 + j];
            #pragma unroll
            for (int i = 0; i < 4; i++) acc[j][i] = bb;
        }
        for (int cc = 0; cc < 64; cc++) {
            float4 a = *(const float4*)&wst[cc*64 + o0];
            float4 bq = *(const float4*)&sfs[cc*68 + kl0];
            acc[0][0] += a.x*bq.x; acc[0][1] += a.x*bq.y; acc[0][2] += a.x*bq.z; acc[0][3] += a.x*bq.w;
            acc[1][0] += a.y*bq.x; acc[1][1] += a.y*bq.y; acc[1][2] += a.y*bq.z; acc[1][3] += a.y*bq.w;
            acc[2][0] += a.z*bq.x; acc[2][1] += a.z*bq.y; acc[2][2] += a.z*bq.z; acc[2][3] += a.z*bq.w;
            acc[3][0] += a.w*bq.x; acc[3][1] += a.w*bq.y; acc[3][2] += a.w*bq.z; acc[3][3] += a.w*bq.w;
        }
        #pragma unroll
        for (int j = 0; j < 4; j++) {
            float s = 0.f, ssum = 0.f;
            #pragma unroll
            for (int i = 0; i < 4; i++) {
                int kl = kl0 + i;
                if (kl < 65) {
                    float v = acc[j][i];
                    g_xs[(n*64 + o0 + j)*LTOT + kc*65 + kl] = v;
                    s += v; ssum += v*v;
                }
            }
            red_s [kg*64 + o0 + j] = s;
            red_ss[kg*64 + o0 + j] = ssum;
        }
    }
    __syncthreads();
    if (tid < 64) {
        float S = 0.f, SS = 0.f;
        for (int kg = 0; kg < 17; kg++) { S += red_s[kg*64 + tid]; SS += red_ss[kg*64 + tid]; }
        g_part2[(b*64 + tid)*2 + 0] = S;
        g_part2[(b*64 + tid)*2 + 1] = SS;
    }
}

// ---------------- K56: fused stats2 + xbar column + squeeze outputs (block per l) ----
__global__ void k56(const float* __restrict__ gs, const float* __restrict__ bes,
                    const float* __restrict__ Wt2, const float* __restrict__ bt2,
                    const float* __restrict__ Wv2, const float* __restrict__ bv2,
                    float* __restrict__ out_xtime)
{
    __shared__ float w2t[4096];
    __shared__ float red_a[256], red_b[256];
    __shared__ float stats2_s[128];
    __shared__ float xbar_s[64];

    int l = blockIdx.x;
    int tid = threadIdx.x;

    const float* W2 = (l < TB) ? Wt2 : Wv2;
    for (int i = tid; i < 4096; i += blockDim.x) {
        int o = i >> 6, d = i & 63;
        w2t[d*64 + o] = W2[i];
    }

    {
        int o = tid & 63, sl = tid >> 6;
        float s = 0.f, ss = 0.f;
        for (int ch = sl; ch < 320; ch += 4) {
            s  += g_part2[(ch*64 + o)*2 + 0];
            ss += g_part2[(ch*64 + o)*2 + 1];
        }
        red_a[tid] = s; red_b[tid] = ss;
        __syncthreads();
        if (tid < 64) {
            float S  = red_a[tid] + red_a[64+tid] + red_a[128+tid] + red_a[192+tid];
            float SS = red_b[tid] + red_b[64+tid] + red_b[128+tid] + red_b[192+tid];
            float cnt = 64.f * (float)LTOT;
            float m = S/cnt, v = SS/cnt - m*m;
            stats2_s[tid*2 + 0] = m;
            stats2_s[tid*2 + 1] = rsqrtf(v + EPSB);
        }
        __syncthreads();
    }

    {
        int d = tid & 63, ns = tid >> 6;
        float m = stats2_s[d*2], r = stats2_s[d*2+1];
        float g = gs[d], bb = bes[d];
        float acc = 0.f;
        for (int n = ns; n < 64; n += 4)
            acc += hswish(g * (g_xs[(n*64 + d)*LTOT + l] - m) * r + bb);
        red_a[tid] = acc;
        __syncthreads();
        if (tid < 64)
            xbar_s[tid] = (red_a[tid] + red_a[64+tid] + red_a[128+tid] + red_a[192+tid]) * (1.0f/64.0f);
        __syncthreads();
    }

    if (tid < 64) {
        int o = tid;
        float acc = (l < TB) ? bt2[o] : bv2[o];
        #pragma unroll 8
        for (int d = 0; d < 64; d++) acc += w2t[d*64 + o] * xbar_s[d];
        float sg = 1.0f / (1.0f + expf(-acc));
        if (l < TB) out_xtime[o*TB + l] = sg;
        else        g_scale[(l - TB)*64 + o] = tanhf(sg) + 1.0f;
    }
}

// ---------------- K7: GEMM + inline BN partials + shifted-layout store ----------------
// 800 threads = 25 warps, warp w (0..24), lane = ddg; 12t x 2dd per thread via FFMA2.
// a-loads: exactly 3x LDS.128 per c (12 t = 6 packed pairs). No idle warps.
#define XMP_CS 12
#define XMP_WS 772      // 64*12 + 4 pad
#define XMP_TOT (VB*XMP_WS)   // 19300 floats; also reused as 64x300 perm buffer (19200)
__global__ void __launch_bounds__(800, 1)
k7(const float* __restrict__ x0, const float* __restrict__ Lw,
   const float* __restrict__ Lb)
{
    extern __shared__ float sm7[];
    float* xmp = sm7;                 // 19300
    float* lws = sm7 + XMP_TOT;       // 4096, 16B-aligned
    float* ssc = lws + 4096;          // 25*65
    float* lbs = ssc + 1625;          // 64

    int b = blockIdx.x;
    int n = b / (TB/K7T);             // TB/K7T = 25
    int t0 = (b % (TB/K7T)) * K7T;
    int tid = threadIdx.x;

    for (int i = tid; i < 4096; i += 800) lws[i] = Lw[i];
    for (int i = tid; i < VB*CB; i += 800) {
        int w = i >> 6, c = i & 63;
        ssc[w*65 + c] = g_scale[i];
    }
    if (tid < 64) lbs[tid] = Lb[tid];
    __syncthreads();

    // build: exactly 2 (c,v) pairs per thread; strength-reduced t-loop (MLP 12)
    const float* xbase = x0 + ((size_t)(n*64) * 300 + t0) * 25;
    #pragma unroll
    for (int rep = 0; rep < 2; rep++) {
        int pr = rep*800 + tid;
        int c = pr / 25;
        int v = pr - c*25;
        int w = v - (c % 25); if (w < 0) w += 25;
        float sc = ssc[w*65 + c];
        const float* src = xbase + (size_t)c * 7500 + v;
        float* dst = xmp + w*XMP_WS + c*XMP_CS;
        #pragma unroll
        for (int t = 0; t < K7T; t++)
            dst[t] = src[t*25] * sc;
    }
    __syncthreads();

    int w   = tid >> 5;     // warp index == w, 0..24 (all warps active)
    int ddg = tid & 31;
    int dd0 = ddg << 1;
    unsigned long long acc[6][2];

    {
        const unsigned long long* xq = (const unsigned long long*)(xmp + w*XMP_WS);
        {
            unsigned long long i0 = pk2(lbs[dd0],     lbs[dd0]);
            unsigned long long i1 = pk2(lbs[dd0 + 1], lbs[dd0 + 1]);
            #pragma unroll
            for (int tp = 0; tp < 6; tp++) { acc[tp][0] = i0; acc[tp][1] = i1; }
        }
        #pragma unroll 4
        for (int c = 0; c < 64; c++) {
            ulonglong2 A01 = *(const ulonglong2*)(xq + c*6);      // (t0,t1),(t2,t3)
            ulonglong2 A23 = *(const ulonglong2*)(xq + c*6 + 2);  // (t4,t5),(t6,t7)
            ulonglong2 A45 = *(const ulonglong2*)(xq + c*6 + 4);  // (t8,t9),(t10,t11)
            float2 bf = *(const float2*)&lws[(c << 6) + dd0];
            unsigned long long b0 = pk2(bf.x, bf.x);
            unsigned long long b1 = pk2(bf.y, bf.y);
            fma2(acc[0][0], A01.x, b0); fma2(acc[0][1], A01.x, b1);
            fma2(acc[1][0], A01.y, b0); fma2(acc[1][1], A01.y, b1);
            fma2(acc[2][0], A23.x, b0); fma2(acc[2][1], A23.x, b1);
            fma2(acc[3][0], A23.y, b0); fma2(acc[3][1], A23.y, b1);
            fma2(acc[4][0], A45.x, b0); fma2(acc[4][1], A45.x, b1);
            fma2(acc[5][0], A45.y, b0); fma2(acc[5][1], A45.y, b1);
        }
    }
    __syncthreads();   // all xmp reads done; reuse as permute buffer

    float* ysm = sm7;  // [64][300]: dd*300 + t*25 + i
    {
        int i_e = (w + dd0) % 25;          // dest i for feature dd0
        int i_o = (w + dd0 + 1) % 25;      // dest i for feature dd0+1
        float* ysm_e = ysm + dd0*300 + i_e;
        float* ysm_o = ysm + (dd0 + 1)*300 + i_o;
        float psum0 = 0.f, psum1 = 0.f, psq0 = 0.f, psq1 = 0.f;
        #pragma unroll
        for (int tp = 0; tp < 6; tp++) {
            float e0, o0, e1, o1;
            upk2(e0, o0, acc[tp][0]);      // (t=2tp, dd0), (t=2tp+1, dd0)
            upk2(e1, o1, acc[tp][1]);      // (t=2tp, dd0+1), (t=2tp+1, dd0+1)
            ysm_e[(2*tp)*25]     = e0;
            ysm_o[(2*tp)*25]     = e1;
            ysm_e[(2*tp + 1)*25] = o0;
            ysm_o[(2*tp + 1)*25] = o1;
            psum0 += e0 + o0; psq0 += e0*e0 + o0*o0;
            psum1 += e1 + o1; psq1 += e1*e1 + o1*o1;
        }
        *(float2*)&g_part3[(size_t)b*3200 + (w << 6) + dd0]        = make_float2(psum0, psum1);
        *(float2*)&g_part3[(size_t)b*3200 + 1600 + (w << 6) + dd0] = make_float2(psq0,  psq1);
    }
    __syncthreads();

    // coalesced float2 store: g_y0 layout [n][dd][t][i]; per dd the 300 floats
    // are contiguous in both ysm and g_y0. 9600 float2 = 12 per thread exactly.
    size_t base = (size_t)n * 480000 + (size_t)t0 * 25;
    #pragma unroll
    for (int k = 0; k < 12; k++) {
        int idx2 = k*800 + tid;            // float2 index, 0..9599
        int dd = idx2 / 150;
        int r2 = idx2 - dd*150;
        *(float2*)&g_y0[base + (size_t)dd*7500 + 2*r2] =
            *(const float2*)&ysm[dd*300 + 2*r2];
    }
}

// ---------------- K8b: reduce BN partials -> per-feature stats ----------------
__global__ void k8b()
{
    __shared__ float red_s[256], red_ss[256];
    int f = blockIdx.x * 32 + (threadIdx.x & 31);
    int sl = threadIdx.x >> 5;
    float s = 0.f, ss = 0.f;
    for (int b = sl; b < K7_BLOCKS; b += 8) {
        s  += g_part3[(size_t)b*3200 + f];
        ss += g_part3[(size_t)b*3200 + 1600 + f];
    }
    red_s[threadIdx.x] = s; red_ss[threadIdx.x] = ss;
    __syncthreads();
    if (threadIdx.x < 32) {
        float S = 0.f, SS = 0.f;
        #pragma unroll
        for (int k = 0; k < 8; k++) { S += red_s[k*32 + threadIdx.x]; SS += red_ss[k*32 + threadIdx.x]; }
        int ff = blockIdx.x * 32 + threadIdx.x;
        float cnt = (float)NTOT;
        float m = S/cnt, v = SS/cnt - m*m;
        g_stats3[ff*2 + 0] = m;
        g_stats3[ff*2 + 1] = rsqrtf(v + EPSB);
    }
}

// ---------------- K9: pure streaming BN + residual + relu ----------------
// g_y0 is already in output layout [n][dd][t][i]; block = one (n,dd) row (7500 floats).
__global__ void k9(const float* __restrict__ x0, const float* __restrict__ gbn,
                   const float* __restrict__ bbn, float* __restrict__ out)
{
    __shared__ float A[25], Bc[25];
    int b = blockIdx.x;            // n*64 + dd
    int dd = b & 63;
    int tid = threadIdx.x;

    if (tid < 25) {
        int i = tid;
        int wsrc = i - (dd % 25); if (wsrc < 0) wsrc += 25;   // pre-shift w for (i,dd)
        int p = wsrc*64 + dd;      // stats feature (pre-shift)
        int q = i*64 + dd;         // gbn/bbn feature (post-shift)
        float m = g_stats3[p*2], r = g_stats3[p*2 + 1];
        float g = gbn[q];
        A[i]  = g * r;
        Bc[i] = bbn[q] - g * r * m;
    }
    __syncthreads();

    const float4* y4 = (const float4*)(g_y0 + (size_t)b * 7500);
    const float4* x4 = (const float4*)(x0   + (size_t)b * 7500);
    float4*       o4 = (float4*)(out        + (size_t)b * 7500);
    for (int p4 = tid; p4 < 1875; p4 += blockDim.x) {
        float4 y = y4[p4];
        float4 x = x4[p4];
        int i = (p4 << 2) % 25;
        float4 o;
        o.x = fmaxf(fmaf(A[i], y.x, Bc[i]) + x.x, 0.f); if (++i == 25) i = 0;
        o.y = fmaxf(fmaf(A[i], y.y, Bc[i]) + x.y, 0.f); if (++i == 25) i = 0;
        o.z = fmaxf(fmaf(A[i], y.z, Bc[i]) + x.z, 0.f); if (++i == 25) i = 0;
        o.w = fmaxf(fmaf(A[i], y.w, Bc[i]) + x.w, 0.f);
        o4[p4] = o;
    }
}

// ---------------- launcher (6 launches; slot 4 = k7 for ncu capture) ----------------
extern "C" void kernel_launch(void* const* d_in, const int* in_sizes, int n_in,
                              void* d_out, int out_size)
{
    const float* x0  = (const float*)d_in[0];
    const float* Wv  = (const float*)d_in[3];
    const float* bv  = (const float*)d_in[4];
    const float* gv  = (const float*)d_in[5];
    const float* bev = (const float*)d_in[6];
    const float* Wt  = (const float*)d_in[7];
    const float* bt  = (const float*)d_in[8];
    const float* gt  = (const float*)d_in[9];
    const float* bet = (const float*)d_in[10];
    const float* Ws  = (const float*)d_in[11];
    const float* bs  = (const float*)d_in[12];
    const float* gs  = (const float*)d_in[13];
    const float* bes = (const float*)d_in[14];
    const float* Wv2 = (const float*)d_in[15];
    const float* bv2 = (const float*)d_in[16];
    const float* Wt2 = (const float*)d_in[17];
    const float* bt2 = (const float*)d_in[18];
    const float* Lw  = (const float*)d_in[19];
    const float* Lb  = (const float*)d_in[20];
    const float* gbn = (const float*)d_in[21];
    const float* bbn = (const float*)d_in[22];
    float* out = (float*)d_out;

    static_assert((TB % K7T) == 0, "k7 t tiling");
    static_assert((XMP_TOT % 4) == 0, "xmp align");
    static_assert(XMP_CS * CB < XMP_WS, "xmp pad");
    static_assert(DB * 300 <= XMP_TOT, "perm buffer fits");
    static_assert(CB*VB == 2*800, "build pairs = 2/thread");

    const int smem3 = (64*68 + 4096 + 17*64*2) * 4;                 // 51200
    const int smem7 = (XMP_TOT + 4096 + 1625 + 64) * 4;             // 100340
    cudaFuncSetAttribute(k3, cudaFuncAttributeMaxDynamicSharedMemorySize, smem3);
    cudaFuncSetAttribute(k7, cudaFuncAttributeMaxDynamicSharedMemorySize, smem7);

    k1 <<<NB*CB, 256>>>(x0, Wv, bv, Wt, bt);
    k3 <<<NB*5, 288, smem3>>>(gv, bev, gt, bet, Ws, bs);
    k56<<<LTOT, 256>>>(gs, bes, Wt2, bt2, Wv2, bv2, out + Y_SIZE);
    k7 <<<K7_BLOCKS, 800, smem7>>>(x0, Lw, Lb);
    k8b<<<FEAT/32, 256>>>();
    k9 <<<NB*DB, 256>>>(x0, gbn, bbn, out);
}